// round 1
// baseline (speedup 1.0000x reference)
#include <cuda_runtime.h>

#define Bb 2
#define Hh 12
#define Ll 2048
#define Dd 768
#define DK 64
#define NEGV (-1000000000.0f)

// scratch (static device allocations are allowed)
__device__ float g_q[Bb*Hh*Ll*DK];
__device__ float g_k[Bb*Hh*Ll*DK];
__device__ float g_pi[Bb*Hh*Ll];

// ---------------------------------------------------------------------------
// Projection GEMM: C(4096x768) = A @ W + b, scattered to (B,H,L,64) layout.
// blockIdx.x: 64-row tile (64 tiles), blockIdx.y: head (=64-col tile), z: q/k
// ---------------------------------------------------------------------------
__global__ __launch_bounds__(256) void proj_kernel(
    const float* __restrict__ Aq, const float* __restrict__ Wq, const float* __restrict__ bq,
    const float* __restrict__ Ak, const float* __restrict__ Wk, const float* __restrict__ bk)
{
    const float *A, *W, *bias;
    float* out;
    if (blockIdx.z == 0) { A = Aq; W = Wq; bias = bq; out = g_q; }
    else                 { A = Ak; W = Wk; bias = bk; out = g_k; }

    __shared__ float As[16][64];   // [k][m]
    __shared__ float Bs[16][68];   // [k][n] padded

    const int tid = threadIdx.x;
    const int tx = tid & 15, ty = tid >> 4;
    const int row0 = blockIdx.x * 64;
    const int h    = blockIdx.y;
    const int col0 = h * 64;

    float acc[4][4] = {};

    for (int k0 = 0; k0 < Dd; k0 += 16) {
        // A tile 64x16, transposed store
        {
            int r  = tid >> 2;
            int kq = (tid & 3) * 4;
            float4 a4 = *(const float4*)&A[(size_t)(row0 + r) * Dd + k0 + kq];
            As[kq + 0][r] = a4.x; As[kq + 1][r] = a4.y;
            As[kq + 2][r] = a4.z; As[kq + 3][r] = a4.w;
        }
        // W tile 16x64, natural
        {
            int kb = tid >> 4;
            int nb = (tid & 15) * 4;
            *(float4*)&Bs[kb][nb] = *(const float4*)&W[(size_t)(k0 + kb) * Dd + col0 + nb];
        }
        __syncthreads();
        #pragma unroll
        for (int kk = 0; kk < 16; kk++) {
            float4 av = *(const float4*)&As[kk][ty * 4];
            float4 cv = *(const float4*)&Bs[kk][tx * 4];
            float a[4] = {av.x, av.y, av.z, av.w};
            float c[4] = {cv.x, cv.y, cv.z, cv.w};
            #pragma unroll
            for (int i = 0; i < 4; i++)
                #pragma unroll
                for (int j = 0; j < 4; j++)
                    acc[i][j] += a[i] * c[j];
        }
        __syncthreads();
    }

    float4 b4 = *(const float4*)&bias[col0 + tx * 4];
    #pragma unroll
    for (int i = 0; i < 4; i++) {
        int row = row0 + ty * 4 + i;
        int b = row >> 11, l = row & (Ll - 1);
        float4 o;
        o.x = acc[i][0] + b4.x;
        o.y = acc[i][1] + b4.y;
        o.z = acc[i][2] + b4.z;
        o.w = acc[i][3] + b4.w;
        *(float4*)&out[(((size_t)b * Hh + h) * Ll + l) * DK + tx * 4] = o;
    }
}

// ---------------------------------------------------------------------------
// Block reductions (256 threads, 8 warps)
// ---------------------------------------------------------------------------
__device__ __forceinline__ float warpSum(float v) {
    #pragma unroll
    for (int o = 16; o; o >>= 1) v += __shfl_xor_sync(0xffffffffu, v, o);
    return v;
}
__device__ __forceinline__ float warpMax(float v) {
    #pragma unroll
    for (int o = 16; o; o >>= 1) v = fmaxf(v, __shfl_xor_sync(0xffffffffu, v, o));
    return v;
}
__device__ float blockSum(float v, float* red) {
    int w = threadIdx.x >> 5, lane = threadIdx.x & 31;
    v = warpSum(v);
    if (lane == 0) red[w] = v;
    __syncthreads();
    if (w == 0) {
        float r = (lane < 8) ? red[lane] : 0.0f;
        r = warpSum(r);
        if (lane == 0) red[0] = r;
    }
    __syncthreads();
    float r = red[0];
    __syncthreads();
    return r;
}
__device__ float blockMax(float v, float* red) {
    int w = threadIdx.x >> 5, lane = threadIdx.x & 31;
    v = warpMax(v);
    if (lane == 0) red[w] = v;
    __syncthreads();
    if (w == 0) {
        float r = (lane < 8) ? red[lane] : -1e30f;
        r = warpMax(r);
        if (lane == 0) red[0] = r;
    }
    __syncthreads();
    float r = red[0];
    __syncthreads();
    return r;
}

// ---------------------------------------------------------------------------
// Sinkhorn OT: pi[b][h][l]. One block per (b,h). nu == 1 (softmax over len-1).
// ---------------------------------------------------------------------------
__global__ __launch_bounds__(256) void sinkhorn_kernel(
    const float* __restrict__ query, const float* __restrict__ aspect,
    const int* __restrict__ mask, const float* __restrict__ w_mu,
    const float* __restrict__ b_mu)
{
    const int h = blockIdx.x, b = blockIdx.y;
    const int tid = threadIdx.x;
    __shared__ float aspn[64];
    __shared__ float wmu[64];
    __shared__ float red[8];

    if (tid < 64) {
        aspn[tid] = aspect[b * Dd + h * DK + tid];
        wmu[tid]  = w_mu[tid];
    }
    __syncthreads();

    float ssa = 0.0f;
    #pragma unroll
    for (int d = 0; d < 64; d++) ssa += aspn[d] * aspn[d];
    const float inv_na = 1.0f / fmaxf(sqrtf(ssa), 1e-12f);
    const float bmu = b_mu[0];

    float Kl[8], mu[8], u[8];
    float lmax = -1e30f;
    #pragma unroll
    for (int j = 0; j < 8; j++) {
        int l = tid + j * 256;
        const float* sp = &query[((size_t)b * Ll + l) * Dd + h * DK];
        float sq = 0.0f, da = 0.0f, dm = 0.0f;
        #pragma unroll
        for (int d = 0; d < 64; d += 4) {
            float4 s4 = *(const float4*)&sp[d];
            sq += s4.x * s4.x + s4.y * s4.y + s4.z * s4.z + s4.w * s4.w;
            da += s4.x * aspn[d] + s4.y * aspn[d + 1] + s4.z * aspn[d + 2] + s4.w * aspn[d + 3];
            dm += s4.x * wmu[d]  + s4.y * wmu[d + 1]  + s4.z * wmu[d + 2]  + s4.w * wmu[d + 3];
        }
        float inv_ns = 1.0f / fmaxf(sqrtf(sq), 1e-12f);
        float cosv = da * inv_ns * inv_na;
        Kl[j] = __expf(cosv - 1.0f);           // exp(-(1-cos)/eps), eps=1
        float lg = dm + bmu;
        if (mask[b * Ll + l] == 0) lg = NEGV;
        mu[j] = lg;                             // holds logits for now
        lmax = fmaxf(lmax, lg);
    }
    lmax = blockMax(lmax, red);
    float lsum = 0.0f;
    #pragma unroll
    for (int j = 0; j < 8; j++) { mu[j] = __expf(mu[j] - lmax); lsum += mu[j]; }
    lsum = blockSum(lsum, red);
    float inv = 1.0f / lsum;
    #pragma unroll
    for (int j = 0; j < 8; j++) mu[j] *= inv;

    float v = 1.0f;
    for (int it = 0; it < 50; it++) {
        float part = 0.0f;
        #pragma unroll
        for (int j = 0; j < 8; j++) {
            u[j] = mu[j] / (Kl[j] * v + 1e-8f);
            part += Kl[j] * u[j];
        }
        float S = blockSum(part, red);
        v = 1.0f / (S + 1e-8f);                 // nu == 1
    }
    #pragma unroll
    for (int j = 0; j < 8; j++)
        g_pi[((size_t)b * Hh + h) * Ll + tid + j * 256] = u[j] * Kl[j] * v;
}

// ---------------------------------------------------------------------------
// Attention: flash-style fp32, 64-row tile per block, 64-col chunks.
// Fused epilogue: out = 0.8*attn_out + 0.2*pi*seq_h + bias_m
// ---------------------------------------------------------------------------
#define QS(d, m) Qs[(d) * 68 + (m)]
#define KS(d, n) Ks[(d) * 68 + (n)]
#define VS(n, d) Vs[(n) * 64 + (d)]
#define PS(m, n) Ps[(m) * 64 + (n)]
#define ATTN_SMEM ((64 * 68 * 2 + 64 * 64 * 2) * 4)

__global__ __launch_bounds__(256) void attn_kernel(
    const float* __restrict__ query, const float* __restrict__ shortb,
    const int* __restrict__ mask, const float* __restrict__ bias_m,
    float* __restrict__ out)
{
    extern __shared__ float sm[];
    float* Qs = sm;                   // [64][68]  (d, m)
    float* Ks = Qs + 64 * 68;         // [64][68]  (d, n)
    float* Vs = Ks + 64 * 68;         // [64][64]  (n, d)
    float* Ps = Vs + 64 * 64;         // [64][64]  (m, n)

    const int tid = threadIdx.x;
    const int tx = tid & 15, ty = tid >> 4;
    const int m0 = blockIdx.x * 64;
    const int h = blockIdx.y, b = blockIdx.z;
    const size_t bh = (size_t)b * Hh + h;
    const float* qp = g_q + bh * Ll * DK;
    const float* kp = g_k + bh * Ll * DK;

    // load Q tile transposed
    #pragma unroll
    for (int it = 0; it < 4; it++) {
        int idx = tid + it * 256;
        int r = idx >> 4;
        int d4 = (idx & 15) * 4;
        float4 v = *(const float4*)&qp[(size_t)(m0 + r) * DK + d4];
        QS(d4 + 0, r) = v.x; QS(d4 + 1, r) = v.y;
        QS(d4 + 2, r) = v.z; QS(d4 + 3, r) = v.w;
    }

    float accO[4][4] = {};
    float mrow[4] = {-1e30f, -1e30f, -1e30f, -1e30f};
    float lrow[4] = {};

    for (int nb = 0; nb < 32; nb++) {
        const int n0 = nb * 64;
        // K tile transposed + V tile natural
        #pragma unroll
        for (int it = 0; it < 4; it++) {
            int idx = tid + it * 256;
            int r = idx >> 4;
            int d4 = (idx & 15) * 4;
            float4 kv = *(const float4*)&kp[(size_t)(n0 + r) * DK + d4];
            KS(d4 + 0, r) = kv.x; KS(d4 + 1, r) = kv.y;
            KS(d4 + 2, r) = kv.z; KS(d4 + 3, r) = kv.w;
            float4 vv = *(const float4*)&query[((size_t)b * Ll + n0 + r) * Dd + h * DK + d4];
            *(float4*)&VS(r, d4) = vv;
        }
        __syncthreads();

        // prefetch short + mask (hidden behind QK FMAs)
        float4 sh[4];
        #pragma unroll
        for (int i = 0; i < 4; i++)
            sh[i] = *(const float4*)&shortb[(bh * Ll + m0 + ty * 4 + i) * Ll + n0 + tx * 4];
        int4 mk = *(const int4*)&mask[b * Ll + n0 + tx * 4];

        // S = Q K^T
        float s[4][4] = {};
        #pragma unroll 16
        for (int kk = 0; kk < 64; kk++) {
            float4 aq = *(const float4*)&QS(kk, ty * 4);
            float4 ak = *(const float4*)&KS(kk, tx * 4);
            float a[4] = {aq.x, aq.y, aq.z, aq.w};
            float c[4] = {ak.x, ak.y, ak.z, ak.w};
            #pragma unroll
            for (int i = 0; i < 4; i++)
                #pragma unroll
                for (int j = 0; j < 4; j++)
                    s[i][j] += a[i] * c[j];
        }

        // scale (1/sqrt(64)), mask, +short
        int mki[4] = {mk.x, mk.y, mk.z, mk.w};
        float shf[4][4];
        #pragma unroll
        for (int i = 0; i < 4; i++) {
            shf[i][0] = sh[i].x; shf[i][1] = sh[i].y;
            shf[i][2] = sh[i].z; shf[i][3] = sh[i].w;
        }
        #pragma unroll
        for (int i = 0; i < 4; i++)
            #pragma unroll
            for (int j = 0; j < 4; j++) {
                float sv = (mki[j] == 0) ? NEGV : s[i][j] * 0.125f;
                s[i][j] = sv + shf[i][j];
            }

        // online softmax (row groups = 16 consecutive lanes)
        #pragma unroll
        for (int i = 0; i < 4; i++) {
            float tm = fmaxf(fmaxf(s[i][0], s[i][1]), fmaxf(s[i][2], s[i][3]));
            #pragma unroll
            for (int o = 8; o; o >>= 1)
                tm = fmaxf(tm, __shfl_xor_sync(0xffffffffu, tm, o, 16));
            float mn = fmaxf(mrow[i], tm);
            float sc = __expf(mrow[i] - mn);
            float ps = 0.0f;
            #pragma unroll
            for (int j = 0; j < 4; j++) { s[i][j] = __expf(s[i][j] - mn); ps += s[i][j]; }
            #pragma unroll
            for (int o = 8; o; o >>= 1)
                ps += __shfl_xor_sync(0xffffffffu, ps, o, 16);
            lrow[i] = lrow[i] * sc + ps;
            mrow[i] = mn;
            #pragma unroll
            for (int j = 0; j < 4; j++) accO[i][j] *= sc;
            *(float4*)&PS(ty * 4 + i, tx * 4) = make_float4(s[i][0], s[i][1], s[i][2], s[i][3]);
        }
        __syncthreads();

        // accO += P V
        #pragma unroll 4
        for (int n = 0; n < 64; n += 4) {
            float p[4][4], vv[4][4];
            #pragma unroll
            for (int i = 0; i < 4; i++) {
                float4 t = *(const float4*)&PS(ty * 4 + i, n);
                p[i][0] = t.x; p[i][1] = t.y; p[i][2] = t.z; p[i][3] = t.w;
            }
            #pragma unroll
            for (int jn = 0; jn < 4; jn++) {
                float4 t = *(const float4*)&VS(n + jn, tx * 4);
                vv[jn][0] = t.x; vv[jn][1] = t.y; vv[jn][2] = t.z; vv[jn][3] = t.w;
            }
            #pragma unroll
            for (int i = 0; i < 4; i++)
                #pragma unroll
                for (int j = 0; j < 4; j++)
                    accO[i][j] += p[i][0] * vv[0][j] + p[i][1] * vv[1][j]
                                + p[i][2] * vv[2][j] + p[i][3] * vv[3][j];
        }
        __syncthreads();
    }

    // fused epilogue
    const float bm = bias_m[0];
    #pragma unroll
    for (int i = 0; i < 4; i++) {
        int r = m0 + ty * 4 + i;
        float piv = g_pi[bh * Ll + r] * 0.2f;
        float4 sh4 = *(const float4*)&query[((size_t)b * Ll + r) * Dd + h * DK + tx * 4];
        float inv = 0.8f / lrow[i];
        float4 o;
        o.x = accO[i][0] * inv + piv * sh4.x + bm;
        o.y = accO[i][1] * inv + piv * sh4.y + bm;
        o.z = accO[i][2] * inv + piv * sh4.z + bm;
        o.w = accO[i][3] * inv + piv * sh4.w + bm;
        *(float4*)&out[(bh * Ll + r) * DK + tx * 4] = o;
    }
}

// ---------------------------------------------------------------------------
extern "C" void kernel_launch(void* const* d_in, const int* in_sizes, int n_in,
                              void* d_out, int out_size)
{
    const float* query  = (const float*)d_in[0];
    const float* key    = (const float*)d_in[1];
    const float* shortb = (const float*)d_in[2];
    const float* aspect = (const float*)d_in[3];
    const int*   mask   = (const int*)d_in[4];
    const float* Wq     = (const float*)d_in[5];
    const float* bq     = (const float*)d_in[6];
    const float* Wk     = (const float*)d_in[7];
    const float* bk     = (const float*)d_in[8];
    const float* w_mu   = (const float*)d_in[9];
    const float* b_mu   = (const float*)d_in[10];
    const float* bias_m = (const float*)d_in[11];
    float* out = (float*)d_out;

    cudaFuncSetAttribute(attn_kernel, cudaFuncAttributeMaxDynamicSharedMemorySize, ATTN_SMEM);

    proj_kernel<<<dim3(64, 12, 2), 256>>>(query, Wq, bq, key, Wk, bk);
    sinkhorn_kernel<<<dim3(12, 2), 256>>>(query, aspect, mask, w_mu, b_mu);
    attn_kernel<<<dim3(32, 12, 2), 256, ATTN_SMEM>>>(query, shortb, mask, bias_m, out);
}

// round 2
// speedup vs baseline: 1.0856x; 1.0856x over previous
#include <cuda_runtime.h>
#include <cstdint>

#define Bb 2
#define Hh 12
#define Ll 2048
#define Dd 768
#define DK 64
#define NEGV (-1000000000.0f)

// scratch
__device__ float g_q[Bb*Hh*Ll*DK];
__device__ float g_k[Bb*Hh*Ll*DK];
__device__ float g_pi[Bb*Hh*Ll];

// ---------------------------------------------------------------------------
// tf32 helpers
// ---------------------------------------------------------------------------
__device__ __forceinline__ float f2tf32(float x) {
    uint32_t u;
    asm("cvt.rna.tf32.f32 %0, %1;" : "=r"(u) : "f"(x));
    return __uint_as_float(u);
}

__device__ __forceinline__ void mma8(float d[4], float a0, float a1, float a2, float a3,
                                     float b0, float b1) {
    asm volatile(
        "mma.sync.aligned.m16n8k8.row.col.f32.tf32.tf32.f32 "
        "{%0,%1,%2,%3},{%4,%5,%6,%7},{%8,%9},{%0,%1,%2,%3};\n"
        : "+f"(d[0]), "+f"(d[1]), "+f"(d[2]), "+f"(d[3])
        : "r"(__float_as_uint(a0)), "r"(__float_as_uint(a1)),
          "r"(__float_as_uint(a2)), "r"(__float_as_uint(a3)),
          "r"(__float_as_uint(b0)), "r"(__float_as_uint(b1)));
}

// ---------------------------------------------------------------------------
// Projection GEMM: 128x64 tile, 256 threads, 8x4 per thread.
// ---------------------------------------------------------------------------
__global__ __launch_bounds__(256) void proj_kernel(
    const float* __restrict__ Aq, const float* __restrict__ Wq, const float* __restrict__ bq,
    const float* __restrict__ Ak, const float* __restrict__ Wk, const float* __restrict__ bk)
{
    const float *A, *W, *bias;
    float* out;
    if (blockIdx.z == 0) { A = Aq; W = Wq; bias = bq; out = g_q; }
    else                 { A = Ak; W = Wk; bias = bk; out = g_k; }

    __shared__ float As[16][132];   // [k][m]
    __shared__ float Bs[16][68];    // [k][n]

    const int tid = threadIdx.x;
    const int tx = tid & 15, ty = tid >> 4;
    const int row0 = blockIdx.x * 128;
    const int h    = blockIdx.y;
    const int col0 = h * 64;

    float acc[8][4] = {};

    for (int k0 = 0; k0 < Dd; k0 += 16) {
        #pragma unroll
        for (int it = 0; it < 2; it++) {
            int lin = tid + it * 256;
            int r = lin & 127;
            int kq4 = (lin >> 7) * 4;
            float4 a4 = *(const float4*)&A[(size_t)(row0 + r) * Dd + k0 + kq4];
            As[kq4 + 0][r] = a4.x; As[kq4 + 1][r] = a4.y;
            As[kq4 + 2][r] = a4.z; As[kq4 + 3][r] = a4.w;
        }
        {
            int kb = tid >> 4;
            int nb = (tid & 15) * 4;
            *(float4*)&Bs[kb][nb] = *(const float4*)&W[(size_t)(k0 + kb) * Dd + col0 + nb];
        }
        __syncthreads();
        #pragma unroll
        for (int kk = 0; kk < 16; kk++) {
            float a[8];
            *(float4*)&a[0] = *(const float4*)&As[kk][ty * 8];
            *(float4*)&a[4] = *(const float4*)&As[kk][ty * 8 + 4];
            float4 cv = *(const float4*)&Bs[kk][tx * 4];
            float c[4] = {cv.x, cv.y, cv.z, cv.w};
            #pragma unroll
            for (int i = 0; i < 8; i++)
                #pragma unroll
                for (int j = 0; j < 4; j++)
                    acc[i][j] += a[i] * c[j];
        }
        __syncthreads();
    }

    float4 b4 = *(const float4*)&bias[col0 + tx * 4];
    #pragma unroll
    for (int i = 0; i < 8; i++) {
        int row = row0 + ty * 8 + i;
        int b = row >> 11, l = row & (Ll - 1);
        float4 o;
        o.x = acc[i][0] + b4.x;
        o.y = acc[i][1] + b4.y;
        o.z = acc[i][2] + b4.z;
        o.w = acc[i][3] + b4.w;
        *(float4*)&out[(((size_t)b * Hh + h) * Ll + l) * DK + tx * 4] = o;
    }
}

// ---------------------------------------------------------------------------
// Block reductions
// ---------------------------------------------------------------------------
__device__ __forceinline__ float warpSum(float v) {
    #pragma unroll
    for (int o = 16; o; o >>= 1) v += __shfl_xor_sync(0xffffffffu, v, o);
    return v;
}
__device__ __forceinline__ float warpMax(float v) {
    #pragma unroll
    for (int o = 16; o; o >>= 1) v = fmaxf(v, __shfl_xor_sync(0xffffffffu, v, o));
    return v;
}
__device__ float blockSum(float v, float* red) {
    int w = threadIdx.x >> 5, lane = threadIdx.x & 31;
    v = warpSum(v);
    if (lane == 0) red[w] = v;
    __syncthreads();
    if (w == 0) {
        float r = (lane < 8) ? red[lane] : 0.0f;
        r = warpSum(r);
        if (lane == 0) red[0] = r;
    }
    __syncthreads();
    float r = red[0];
    __syncthreads();
    return r;
}
__device__ float blockMax(float v, float* red) {
    int w = threadIdx.x >> 5, lane = threadIdx.x & 31;
    v = warpMax(v);
    if (lane == 0) red[w] = v;
    __syncthreads();
    if (w == 0) {
        float r = (lane < 8) ? red[lane] : -1e30f;
        r = warpMax(r);
        if (lane == 0) red[0] = r;
    }
    __syncthreads();
    float r = red[0];
    __syncthreads();
    return r;
}

// ---------------------------------------------------------------------------
// Sinkhorn OT (unchanged, correct)
// ---------------------------------------------------------------------------
__global__ __launch_bounds__(256) void sinkhorn_kernel(
    const float* __restrict__ query, const float* __restrict__ aspect,
    const int* __restrict__ mask, const float* __restrict__ w_mu,
    const float* __restrict__ b_mu)
{
    const int h = blockIdx.x, b = blockIdx.y;
    const int tid = threadIdx.x;
    __shared__ float aspn[64];
    __shared__ float wmu[64];
    __shared__ float red[8];

    if (tid < 64) {
        aspn[tid] = aspect[b * Dd + h * DK + tid];
        wmu[tid]  = w_mu[tid];
    }
    __syncthreads();

    float ssa = 0.0f;
    #pragma unroll
    for (int d = 0; d < 64; d++) ssa += aspn[d] * aspn[d];
    const float inv_na = 1.0f / fmaxf(sqrtf(ssa), 1e-12f);
    const float bmu = b_mu[0];

    float Kl[8], mu[8], u[8];
    float lmax = -1e30f;
    #pragma unroll
    for (int j = 0; j < 8; j++) {
        int l = tid + j * 256;
        const float* sp = &query[((size_t)b * Ll + l) * Dd + h * DK];
        float sq = 0.0f, da = 0.0f, dm = 0.0f;
        #pragma unroll
        for (int d = 0; d < 64; d += 4) {
            float4 s4 = *(const float4*)&sp[d];
            sq += s4.x * s4.x + s4.y * s4.y + s4.z * s4.z + s4.w * s4.w;
            da += s4.x * aspn[d] + s4.y * aspn[d + 1] + s4.z * aspn[d + 2] + s4.w * aspn[d + 3];
            dm += s4.x * wmu[d]  + s4.y * wmu[d + 1]  + s4.z * wmu[d + 2]  + s4.w * wmu[d + 3];
        }
        float inv_ns = 1.0f / fmaxf(sqrtf(sq), 1e-12f);
        float cosv = da * inv_ns * inv_na;
        Kl[j] = __expf(cosv - 1.0f);
        float lg = dm + bmu;
        if (mask[b * Ll + l] == 0) lg = NEGV;
        mu[j] = lg;
        lmax = fmaxf(lmax, lg);
    }
    lmax = blockMax(lmax, red);
    float lsum = 0.0f;
    #pragma unroll
    for (int j = 0; j < 8; j++) { mu[j] = __expf(mu[j] - lmax); lsum += mu[j]; }
    lsum = blockSum(lsum, red);
    float inv = 1.0f / lsum;
    #pragma unroll
    for (int j = 0; j < 8; j++) mu[j] *= inv;

    float v = 1.0f;
    for (int it = 0; it < 50; it++) {
        float part = 0.0f;
        #pragma unroll
        for (int j = 0; j < 8; j++) {
            u[j] = mu[j] / (Kl[j] * v + 1e-8f);
            part += Kl[j] * u[j];
        }
        float S = blockSum(part, red);
        v = 1.0f / (S + 1e-8f);
    }
    #pragma unroll
    for (int j = 0; j < 8; j++)
        g_pi[((size_t)b * Hh + h) * Ll + tid + j * 256] = u[j] * Kl[j] * v;
}

// ---------------------------------------------------------------------------
// Attention via tf32 mma.sync (3xTF32 split), flash-style online softmax.
// Block: 128 rows of one (b,h); 8 warps; each warp 16 rows; chunks of 64 cols.
// Fused epilogue: out = 0.8*attn/l + 0.2*pi*seq + bias_m
// ---------------------------------------------------------------------------
#define LS 68
#define VSTRIDE 72
#define ATTN_SMEM ((128*68 + 64*68 + 64*72) * 4 + 64 * 4)

__global__ __launch_bounds__(256) void attn_mma_kernel(
    const float* __restrict__ query, const float* __restrict__ shortb,
    const int* __restrict__ mask, const float* __restrict__ bias_m,
    float* __restrict__ out)
{
    extern __shared__ float sm[];
    float* SB = sm;                    // [128][68]: Q staging, then short tile, then per-warp P
    float* Ks = sm + 128 * LS;         // [64][68]  (pos, dk)
    float* Vs = Ks + 64 * LS;          // [64][72]  (pos, dk)
    int*  Msk = (int*)(Vs + 64 * VSTRIDE);  // [64]

    const int tid = threadIdx.x;
    const int w = tid >> 5, lane = tid & 31;
    const int g = lane >> 2, t = lane & 3;
    const int m0 = blockIdx.x * 128;
    const int h = blockIdx.y, b = blockIdx.z;
    const size_t bh = (size_t)b * Hh + h;
    const float* qp = g_q + bh * Ll * DK;
    const float* kp = g_k + bh * Ll * DK;
    const float* vbase = query + (size_t)b * Ll * Dd + h * DK;
    const float* sp = shortb + (bh * Ll + m0) * Ll;

    // ---- stage Q, extract A-fragments to registers ----
    #pragma unroll
    for (int it = 0; it < 8; it++) {
        int lin = tid + it * 256, row = lin >> 4, c4 = (lin & 15) * 4;
        *(float4*)&SB[row * LS + c4] = *(const float4*)&qp[(size_t)(m0 + row) * DK + c4];
    }
    __syncthreads();
    const int rw = w * 16;
    float qf[32];
    #pragma unroll
    for (int k8 = 0; k8 < 8; k8++) {
        qf[k8*4 + 0] = SB[(rw + g)     * LS + k8*8 + t];
        qf[k8*4 + 1] = SB[(rw + g + 8) * LS + k8*8 + t];
        qf[k8*4 + 2] = SB[(rw + g)     * LS + k8*8 + t + 4];
        qf[k8*4 + 3] = SB[(rw + g + 8) * LS + k8*8 + t + 4];
    }
    __syncthreads();

    float accO[8][4] = {};
    float mrow[2] = {-1e30f, -1e30f};
    float lrow[2] = {0.0f, 0.0f};
    float* SBw = SB + rw * LS;   // this warp's 16 rows

    for (int nb = 0; nb < 32; nb++) {
        const int n0 = nb * 64;
        // ---- stage K, V, short, mask ----
        #pragma unroll
        for (int it = 0; it < 4; it++) {
            int lin = tid + it * 256, row = lin >> 4, c4 = (lin & 15) * 4;
            *(float4*)&Ks[row * LS + c4]      = *(const float4*)&kp[(size_t)(n0 + row) * DK + c4];
            *(float4*)&Vs[row * VSTRIDE + c4] = *(const float4*)&vbase[(size_t)(n0 + row) * Dd + c4];
        }
        #pragma unroll
        for (int it = 0; it < 8; it++) {
            int lin = tid + it * 256, row = lin >> 4, c4 = (lin & 15) * 4;
            *(float4*)&SB[row * LS + c4] = *(const float4*)&sp[(size_t)row * Ll + n0 + c4];
        }
        if (tid < 64) Msk[tid] = mask[b * Ll + n0 + tid];
        __syncthreads();

        // ---- S = Q K^T (3xTF32) ----
        float s[8][4] = {};
        #pragma unroll
        for (int k8 = 0; k8 < 8; k8++) {
            float ah[4], al[4];
            #pragma unroll
            for (int r = 0; r < 4; r++) {
                ah[r] = f2tf32(qf[k8*4 + r]);
                al[r] = qf[k8*4 + r] - ah[r];
            }
            #pragma unroll
            for (int jn = 0; jn < 8; jn++) {
                float b0 = Ks[(jn*8 + g) * LS + k8*8 + t];
                float b1 = Ks[(jn*8 + g) * LS + k8*8 + t + 4];
                float bh0 = f2tf32(b0), bl0 = b0 - bh0;
                float bh1 = f2tf32(b1), bl1 = b1 - bh1;
                mma8(s[jn], ah[0], ah[1], ah[2], ah[3], bh0, bh1);
                mma8(s[jn], ah[0], ah[1], ah[2], ah[3], bl0, bl1);
                mma8(s[jn], al[0], al[1], al[2], al[3], bh0, bh1);
            }
        }

        // ---- scale, mask, +short ----
        #pragma unroll
        for (int jn = 0; jn < 8; jn++) {
            int c0 = jn * 8 + 2 * t;
            int mk0 = Msk[c0], mk1 = Msk[c0 + 1];
            float2 sh0 = *(const float2*)&SBw[(g)     * LS + c0];
            float2 sh1 = *(const float2*)&SBw[(g + 8) * LS + c0];
            s[jn][0] = (mk0 ? s[jn][0] * 0.125f : NEGV) + sh0.x;
            s[jn][1] = (mk1 ? s[jn][1] * 0.125f : NEGV) + sh0.y;
            s[jn][2] = (mk0 ? s[jn][2] * 0.125f : NEGV) + sh1.x;
            s[jn][3] = (mk1 ? s[jn][3] * 0.125f : NEGV) + sh1.y;
        }

        // ---- online softmax (rows g and g+8; quad = 4 lanes) ----
        #pragma unroll
        for (int half = 0; half < 2; half++) {
            const int r0 = half * 2;
            float tm = -1e30f;
            #pragma unroll
            for (int jn = 0; jn < 8; jn++)
                tm = fmaxf(tm, fmaxf(s[jn][r0], s[jn][r0 + 1]));
            tm = fmaxf(tm, __shfl_xor_sync(0xffffffffu, tm, 1));
            tm = fmaxf(tm, __shfl_xor_sync(0xffffffffu, tm, 2));
            float mn = fmaxf(mrow[half], tm);
            float sc = __expf(mrow[half] - mn);
            float ps = 0.0f;
            #pragma unroll
            for (int jn = 0; jn < 8; jn++) {
                s[jn][r0]     = __expf(s[jn][r0]     - mn);
                s[jn][r0 + 1] = __expf(s[jn][r0 + 1] - mn);
                ps += s[jn][r0] + s[jn][r0 + 1];
            }
            ps += __shfl_xor_sync(0xffffffffu, ps, 1);
            ps += __shfl_xor_sync(0xffffffffu, ps, 2);
            lrow[half] = lrow[half] * sc + ps;
            mrow[half] = mn;
            #pragma unroll
            for (int jd = 0; jd < 8; jd++) {
                accO[jd][r0]     *= sc;
                accO[jd][r0 + 1] *= sc;
            }
        }

        // ---- write P to warp-local buffer (overwrites this warp's short rows) ----
        #pragma unroll
        for (int jn = 0; jn < 8; jn++) {
            int c0 = jn * 8 + 2 * t;
            *(float2*)&SBw[(g)     * LS + c0] = make_float2(s[jn][0], s[jn][1]);
            *(float2*)&SBw[(g + 8) * LS + c0] = make_float2(s[jn][2], s[jn][3]);
        }
        __syncwarp();

        // ---- accO += P V (3xTF32) ----
        #pragma unroll
        for (int k8 = 0; k8 < 8; k8++) {
            float pa[4];
            pa[0] = SBw[(g)     * LS + k8*8 + t];
            pa[1] = SBw[(g + 8) * LS + k8*8 + t];
            pa[2] = SBw[(g)     * LS + k8*8 + t + 4];
            pa[3] = SBw[(g + 8) * LS + k8*8 + t + 4];
            float ph[4], pl[4];
            #pragma unroll
            for (int r = 0; r < 4; r++) { ph[r] = f2tf32(pa[r]); pl[r] = pa[r] - ph[r]; }
            #pragma unroll
            for (int jd = 0; jd < 8; jd++) {
                float b0 = Vs[(k8*8 + t)     * VSTRIDE + jd*8 + g];
                float b1 = Vs[(k8*8 + t + 4) * VSTRIDE + jd*8 + g];
                float bh0 = f2tf32(b0), bl0 = b0 - bh0;
                float bh1 = f2tf32(b1), bl1 = b1 - bh1;
                mma8(accO[jd], ph[0], ph[1], ph[2], ph[3], bh0, bh1);
                mma8(accO[jd], ph[0], ph[1], ph[2], ph[3], bl0, bl1);
                mma8(accO[jd], pl[0], pl[1], pl[2], pl[3], bh0, bh1);
            }
        }
        __syncthreads();
    }

    // ---- fused epilogue ----
    const float bm = bias_m[0];
    #pragma unroll
    for (int half = 0; half < 2; half++) {
        const int r0 = half * 2;
        int row = m0 + rw + g + half * 8;
        float piv = g_pi[bh * Ll + row] * 0.2f;
        float inv = 0.8f / lrow[half];
        #pragma unroll
        for (int jd = 0; jd < 8; jd++) {
            int c = jd * 8 + 2 * t;
            float2 sq = *(const float2*)&query[((size_t)b * Ll + row) * Dd + h * DK + c];
            float2 o;
            o.x = accO[jd][r0]     * inv + piv * sq.x + bm;
            o.y = accO[jd][r0 + 1] * inv + piv * sq.y + bm;
            *(float2*)&out[(bh * Ll + row) * DK + c] = o;
        }
    }
}

// ---------------------------------------------------------------------------
extern "C" void kernel_launch(void* const* d_in, const int* in_sizes, int n_in,
                              void* d_out, int out_size)
{
    const float* query  = (const float*)d_in[0];
    const float* key    = (const float*)d_in[1];
    const float* shortb = (const float*)d_in[2];
    const float* aspect = (const float*)d_in[3];
    const int*   mask   = (const int*)d_in[4];
    const float* Wq     = (const float*)d_in[5];
    const float* bq     = (const float*)d_in[6];
    const float* Wk     = (const float*)d_in[7];
    const float* bk     = (const float*)d_in[8];
    const float* w_mu   = (const float*)d_in[9];
    const float* b_mu   = (const float*)d_in[10];
    const float* bias_m = (const float*)d_in[11];
    float* out = (float*)d_out;

    cudaFuncSetAttribute(attn_mma_kernel, cudaFuncAttributeMaxDynamicSharedMemorySize, ATTN_SMEM);

    proj_kernel<<<dim3(32, 12, 2), 256>>>(query, Wq, bq, key, Wk, bk);
    sinkhorn_kernel<<<dim3(12, 2), 256>>>(query, aspect, mask, w_mu, b_mu);
    attn_mma_kernel<<<dim3(16, 12, 2), 256, ATTN_SMEM>>>(query, shortb, mask, bias_m, out);
}

// round 3
// speedup vs baseline: 1.3751x; 1.2667x over previous
#include <cuda_runtime.h>
#include <cstdint>

#define Bb 2
#define Hh 12
#define Ll 2048
#define Dd 768
#define DK 64
#define NEGV (-1000000000.0f)

// scratch
__device__ float g_q[Bb*Hh*Ll*DK];
__device__ float g_k[Bb*Hh*Ll*DK];
__device__ float g_pi[Bb*Hh*Ll];

// ---------------------------------------------------------------------------
// helpers
// ---------------------------------------------------------------------------
__device__ __forceinline__ float f2tf32(float x) {
    uint32_t u;
    asm("cvt.rna.tf32.f32 %0, %1;" : "=r"(u) : "f"(x));
    return __uint_as_float(u);
}

__device__ __forceinline__ void mma8(float d[4], float a0, float a1, float a2, float a3,
                                     float b0, float b1) {
    asm volatile(
        "mma.sync.aligned.m16n8k8.row.col.f32.tf32.tf32.f32 "
        "{%0,%1,%2,%3},{%4,%5,%6,%7},{%8,%9},{%0,%1,%2,%3};\n"
        : "+f"(d[0]), "+f"(d[1]), "+f"(d[2]), "+f"(d[3])
        : "r"(__float_as_uint(a0)), "r"(__float_as_uint(a1)),
          "r"(__float_as_uint(a2)), "r"(__float_as_uint(a3)),
          "r"(__float_as_uint(b0)), "r"(__float_as_uint(b1)));
}

__device__ __forceinline__ uint32_t s2u(const void* p) {
    return (uint32_t)__cvta_generic_to_shared(p);
}
#define CP16(dst, src) asm volatile("cp.async.cg.shared.global [%0], [%1], 16;\n" :: "r"(dst), "l"(src))
#define CPCOMMIT() asm volatile("cp.async.commit_group;\n" ::: "memory")
#define CPWAIT1()  asm volatile("cp.async.wait_group 1;\n" ::: "memory")
#define CPWAIT0()  asm volatile("cp.async.wait_group 0;\n" ::: "memory")

// ---------------------------------------------------------------------------
// Projection GEMM via tf32 mma (3x split): 128 rows x 64 cols (one head) per block.
// ---------------------------------------------------------------------------
#define PROJ_SMEM ((128*68 + 64*68) * 4)

__global__ __launch_bounds__(256) void proj_mma_kernel(
    const float* __restrict__ Aq, const float* __restrict__ Wq, const float* __restrict__ bq,
    const float* __restrict__ Ak, const float* __restrict__ Wk, const float* __restrict__ bk)
{
    const float *A, *W, *bias;
    float* out;
    if (blockIdx.z == 0) { A = Aq; W = Wq; bias = bq; out = g_q; }
    else                 { A = Ak; W = Wk; bias = bk; out = g_k; }

    extern __shared__ float sm[];
    float* As = sm;              // [128][68]  (m, k-chunk)
    float* Bs = sm + 128 * 68;   // [64][68]   (n, k-chunk)

    const int tid = threadIdx.x;
    const int w = tid >> 5, lane = tid & 31;
    const int g = lane >> 2, t = lane & 3;
    const int rw = w * 16;
    const int row0 = blockIdx.x * 128;
    const int h = blockIdx.y;
    const int col0 = h * 64;

    float acc[8][4] = {};

    for (int k0 = 0; k0 < Dd; k0 += 64) {
        #pragma unroll
        for (int it = 0; it < 8; it++) {
            int lin = tid + it * 256, r = lin >> 4, c4 = (lin & 15) * 4;
            *(float4*)&As[r * 68 + c4] = *(const float4*)&A[(size_t)(row0 + r) * Dd + k0 + c4];
        }
        #pragma unroll
        for (int it = 0; it < 4; it++) {
            int lin = tid + it * 256, kr = lin >> 4, n4 = (lin & 15) * 4;
            float4 w4 = *(const float4*)&W[(size_t)(k0 + kr) * Dd + col0 + n4];
            Bs[(n4 + 0) * 68 + kr] = w4.x;
            Bs[(n4 + 1) * 68 + kr] = w4.y;
            Bs[(n4 + 2) * 68 + kr] = w4.z;
            Bs[(n4 + 3) * 68 + kr] = w4.w;
        }
        __syncthreads();
        #pragma unroll
        for (int k8 = 0; k8 < 8; k8++) {
            float a0 = As[(rw + g)     * 68 + k8*8 + t];
            float a1 = As[(rw + g + 8) * 68 + k8*8 + t];
            float a2 = As[(rw + g)     * 68 + k8*8 + t + 4];
            float a3 = As[(rw + g + 8) * 68 + k8*8 + t + 4];
            float ah[4] = {f2tf32(a0), f2tf32(a1), f2tf32(a2), f2tf32(a3)};
            float al[4] = {a0 - ah[0], a1 - ah[1], a2 - ah[2], a3 - ah[3]};
            #pragma unroll
            for (int jn = 0; jn < 8; jn++) {
                float b0 = Bs[(jn*8 + g) * 68 + k8*8 + t];
                float b1 = Bs[(jn*8 + g) * 68 + k8*8 + t + 4];
                float bh0 = f2tf32(b0), bl0 = b0 - bh0;
                float bh1 = f2tf32(b1), bl1 = b1 - bh1;
                mma8(acc[jn], ah[0], ah[1], ah[2], ah[3], bh0, bh1);
                mma8(acc[jn], ah[0], ah[1], ah[2], ah[3], bl0, bl1);
                mma8(acc[jn], al[0], al[1], al[2], al[3], bh0, bh1);
            }
        }
        __syncthreads();
    }

    #pragma unroll
    for (int half = 0; half < 2; half++) {
        const int r0 = half * 2;
        int row = row0 + rw + g + half * 8;
        int b = row >> 11, l = row & (Ll - 1);
        float* op = &out[(((size_t)b * Hh + h) * Ll + l) * DK];
        #pragma unroll
        for (int jn = 0; jn < 8; jn++) {
            int c = jn * 8 + 2 * t;
            float2 o;
            o.x = acc[jn][r0]     + bias[col0 + c];
            o.y = acc[jn][r0 + 1] + bias[col0 + c + 1];
            *(float2*)&op[c] = o;
        }
    }
}

// ---------------------------------------------------------------------------
// Block reductions
// ---------------------------------------------------------------------------
__device__ __forceinline__ float warpSum(float v) {
    #pragma unroll
    for (int o = 16; o; o >>= 1) v += __shfl_xor_sync(0xffffffffu, v, o);
    return v;
}
__device__ __forceinline__ float warpMax(float v) {
    #pragma unroll
    for (int o = 16; o; o >>= 1) v = fmaxf(v, __shfl_xor_sync(0xffffffffu, v, o));
    return v;
}
__device__ float blockSum(float v, float* red) {
    int w = threadIdx.x >> 5, lane = threadIdx.x & 31;
    v = warpSum(v);
    if (lane == 0) red[w] = v;
    __syncthreads();
    if (w == 0) {
        float r = (lane < 8) ? red[lane] : 0.0f;
        r = warpSum(r);
        if (lane == 0) red[0] = r;
    }
    __syncthreads();
    float r = red[0];
    __syncthreads();
    return r;
}
__device__ float blockMax(float v, float* red) {
    int w = threadIdx.x >> 5, lane = threadIdx.x & 31;
    v = warpMax(v);
    if (lane == 0) red[w] = v;
    __syncthreads();
    if (w == 0) {
        float r = (lane < 8) ? red[lane] : -1e30f;
        r = warpMax(r);
        if (lane == 0) red[0] = r;
    }
    __syncthreads();
    float r = red[0];
    __syncthreads();
    return r;
}

// ---------------------------------------------------------------------------
// Sinkhorn OT (unchanged)
// ---------------------------------------------------------------------------
__global__ __launch_bounds__(256) void sinkhorn_kernel(
    const float* __restrict__ query, const float* __restrict__ aspect,
    const int* __restrict__ mask, const float* __restrict__ w_mu,
    const float* __restrict__ b_mu)
{
    const int h = blockIdx.x, b = blockIdx.y;
    const int tid = threadIdx.x;
    __shared__ float aspn[64];
    __shared__ float wmu[64];
    __shared__ float red[8];

    if (tid < 64) {
        aspn[tid] = aspect[b * Dd + h * DK + tid];
        wmu[tid]  = w_mu[tid];
    }
    __syncthreads();

    float ssa = 0.0f;
    #pragma unroll
    for (int d = 0; d < 64; d++) ssa += aspn[d] * aspn[d];
    const float inv_na = 1.0f / fmaxf(sqrtf(ssa), 1e-12f);
    const float bmu = b_mu[0];

    float Kl[8], mu[8], u[8];
    float lmax = -1e30f;
    #pragma unroll
    for (int j = 0; j < 8; j++) {
        int l = tid + j * 256;
        const float* sp = &query[((size_t)b * Ll + l) * Dd + h * DK];
        float sq = 0.0f, da = 0.0f, dm = 0.0f;
        #pragma unroll
        for (int d = 0; d < 64; d += 4) {
            float4 s4 = *(const float4*)&sp[d];
            sq += s4.x * s4.x + s4.y * s4.y + s4.z * s4.z + s4.w * s4.w;
            da += s4.x * aspn[d] + s4.y * aspn[d + 1] + s4.z * aspn[d + 2] + s4.w * aspn[d + 3];
            dm += s4.x * wmu[d]  + s4.y * wmu[d + 1]  + s4.z * wmu[d + 2]  + s4.w * wmu[d + 3];
        }
        float inv_ns = 1.0f / fmaxf(sqrtf(sq), 1e-12f);
        float cosv = da * inv_ns * inv_na;
        Kl[j] = __expf(cosv - 1.0f);
        float lg = dm + bmu;
        if (mask[b * Ll + l] == 0) lg = NEGV;
        mu[j] = lg;
        lmax = fmaxf(lmax, lg);
    }
    lmax = blockMax(lmax, red);
    float lsum = 0.0f;
    #pragma unroll
    for (int j = 0; j < 8; j++) { mu[j] = __expf(mu[j] - lmax); lsum += mu[j]; }
    lsum = blockSum(lsum, red);
    float inv = 1.0f / lsum;
    #pragma unroll
    for (int j = 0; j < 8; j++) mu[j] *= inv;

    float v = 1.0f;
    for (int it = 0; it < 50; it++) {
        float part = 0.0f;
        #pragma unroll
        for (int j = 0; j < 8; j++) {
            u[j] = mu[j] / (Kl[j] * v + 1e-8f);
            part += Kl[j] * u[j];
        }
        float S = blockSum(part, red);
        v = 1.0f / (S + 1e-8f);
    }
    #pragma unroll
    for (int j = 0; j < 8; j++)
        g_pi[((size_t)b * Hh + h) * Ll + tid + j * 256] = u[j] * Kl[j] * v;
}

// ---------------------------------------------------------------------------
// Attention via tf32 mma (3x split), cp.async double-buffered `short` stream.
// Block: 128 rows of one (b,h), 8 warps x 16 rows, 64-col chunks.
// ---------------------------------------------------------------------------
#define LS 68
#define VSTRIDE 72
#define ATTN_SMEM ((128*68*2 + 64*68 + 64*72) * 4 + 64 * 4)

__global__ __launch_bounds__(256, 2) void attn_mma_kernel(
    const float* __restrict__ query, const float* __restrict__ shortb,
    const int* __restrict__ mask, const float* __restrict__ bias_m,
    float* __restrict__ out)
{
    extern __shared__ float sm[];
    float* SB0 = sm;                   // [128][68] short/P buffer 0 (also Q staging)
    float* SB1 = SB0 + 128 * LS;       // [128][68] short buffer 1
    float* Ks  = SB1 + 128 * LS;       // [64][68]
    float* Vs  = Ks + 64 * LS;         // [64][72]
    int*  Msk  = (int*)(Vs + 64 * VSTRIDE);

    const int tid = threadIdx.x;
    const int w = tid >> 5, lane = tid & 31;
    const int g = lane >> 2, t = lane & 3;
    const int m0 = blockIdx.x * 128;
    const int h = blockIdx.y, b = blockIdx.z;
    const size_t bh = (size_t)b * Hh + h;
    const float* qp = g_q + bh * Ll * DK;
    const float* kp = g_k + bh * Ll * DK;
    const float* vbase = query + (size_t)b * Ll * Dd + h * DK;
    const float* sp = shortb + (bh * Ll + m0) * Ll;

    // per-thread staging coords
    const int rw = w * 16;

    // ---- stage Q (plain; L2-resident), extract A-fragments ----
    #pragma unroll
    for (int it = 0; it < 8; it++) {
        int lin = tid + it * 256, row = lin >> 4, c4 = (lin & 15) * 4;
        *(float4*)&SB0[row * LS + c4] = *(const float4*)&qp[(size_t)(m0 + row) * DK + c4];
    }
    __syncthreads();
    float qf[32];
    #pragma unroll
    for (int k8 = 0; k8 < 8; k8++) {
        qf[k8*4 + 0] = SB0[(rw + g)     * LS + k8*8 + t];
        qf[k8*4 + 1] = SB0[(rw + g + 8) * LS + k8*8 + t];
        qf[k8*4 + 2] = SB0[(rw + g)     * LS + k8*8 + t + 4];
        qf[k8*4 + 3] = SB0[(rw + g + 8) * LS + k8*8 + t + 4];
    }
    __syncthreads();

    // ---- prologue: short[0] -> SB0 (group A0), KV[0]+mask (group B0) ----
    #pragma unroll
    for (int it = 0; it < 8; it++) {
        int lin = tid + it * 256, row = lin >> 4, c4 = (lin & 15) * 4;
        CP16(s2u(&SB0[row * LS + c4]), &sp[(size_t)row * Ll + c4]);
    }
    CPCOMMIT();
    #pragma unroll
    for (int it = 0; it < 4; it++) {
        int lin = tid + it * 256, row = lin >> 4, c4 = (lin & 15) * 4;
        CP16(s2u(&Ks[row * LS + c4]),      &kp[(size_t)row * DK + c4]);
        CP16(s2u(&Vs[row * VSTRIDE + c4]), &vbase[(size_t)row * Dd + c4]);
    }
    if (tid < 16) CP16(s2u(&Msk[tid * 4]), &mask[b * Ll + tid * 4]);
    CPCOMMIT();

    float accO[8][4] = {};
    float mrow[2] = {-1e30f, -1e30f};
    float lrow[2] = {0.0f, 0.0f};

    for (int nb = 0; nb < 32; nb++) {
        const int n0 = nb * 64;
        float* SBc = (nb & 1) ? SB1 : SB0;
        float* SBa = (nb & 1) ? SB0 : SB1;
        float* SBw = SBc + rw * LS;

        // prefetch next short chunk into alt buffer (group A_{nb+1})
        const int n1 = (nb < 31 ? nb + 1 : 31) * 64;
        #pragma unroll
        for (int it = 0; it < 8; it++) {
            int lin = tid + it * 256, row = lin >> 4, c4 = (lin & 15) * 4;
            CP16(s2u(&SBa[row * LS + c4]), &sp[(size_t)row * Ll + n1 + c4]);
        }
        CPCOMMIT();

        // wait: everything except the just-issued prefetch
        CPWAIT1();
        __syncthreads();

        // ---- S = Q K^T (3xTF32) ----
        float s[8][4] = {};
        #pragma unroll
        for (int k8 = 0; k8 < 8; k8++) {
            float ah[4], al[4];
            #pragma unroll
            for (int r = 0; r < 4; r++) {
                ah[r] = f2tf32(qf[k8*4 + r]);
                al[r] = qf[k8*4 + r] - ah[r];
            }
            #pragma unroll
            for (int jn = 0; jn < 8; jn++) {
                float b0 = Ks[(jn*8 + g) * LS + k8*8 + t];
                float b1 = Ks[(jn*8 + g) * LS + k8*8 + t + 4];
                float bh0 = f2tf32(b0), bl0 = b0 - bh0;
                float bh1 = f2tf32(b1), bl1 = b1 - bh1;
                mma8(s[jn], ah[0], ah[1], ah[2], ah[3], bh0, bh1);
                mma8(s[jn], ah[0], ah[1], ah[2], ah[3], bl0, bl1);
                mma8(s[jn], al[0], al[1], al[2], al[3], bh0, bh1);
            }
        }

        // ---- scale, mask, +short ----
        #pragma unroll
        for (int jn = 0; jn < 8; jn++) {
            int c0 = jn * 8 + 2 * t;
            int mk0 = Msk[c0], mk1 = Msk[c0 + 1];
            float2 sh0 = *(const float2*)&SBw[(g)     * LS + c0];
            float2 sh1 = *(const float2*)&SBw[(g + 8) * LS + c0];
            s[jn][0] = (mk0 ? s[jn][0] * 0.125f : NEGV) + sh0.x;
            s[jn][1] = (mk1 ? s[jn][1] * 0.125f : NEGV) + sh0.y;
            s[jn][2] = (mk0 ? s[jn][2] * 0.125f : NEGV) + sh1.x;
            s[jn][3] = (mk1 ? s[jn][3] * 0.125f : NEGV) + sh1.y;
        }

        // ---- online softmax ----
        #pragma unroll
        for (int half = 0; half < 2; half++) {
            const int r0 = half * 2;
            float tm = -1e30f;
            #pragma unroll
            for (int jn = 0; jn < 8; jn++)
                tm = fmaxf(tm, fmaxf(s[jn][r0], s[jn][r0 + 1]));
            tm = fmaxf(tm, __shfl_xor_sync(0xffffffffu, tm, 1));
            tm = fmaxf(tm, __shfl_xor_sync(0xffffffffu, tm, 2));
            float mn = fmaxf(mrow[half], tm);
            float sc = __expf(mrow[half] - mn);
            float ps = 0.0f;
            #pragma unroll
            for (int jn = 0; jn < 8; jn++) {
                s[jn][r0]     = __expf(s[jn][r0]     - mn);
                s[jn][r0 + 1] = __expf(s[jn][r0 + 1] - mn);
                ps += s[jn][r0] + s[jn][r0 + 1];
            }
            ps += __shfl_xor_sync(0xffffffffu, ps, 1);
            ps += __shfl_xor_sync(0xffffffffu, ps, 2);
            lrow[half] = lrow[half] * sc + ps;
            mrow[half] = mn;
            #pragma unroll
            for (int jd = 0; jd < 8; jd++) {
                accO[jd][r0]     *= sc;
                accO[jd][r0 + 1] *= sc;
            }
        }

        // ---- write P into this warp's rows of current buffer ----
        #pragma unroll
        for (int jn = 0; jn < 8; jn++) {
            int c0 = jn * 8 + 2 * t;
            *(float2*)&SBw[(g)     * LS + c0] = make_float2(s[jn][0], s[jn][1]);
            *(float2*)&SBw[(g + 8) * LS + c0] = make_float2(s[jn][2], s[jn][3]);
        }
        __syncwarp();

        // ---- accO += P V (3xTF32) ----
        #pragma unroll
        for (int k8 = 0; k8 < 8; k8++) {
            float pa[4];
            pa[0] = SBw[(g)     * LS + k8*8 + t];
            pa[1] = SBw[(g + 8) * LS + k8*8 + t];
            pa[2] = SBw[(g)     * LS + k8*8 + t + 4];
            pa[3] = SBw[(g + 8) * LS + k8*8 + t + 4];
            float ph[4], pl[4];
            #pragma unroll
            for (int r = 0; r < 4; r++) { ph[r] = f2tf32(pa[r]); pl[r] = pa[r] - ph[r]; }
            #pragma unroll
            for (int jd = 0; jd < 8; jd++) {
                float b0 = Vs[(k8*8 + t)     * VSTRIDE + jd*8 + g];
                float b1 = Vs[(k8*8 + t + 4) * VSTRIDE + jd*8 + g];
                float bh0 = f2tf32(b0), bl0 = b0 - bh0;
                float bh1 = f2tf32(b1), bl1 = b1 - bh1;
                mma8(accO[jd], ph[0], ph[1], ph[2], ph[3], bh0, bh1);
                mma8(accO[jd], ph[0], ph[1], ph[2], ph[3], bl0, bl1);
                mma8(accO[jd], pl[0], pl[1], pl[2], pl[3], bh0, bh1);
            }
        }
        __syncthreads();

        // ---- issue next K/V/mask (group B_{nb+1}) ----
        if (nb < 31) {
            const int n2 = (nb + 1) * 64;
            #pragma unroll
            for (int it = 0; it < 4; it++) {
                int lin = tid + it * 256, row = lin >> 4, c4 = (lin & 15) * 4;
                CP16(s2u(&Ks[row * LS + c4]),      &kp[(size_t)(n2 + row) * DK + c4]);
                CP16(s2u(&Vs[row * VSTRIDE + c4]), &vbase[(size_t)(n2 + row) * Dd + c4]);
            }
            if (tid < 16) CP16(s2u(&Msk[tid * 4]), &mask[b * Ll + n2 + tid * 4]);
            CPCOMMIT();
        }
    }
    CPWAIT0();

    // ---- fused epilogue ----
    const float bm = bias_m[0];
    #pragma unroll
    for (int half = 0; half < 2; half++) {
        const int r0 = half * 2;
        int row = m0 + rw + g + half * 8;
        float piv = g_pi[bh * Ll + row] * 0.2f;
        float inv = 0.8f / lrow[half];
        #pragma unroll
        for (int jd = 0; jd < 8; jd++) {
            int c = jd * 8 + 2 * t;
            float2 sq = *(const float2*)&query[((size_t)b * Ll + row) * Dd + h * DK + c];
            float2 o;
            o.x = accO[jd][r0]     * inv + piv * sq.x + bm;
            o.y = accO[jd][r0 + 1] * inv + piv * sq.y + bm;
            *(float2*)&out[(bh * Ll + row) * DK + c] = o;
        }
    }
}

// ---------------------------------------------------------------------------
extern "C" void kernel_launch(void* const* d_in, const int* in_sizes, int n_in,
                              void* d_out, int out_size)
{
    const float* query  = (const float*)d_in[0];
    const float* key    = (const float*)d_in[1];
    const float* shortb = (const float*)d_in[2];
    const float* aspect = (const float*)d_in[3];
    const int*   mask   = (const int*)d_in[4];
    const float* Wq     = (const float*)d_in[5];
    const float* bq     = (const float*)d_in[6];
    const float* Wk     = (const float*)d_in[7];
    const float* bk     = (const float*)d_in[8];
    const float* w_mu   = (const float*)d_in[9];
    const float* b_mu   = (const float*)d_in[10];
    const float* bias_m = (const float*)d_in[11];
    float* out = (float*)d_out;

    cudaFuncSetAttribute(proj_mma_kernel, cudaFuncAttributeMaxDynamicSharedMemorySize, PROJ_SMEM);
    cudaFuncSetAttribute(attn_mma_kernel, cudaFuncAttributeMaxDynamicSharedMemorySize, ATTN_SMEM);

    proj_mma_kernel<<<dim3(32, 12, 2), 256, PROJ_SMEM>>>(query, Wq, bq, key, Wk, bk);
    sinkhorn_kernel<<<dim3(12, 2), 256>>>(query, aspect, mask, w_mu, b_mu);
    attn_mma_kernel<<<dim3(16, 12, 2), 256, ATTN_SMEM>>>(query, shortb, mask, bias_m, out);
}

// round 4
// speedup vs baseline: 2.2690x; 1.6501x over previous
#include <cuda_runtime.h>
#include <cuda_fp16.h>
#include <cstdint>

#define Bb 2
#define Hh 12
#define Ll 2048
#define Dd 768
#define DK 64
#define NEGV (-1000000000.0f)

// ---------------------------------------------------------------------------
// global scratch (pre-split half2 representations)
// ---------------------------------------------------------------------------
__device__ uint32_t g_qh[Bb*Hh*Ll*32], g_ql[Bb*Hh*Ll*32];   // proj q output [bh*L + l][k2]
__device__ uint32_t g_kh[Bb*Hh*Ll*32], g_kl[Bb*Hh*Ll*32];   // proj k output
__device__ uint32_t g_wh[2][Hh*64*384], g_wl[2][Hh*64*384]; // [qk][h][n][k2]
__device__ uint32_t g_ah[2][4096*384],  g_al[2][4096*384];  // [qk][row][k2]
__device__ uint32_t g_vh[Bb*Hh*1024*64], g_vl[Bb*Hh*1024*64]; // [bh][n2][d]
__device__ float g_pi[Bb*Hh*Ll];

// ---------------------------------------------------------------------------
// helpers
// ---------------------------------------------------------------------------
__device__ __forceinline__ void split2(float x, float y, uint32_t& h, uint32_t& l) {
    __half2 hh = __floats2half2_rn(x, y);
    float rx = x - __low2float(hh);
    float ry = y - __high2float(hh);
    __half2 ll = __floats2half2_rn(rx, ry);
    h = *(uint32_t*)&hh;
    l = *(uint32_t*)&ll;
}

__device__ __forceinline__ void mma16(float d[4], uint32_t a0, uint32_t a1, uint32_t a2,
                                      uint32_t a3, uint32_t b0, uint32_t b1) {
    asm volatile(
        "mma.sync.aligned.m16n8k16.row.col.f32.f16.f16.f32 "
        "{%0,%1,%2,%3},{%4,%5,%6,%7},{%8,%9},{%0,%1,%2,%3};\n"
        : "+f"(d[0]), "+f"(d[1]), "+f"(d[2]), "+f"(d[3])
        : "r"(a0), "r"(a1), "r"(a2), "r"(a3), "r"(b0), "r"(b1));
}

__device__ __forceinline__ uint32_t s2u(const void* p) {
    return (uint32_t)__cvta_generic_to_shared(p);
}
#define CP16(dst, src) asm volatile("cp.async.cg.shared.global [%0], [%1], 16;\n" :: "r"(dst), "l"(src))
#define CPCOMMIT() asm volatile("cp.async.commit_group;\n" ::: "memory")
#define CPWAIT1()  asm volatile("cp.async.wait_group 1;\n" ::: "memory")
#define CPWAIT0()  asm volatile("cp.async.wait_group 0;\n" ::: "memory")

// ---------------------------------------------------------------------------
// prep kernels: one-time fp32 -> (h,l) half2-pair splits
// ---------------------------------------------------------------------------
__global__ __launch_bounds__(256) void prep_w_kernel(
    const float* __restrict__ Wq, const float* __restrict__ Wk)
{
    int idx = blockIdx.x * 256 + threadIdx.x;          // < 2*294912
    int qk = idx >= (Hh*64*384);
    int r = idx - qk * (Hh*64*384);
    int h  = r / (64*384);
    int r2 = r % (64*384);
    int n  = r2 / 384;
    int k2 = r2 % 384;
    const float* W = qk ? Wk : Wq;
    int col = h * 64 + n;
    float a = W[(size_t)(2*k2) * Dd + col];
    float b = W[(size_t)(2*k2 + 1) * Dd + col];
    uint32_t hh, ll;
    split2(a, b, hh, ll);
    g_wh[qk][r] = hh;
    g_wl[qk][r] = ll;
}

__global__ __launch_bounds__(256) void prep_a_kernel(
    const float* __restrict__ query, const float* __restrict__ key)
{
    int idx = blockIdx.x * 256 + threadIdx.x;          // < 2*1572864
    int qk = idx >= (4096*384);
    int r = idx - qk * (4096*384);
    int row = r / 384;
    int k2  = r % 384;
    const float* src = qk ? key : query;
    float2 f = *(const float2*)&src[(size_t)row * Dd + 2*k2];
    uint32_t hh, ll;
    split2(f.x, f.y, hh, ll);
    g_ah[qk][r] = hh;
    g_al[qk][r] = ll;
}

__global__ __launch_bounds__(256) void prep_v_kernel(const float* __restrict__ query)
{
    int idx = blockIdx.x * 256 + threadIdx.x;          // < 1572864
    int bh  = idx >> 16;           // / (1024*64)
    int rem = idx & 65535;
    int n2  = rem >> 6;
    int d   = rem & 63;
    int b = bh / Hh, h = bh % Hh;
    const float* q0 = &query[(size_t)(b * Ll + 2*n2) * Dd + h * DK + d];
    uint32_t hh, ll;
    split2(q0[0], q0[Dd], hh, ll);
    g_vh[idx] = hh;
    g_vl[idx] = ll;
}

// ---------------------------------------------------------------------------
// Projection GEMM, fp16 3x-split mma. 128 rows x 64 cols (one head) per block.
// Double-buffered cp.async of pre-split A and W. Output written pre-split.
// ---------------------------------------------------------------------------
#define PROJ_SET 13824   // u32 per buffer set: Ah 4608 + Al 4608 + Wh 2304 + Wl 2304
#define PROJ_SMEM (2 * PROJ_SET * 4)

__global__ __launch_bounds__(256, 2) void proj_mma_kernel(
    const float* __restrict__ bq, const float* __restrict__ bk)
{
    extern __shared__ uint32_t psm[];
    const int qk = blockIdx.z;
    const int tid = threadIdx.x;
    const int w = tid >> 5, lane = tid & 31, g = lane >> 2, t = lane & 3;
    const int rw = w * 16;
    const int row0 = blockIdx.x * 128;
    const int h = blockIdx.y;

    const uint32_t* Agh = g_ah[qk];
    const uint32_t* Agl = g_al[qk];
    const uint32_t* Wgh = g_wh[qk];
    const uint32_t* Wgl = g_wl[qk];
    const float* bias = qk ? bk : bq;

    const int mA = tid >> 1, kbA = (tid & 1) * 16;
    const int nW = tid >> 2, kbW = (tid & 3) * 8;

    // staging of one 64-k block (32 k2)
    auto issue = [&](int kb) {
        uint32_t* S  = psm + (kb & 1) * PROJ_SET;
        uint32_t* Ah = S;
        uint32_t* Al = S + 4608;
        uint32_t* Wh = S + 9216;
        uint32_t* Wl = S + 11520;
        const uint32_t* sa  = &Agh[(size_t)(row0 + mA) * 384 + kb*32 + kbA];
        const uint32_t* sal = &Agl[(size_t)(row0 + mA) * 384 + kb*32 + kbA];
        #pragma unroll
        for (int i = 0; i < 4; i++) {
            CP16(s2u(&Ah[mA*36 + kbA + i*4]), sa + i*4);
            CP16(s2u(&Al[mA*36 + kbA + i*4]), sal + i*4);
        }
        const uint32_t* sw  = &Wgh[(size_t)(h*64 + nW) * 384 + kb*32 + kbW];
        const uint32_t* swl = &Wgl[(size_t)(h*64 + nW) * 384 + kb*32 + kbW];
        CP16(s2u(&Wh[nW*36 + kbW]),     sw);
        CP16(s2u(&Wh[nW*36 + kbW + 4]), sw + 4);
        CP16(s2u(&Wl[nW*36 + kbW]),     swl);
        CP16(s2u(&Wl[nW*36 + kbW + 4]), swl + 4);
        CPCOMMIT();
    };

    issue(0);
    float acc[8][4] = {};

    for (int kb = 0; kb < 12; kb++) {
        if (kb < 11) { issue(kb + 1); CPWAIT1(); } else { CPWAIT0(); }
        __syncthreads();
        uint32_t* S  = psm + (kb & 1) * PROJ_SET;
        uint32_t* Ah = S;
        uint32_t* Al = S + 4608;
        uint32_t* Wh = S + 9216;
        uint32_t* Wl = S + 11520;
        #pragma unroll
        for (int j = 0; j < 4; j++) {
            uint32_t ah0 = Ah[(rw+g)  *36 + 8*j + t];
            uint32_t ah1 = Ah[(rw+g+8)*36 + 8*j + t];
            uint32_t ah2 = Ah[(rw+g)  *36 + 8*j + t + 4];
            uint32_t ah3 = Ah[(rw+g+8)*36 + 8*j + t + 4];
            uint32_t al0 = Al[(rw+g)  *36 + 8*j + t];
            uint32_t al1 = Al[(rw+g+8)*36 + 8*j + t];
            uint32_t al2 = Al[(rw+g)  *36 + 8*j + t + 4];
            uint32_t al3 = Al[(rw+g+8)*36 + 8*j + t + 4];
            #pragma unroll
            for (int jn = 0; jn < 8; jn++) {
                uint32_t b0 = Wh[(jn*8+g)*36 + 8*j + t];
                uint32_t b1 = Wh[(jn*8+g)*36 + 8*j + t + 4];
                uint32_t c0 = Wl[(jn*8+g)*36 + 8*j + t];
                uint32_t c1 = Wl[(jn*8+g)*36 + 8*j + t + 4];
                mma16(acc[jn], ah0, ah1, ah2, ah3, b0, b1);
                mma16(acc[jn], ah0, ah1, ah2, ah3, c0, c1);
                mma16(acc[jn], al0, al1, al2, al3, b0, b1);
            }
        }
        __syncthreads();
    }

    // epilogue: +bias, split, store packed halves
    uint32_t* oh = qk ? g_kh : g_qh;
    uint32_t* ol = qk ? g_kl : g_ql;
    const int col0 = h * 64;
    #pragma unroll
    for (int jn = 0; jn < 8; jn++) {
        float2 bb = *(const float2*)&bias[col0 + jn*8 + 2*t];
        int row = row0 + rw + g;
        int b_ = row >> 11, l = row & (Ll - 1);
        size_t base = ((size_t)(b_ * Hh + h) * Ll + l) * 32 + jn*4 + t;
        uint32_t hh, llv;
        split2(acc[jn][0] + bb.x, acc[jn][1] + bb.y, hh, llv);
        oh[base] = hh; ol[base] = llv;
        int row2 = row + 8;
        int b2 = row2 >> 11, l2 = row2 & (Ll - 1);
        size_t base2 = ((size_t)(b2 * Hh + h) * Ll + l2) * 32 + jn*4 + t;
        split2(acc[jn][2] + bb.x, acc[jn][3] + bb.y, hh, llv);
        oh[base2] = hh; ol[base2] = llv;
    }
}

// ---------------------------------------------------------------------------
// Block reductions
// ---------------------------------------------------------------------------
__device__ __forceinline__ float warpSum(float v) {
    #pragma unroll
    for (int o = 16; o; o >>= 1) v += __shfl_xor_sync(0xffffffffu, v, o);
    return v;
}
__device__ __forceinline__ float warpMax(float v) {
    #pragma unroll
    for (int o = 16; o; o >>= 1) v = fmaxf(v, __shfl_xor_sync(0xffffffffu, v, o));
    return v;
}
__device__ float blockSum(float v, float* red) {
    int w = threadIdx.x >> 5, lane = threadIdx.x & 31;
    v = warpSum(v);
    if (lane == 0) red[w] = v;
    __syncthreads();
    if (w == 0) {
        float r = (lane < 8) ? red[lane] : 0.0f;
        r = warpSum(r);
        if (lane == 0) red[0] = r;
    }
    __syncthreads();
    float r = red[0];
    __syncthreads();
    return r;
}
__device__ float blockMax(float v, float* red) {
    int w = threadIdx.x >> 5, lane = threadIdx.x & 31;
    v = warpMax(v);
    if (lane == 0) red[w] = v;
    __syncthreads();
    if (w == 0) {
        float r = (lane < 8) ? red[lane] : -1e30f;
        r = warpMax(r);
        if (lane == 0) red[0] = r;
    }
    __syncthreads();
    float r = red[0];
    __syncthreads();
    return r;
}

// ---------------------------------------------------------------------------
// Sinkhorn OT (unchanged)
// ---------------------------------------------------------------------------
__global__ __launch_bounds__(256) void sinkhorn_kernel(
    const float* __restrict__ query, const float* __restrict__ aspect,
    const int* __restrict__ mask, const float* __restrict__ w_mu,
    const float* __restrict__ b_mu)
{
    const int h = blockIdx.x, b = blockIdx.y;
    const int tid = threadIdx.x;
    __shared__ float aspn[64];
    __shared__ float wmu[64];
    __shared__ float red[8];

    if (tid < 64) {
        aspn[tid] = aspect[b * Dd + h * DK + tid];
        wmu[tid]  = w_mu[tid];
    }
    __syncthreads();

    float ssa = 0.0f;
    #pragma unroll
    for (int d = 0; d < 64; d++) ssa += aspn[d] * aspn[d];
    const float inv_na = 1.0f / fmaxf(sqrtf(ssa), 1e-12f);
    const float bmu = b_mu[0];

    float Kl[8], mu[8], u[8];
    float lmax = -1e30f;
    #pragma unroll
    for (int j = 0; j < 8; j++) {
        int l = tid + j * 256;
        const float* sp = &query[((size_t)b * Ll + l) * Dd + h * DK];
        float sq = 0.0f, da = 0.0f, dm = 0.0f;
        #pragma unroll
        for (int d = 0; d < 64; d += 4) {
            float4 s4 = *(const float4*)&sp[d];
            sq += s4.x * s4.x + s4.y * s4.y + s4.z * s4.z + s4.w * s4.w;
            da += s4.x * aspn[d] + s4.y * aspn[d + 1] + s4.z * aspn[d + 2] + s4.w * aspn[d + 3];
            dm += s4.x * wmu[d]  + s4.y * wmu[d + 1]  + s4.z * wmu[d + 2]  + s4.w * wmu[d + 3];
        }
        float inv_ns = 1.0f / fmaxf(sqrtf(sq), 1e-12f);
        float cosv = da * inv_ns * inv_na;
        Kl[j] = __expf(cosv - 1.0f);
        float lg = dm + bmu;
        if (mask[b * Ll + l] == 0) lg = NEGV;
        mu[j] = lg;
        lmax = fmaxf(lmax, lg);
    }
    lmax = blockMax(lmax, red);
    float lsum = 0.0f;
    #pragma unroll
    for (int j = 0; j < 8; j++) { mu[j] = __expf(mu[j] - lmax); lsum += mu[j]; }
    lsum = blockSum(lsum, red);
    float inv = 1.0f / lsum;
    #pragma unroll
    for (int j = 0; j < 8; j++) mu[j] *= inv;

    float v = 1.0f;
    for (int it = 0; it < 50; it++) {
        float part = 0.0f;
        #pragma unroll
        for (int j = 0; j < 8; j++) {
            u[j] = mu[j] / (Kl[j] * v + 1e-8f);
            part += Kl[j] * u[j];
        }
        float S = blockSum(part, red);
        v = 1.0f / (S + 1e-8f);
    }
    #pragma unroll
    for (int j = 0; j < 8; j++)
        g_pi[((size_t)b * Hh + h) * Ll + tid + j * 256] = u[j] * Kl[j] * v;
}

// ---------------------------------------------------------------------------
// Attention, fp16 3x-split mma, all staging via cp.async.
// Block: 128 rows of one (b,h), 8 warps x 16 rows, 64-col chunks.
// ---------------------------------------------------------------------------
#define LS 68
#define ATTN_SMEM ((128*68*2) * 4 + (2304*4) * 4 + 64 * 4)

__global__ __launch_bounds__(256, 2) void attn_mma_kernel(
    const float* __restrict__ query, const float* __restrict__ shortb,
    const int* __restrict__ mask, const float* __restrict__ bias_m,
    float* __restrict__ out)
{
    extern __shared__ float smb[];
    float* SB0 = smb;                        // [128][68] short buffer 0
    float* SB1 = SB0 + 128 * LS;             // [128][68] short buffer 1
    uint32_t* Khs = (uint32_t*)(SB1 + 128 * LS);  // [64][36]
    uint32_t* Kls = Khs + 2304;
    uint32_t* Vhs = Kls + 2304;              // [32][72]
    uint32_t* Vls = Vhs + 2304;
    int* Msk = (int*)(Vls + 2304);           // [64]

    const int tid = threadIdx.x;
    const int w = tid >> 5, lane = tid & 31;
    const int g = lane >> 2, t = lane & 3;
    const int rw = w * 16;
    const int m0 = blockIdx.x * 128;
    const int h = blockIdx.y, b = blockIdx.z;
    const size_t bh = (size_t)b * Hh + h;
    const float* sp = shortb + (bh * Ll + m0) * Ll;

    // ---- Q fragments straight from pre-split globals ----
    uint32_t qh[16], ql[16];
    {
        const uint32_t* qhp  = &g_qh[(bh * Ll + m0 + rw + g) * 32];
        const uint32_t* qhp8 = qhp + 8 * 32;
        const uint32_t* qlp  = &g_ql[(bh * Ll + m0 + rw + g) * 32];
        const uint32_t* qlp8 = qlp + 8 * 32;
        #pragma unroll
        for (int j = 0; j < 4; j++) {
            qh[j*4 + 0] = qhp [8*j + t];
            qh[j*4 + 1] = qhp8[8*j + t];
            qh[j*4 + 2] = qhp [8*j + t + 4];
            qh[j*4 + 3] = qhp8[8*j + t + 4];
            ql[j*4 + 0] = qlp [8*j + t];
            ql[j*4 + 1] = qlp8[8*j + t];
            ql[j*4 + 2] = qlp [8*j + t + 4];
            ql[j*4 + 3] = qlp8[8*j + t + 4];
        }
    }

    const int nK = tid >> 2, kbK = (tid & 3) * 8;
    const int n2V = tid >> 3, dbV = (tid & 7) * 8;

    auto issueShort = [&](int n0, float* SBdst) {
        #pragma unroll
        for (int it = 0; it < 8; it++) {
            int lin = tid + it * 256, row = lin >> 4, c4 = (lin & 15) * 4;
            CP16(s2u(&SBdst[row * LS + c4]), &sp[(size_t)row * Ll + n0 + c4]);
        }
        CPCOMMIT();
    };
    auto issueKV = [&](int n0) {
        const uint32_t* skh = &g_kh[(bh * Ll + n0 + nK) * 32 + kbK];
        const uint32_t* skl = &g_kl[(bh * Ll + n0 + nK) * 32 + kbK];
        CP16(s2u(&Khs[nK*36 + kbK]),     skh);
        CP16(s2u(&Khs[nK*36 + kbK + 4]), skh + 4);
        CP16(s2u(&Kls[nK*36 + kbK]),     skl);
        CP16(s2u(&Kls[nK*36 + kbK + 4]), skl + 4);
        const uint32_t* svh = &g_vh[(bh * 1024 + (n0 >> 1) + n2V) * 64 + dbV];
        const uint32_t* svl = &g_vl[(bh * 1024 + (n0 >> 1) + n2V) * 64 + dbV];
        CP16(s2u(&Vhs[n2V*72 + dbV]),     svh);
        CP16(s2u(&Vhs[n2V*72 + dbV + 4]), svh + 4);
        CP16(s2u(&Vls[n2V*72 + dbV]),     svl);
        CP16(s2u(&Vls[n2V*72 + dbV + 4]), svl + 4);
        if (tid < 16) CP16(s2u(&Msk[tid * 4]), &mask[b * Ll + n0 + tid * 4]);
        CPCOMMIT();
    };

    // prologue
    issueShort(0, SB0);
    issueKV(0);

    float accO[8][4] = {};
    float mrow[2] = {-1e30f, -1e30f};
    float lrow[2] = {0.0f, 0.0f};

    for (int nb = 0; nb < 32; nb++) {
        float* SBc = (nb & 1) ? SB1 : SB0;
        float* SBa = (nb & 1) ? SB0 : SB1;
        float* SBw = SBc + rw * LS;

        issueShort((nb < 31 ? nb + 1 : 31) * 64, SBa);
        CPWAIT1();
        __syncthreads();

        // ---- S = Q K^T ----
        float s[8][4] = {};
        #pragma unroll
        for (int j = 0; j < 4; j++) {
            #pragma unroll
            for (int jn = 0; jn < 8; jn++) {
                uint32_t b0 = Khs[(jn*8+g)*36 + 8*j + t];
                uint32_t b1 = Khs[(jn*8+g)*36 + 8*j + t + 4];
                uint32_t c0 = Kls[(jn*8+g)*36 + 8*j + t];
                uint32_t c1 = Kls[(jn*8+g)*36 + 8*j + t + 4];
                mma16(s[jn], qh[j*4], qh[j*4+1], qh[j*4+2], qh[j*4+3], b0, b1);
                mma16(s[jn], qh[j*4], qh[j*4+1], qh[j*4+2], qh[j*4+3], c0, c1);
                mma16(s[jn], ql[j*4], ql[j*4+1], ql[j*4+2], ql[j*4+3], b0, b1);
            }
        }

        // ---- scale, mask, +short ----
        #pragma unroll
        for (int jn = 0; jn < 8; jn++) {
            int c0 = jn * 8 + 2 * t;
            int mk0 = Msk[c0], mk1 = Msk[c0 + 1];
            float2 sh0 = *(const float2*)&SBw[(g)     * LS + c0];
            float2 sh1 = *(const float2*)&SBw[(g + 8) * LS + c0];
            s[jn][0] = (mk0 ? s[jn][0] * 0.125f : NEGV) + sh0.x;
            s[jn][1] = (mk1 ? s[jn][1] * 0.125f : NEGV) + sh0.y;
            s[jn][2] = (mk0 ? s[jn][2] * 0.125f : NEGV) + sh1.x;
            s[jn][3] = (mk1 ? s[jn][3] * 0.125f : NEGV) + sh1.y;
        }

        // ---- online softmax (rows g and g+8) ----
        #pragma unroll
        for (int half = 0; half < 2; half++) {
            const int r0 = half * 2;
            float tm = -1e30f;
            #pragma unroll
            for (int jn = 0; jn < 8; jn++)
                tm = fmaxf(tm, fmaxf(s[jn][r0], s[jn][r0 + 1]));
            tm = fmaxf(tm, __shfl_xor_sync(0xffffffffu, tm, 1));
            tm = fmaxf(tm, __shfl_xor_sync(0xffffffffu, tm, 2));
            float mn = fmaxf(mrow[half], tm);
            float sc = __expf(mrow[half] - mn);
            float ps = 0.0f;
            #pragma unroll
            for (int jn = 0; jn < 8; jn++) {
                s[jn][r0]     = __expf(s[jn][r0]     - mn);
                s[jn][r0 + 1] = __expf(s[jn][r0 + 1] - mn);
                ps += s[jn][r0] + s[jn][r0 + 1];
            }
            ps += __shfl_xor_sync(0xffffffffu, ps, 1);
            ps += __shfl_xor_sync(0xffffffffu, ps, 2);
            lrow[half] = lrow[half] * sc + ps;
            mrow[half] = mn;
            #pragma unroll
            for (int jd = 0; jd < 8; jd++) {
                accO[jd][r0]     *= sc;
                accO[jd][r0 + 1] *= sc;
            }
        }

        // ---- accO += P V: split P in registers, no smem round-trip ----
        #pragma unroll
        for (int j = 0; j < 4; j++) {
            uint32_t ph[4], pl[4];
            split2(s[2*j][0],   s[2*j][1],   ph[0], pl[0]);
            split2(s[2*j][2],   s[2*j][3],   ph[1], pl[1]);
            split2(s[2*j+1][0], s[2*j+1][1], ph[2], pl[2]);
            split2(s[2*j+1][2], s[2*j+1][3], ph[3], pl[3]);
            #pragma unroll
            for (int jd = 0; jd < 8; jd++) {
                uint32_t b0 = Vhs[(8*j+t)  *72 + jd*8 + g];
                uint32_t b1 = Vhs[(8*j+t+4)*72 + jd*8 + g];
                uint32_t c0 = Vls[(8*j+t)  *72 + jd*8 + g];
                uint32_t c1 = Vls[(8*j+t+4)*72 + jd*8 + g];
                mma16(accO[jd], ph[0], ph[1], ph[2], ph[3], b0, b1);
                mma16(accO[jd], ph[0], ph[1], ph[2], ph[3], c0, c1);
                mma16(accO[jd], pl[0], pl[1], pl[2], pl[3], b0, b1);
            }
        }
        __syncthreads();

        if (nb < 31) issueKV((nb + 1) * 64);
    }
    CPWAIT0();

    // ---- fused epilogue ----
    const float bm = bias_m[0];
    #pragma unroll
    for (int half = 0; half < 2; half++) {
        const int r0 = half * 2;
        int row = m0 + rw + g + half * 8;
        float piv = g_pi[bh * Ll + row] * 0.2f;
        float inv = 0.8f / lrow[half];
        #pragma unroll
        for (int jd = 0; jd < 8; jd++) {
            int c = jd * 8 + 2 * t;
            float2 sq = *(const float2*)&query[((size_t)b * Ll + row) * Dd + h * DK + c];
            float2 o;
            o.x = accO[jd][r0]     * inv + piv * sq.x + bm;
            o.y = accO[jd][r0 + 1] * inv + piv * sq.y + bm;
            *(float2*)&out[(bh * Ll + row) * DK + c] = o;
        }
    }
}

// ---------------------------------------------------------------------------
extern "C" void kernel_launch(void* const* d_in, const int* in_sizes, int n_in,
                              void* d_out, int out_size)
{
    const float* query  = (const float*)d_in[0];
    const float* key    = (const float*)d_in[1];
    const float* shortb = (const float*)d_in[2];
    const float* aspect = (const float*)d_in[3];
    const int*   mask   = (const int*)d_in[4];
    const float* Wq     = (const float*)d_in[5];
    const float* bq     = (const float*)d_in[6];
    const float* Wk     = (const float*)d_in[7];
    const float* bk     = (const float*)d_in[8];
    const float* w_mu   = (const float*)d_in[9];
    const float* b_mu   = (const float*)d_in[10];
    const float* bias_m = (const float*)d_in[11];
    float* out = (float*)d_out;

    cudaFuncSetAttribute(proj_mma_kernel, cudaFuncAttributeMaxDynamicSharedMemorySize, PROJ_SMEM);
    cudaFuncSetAttribute(attn_mma_kernel, cudaFuncAttributeMaxDynamicSharedMemorySize, ATTN_SMEM);

    prep_w_kernel<<<2304, 256>>>(Wq, Wk);
    prep_a_kernel<<<12288, 256>>>(query, key);
    prep_v_kernel<<<6144, 256>>>(query);
    proj_mma_kernel<<<dim3(32, 12, 2), 256, PROJ_SMEM>>>(bq, bk);
    sinkhorn_kernel<<<dim3(12, 2), 256>>>(query, aspect, mask, w_mu, b_mu);
    attn_mma_kernel<<<dim3(16, 12, 2), 256, ATTN_SMEM>>>(query, shortb, mask, bias_m, out);
}

// round 5
// speedup vs baseline: 2.4839x; 1.0947x over previous
#include <cuda_runtime.h>
#include <cuda_fp16.h>
#include <cstdint>

#define Bb 2
#define Hh 12
#define Ll 2048
#define Dd 768
#define DK 64
#define NEGV (-1000000000.0f)

// ---------------------------------------------------------------------------
// global scratch (pre-split half2 representations)
// ---------------------------------------------------------------------------
__device__ uint32_t g_qh[Bb*Hh*Ll*32], g_ql[Bb*Hh*Ll*32];     // [bh*L + l][k2]
__device__ uint32_t g_kh[Bb*Hh*Ll*32], g_kl[Bb*Hh*Ll*32];
__device__ uint32_t g_wh[2][Hh*64*384], g_wl[2][Hh*64*384];   // [qk][h*64+n][k2]
__device__ uint32_t g_ah[2][4096*384],  g_al[2][4096*384];    // [qk][row][k2]
__device__ uint32_t g_vth[Bb*Hh*64*1024], g_vtl[Bb*Hh*64*1024]; // [bh*64+d][n2]
__device__ float g_pi[Bb*Hh*Ll];

// ---------------------------------------------------------------------------
// helpers
// ---------------------------------------------------------------------------
__device__ __forceinline__ void split2(float x, float y, uint32_t& h, uint32_t& l) {
    __half2 hh = __floats2half2_rn(x, y);
    float rx = x - __low2float(hh);
    float ry = y - __high2float(hh);
    __half2 ll = __floats2half2_rn(rx, ry);
    h = *(uint32_t*)&hh;
    l = *(uint32_t*)&ll;
}

__device__ __forceinline__ void mma16(float d[4], uint32_t a0, uint32_t a1, uint32_t a2,
                                      uint32_t a3, uint32_t b0, uint32_t b1) {
    asm volatile(
        "mma.sync.aligned.m16n8k16.row.col.f32.f16.f16.f32 "
        "{%0,%1,%2,%3},{%4,%5,%6,%7},{%8,%9},{%0,%1,%2,%3};\n"
        : "+f"(d[0]), "+f"(d[1]), "+f"(d[2]), "+f"(d[3])
        : "r"(a0), "r"(a1), "r"(a2), "r"(a3), "r"(b0), "r"(b1));
}

__device__ __forceinline__ uint32_t s2u(const void* p) {
    return (uint32_t)__cvta_generic_to_shared(p);
}
#define LDSM4(r0,r1,r2,r3,addr) \
    asm volatile("ldmatrix.sync.aligned.m8n8.x4.shared.b16 {%0,%1,%2,%3}, [%4];" \
                 : "=r"(r0), "=r"(r1), "=r"(r2), "=r"(r3) : "r"(addr))
#define CP16(dst, src) asm volatile("cp.async.cg.shared.global [%0], [%1], 16;\n" :: "r"(dst), "l"(src))
#define CPCOMMIT() asm volatile("cp.async.commit_group;\n" ::: "memory")
#define CPWAIT1()  asm volatile("cp.async.wait_group 1;\n" ::: "memory")
#define CPWAIT0()  asm volatile("cp.async.wait_group 0;\n" ::: "memory")

// ---------------------------------------------------------------------------
// prep kernels
// ---------------------------------------------------------------------------
__global__ __launch_bounds__(256) void prep_w_kernel(
    const float* __restrict__ Wq, const float* __restrict__ Wk)
{
    int idx = blockIdx.x * 256 + threadIdx.x;
    int qk = idx >= (Hh*64*384);
    int r = idx - qk * (Hh*64*384);
    int col = r / 384;
    int k2 = r % 384;
    const float* W = qk ? Wk : Wq;
    float a = W[(size_t)(2*k2) * Dd + col];
    float b = W[(size_t)(2*k2 + 1) * Dd + col];
    uint32_t hh, ll;
    split2(a, b, hh, ll);
    g_wh[qk][r] = hh;
    g_wl[qk][r] = ll;
}

__global__ __launch_bounds__(256) void prep_a_kernel(
    const float* __restrict__ query, const float* __restrict__ key)
{
    int idx = blockIdx.x * 256 + threadIdx.x;
    int qk = idx >= (4096*384);
    int r = idx - qk * (4096*384);
    int row = r / 384;
    int k2  = r % 384;
    const float* src = qk ? key : query;
    float2 f = *(const float2*)&src[(size_t)row * Dd + 2*k2];
    uint32_t hh, ll;
    split2(f.x, f.y, hh, ll);
    g_ah[qk][r] = hh;
    g_al[qk][r] = ll;
}

// V transposed: g_vt[bh*64 + d][n2], u32 = (V[2n2][d], V[2n2+1][d]) as half2
__global__ __launch_bounds__(256) void prep_v_kernel(const float* __restrict__ query)
{
    __shared__ uint32_t th[64][33], tl[64][33];
    const int tile = blockIdx.x;   // n2-tile (32 per bh)
    const int bh = blockIdx.y;
    const int b = bh / Hh, h = bh % Hh;
    const int n20 = tile * 32;
    const int tid = threadIdx.x;
    #pragma unroll
    for (int i = 0; i < 8; i++) {
        int lin = tid + 256 * i;
        int n2l = lin >> 6;
        int d = lin & 63;
        const float* q0 = &query[(size_t)(b * Ll + 2*(n20 + n2l)) * Dd + h * DK + d];
        uint32_t hh, ll;
        split2(q0[0], q0[Dd], hh, ll);
        th[d][n2l] = hh;
        tl[d][n2l] = ll;
    }
    __syncthreads();
    #pragma unroll
    for (int i = 0; i < 8; i++) {
        int lin = tid + 256 * i;
        int d = lin >> 5;
        int n2l = lin & 31;
        size_t o = (size_t)(bh * 64 + d) * 1024 + n20 + n2l;
        g_vth[o] = th[d][n2l];
        g_vtl[o] = tl[d][n2l];
    }
}

// ---------------------------------------------------------------------------
// Projection GEMM, fp16 3x-split mma + LDSM fragments.
// ---------------------------------------------------------------------------
#define PROJ_SET 13824   // u32: Ah 4608 | Al 4608 | Wh 2304 | Wl 2304
#define PROJ_SMEM (2 * PROJ_SET * 4)

__global__ __launch_bounds__(256, 2) void proj_mma_kernel(
    const float* __restrict__ bq, const float* __restrict__ bk)
{
    extern __shared__ uint32_t psm[];
    const int qk = blockIdx.z;
    const int tid = threadIdx.x;
    const int w = tid >> 5, lane = tid & 31, g = lane >> 2, t = lane & 3;
    const int rw = w * 16;
    const int row0 = blockIdx.x * 128;
    const int h = blockIdx.y;

    const uint32_t* Agh = g_ah[qk];
    const uint32_t* Agl = g_al[qk];
    const uint32_t* Wgh = g_wh[qk];
    const uint32_t* Wgl = g_wl[qk];
    const float* bias = qk ? bk : bq;

    const int mA = tid >> 1, kbA = (tid & 1) * 16;
    const int nW = tid >> 2, kbW = (tid & 3) * 8;

    // ldmatrix per-lane offsets (u32 units)
    const int lm = lane >> 3, lr = lane & 7;
    const int loffA = ((lm & 1) * 8 + lr) * 36 + (lm >> 1) * 4;   // A fragments
    const int loffB = ((lm >> 1) * 8 + lr) * 36 + (lm & 1) * 4;   // W fragments

    auto issue = [&](int kb) {
        uint32_t* S  = psm + (kb & 1) * PROJ_SET;
        uint32_t* Ah = S;
        uint32_t* Al = S + 4608;
        uint32_t* Wh = S + 9216;
        uint32_t* Wl = S + 11520;
        const uint32_t* sa  = &Agh[(size_t)(row0 + mA) * 384 + kb*32 + kbA];
        const uint32_t* sal = &Agl[(size_t)(row0 + mA) * 384 + kb*32 + kbA];
        #pragma unroll
        for (int i = 0; i < 4; i++) {
            CP16(s2u(&Ah[mA*36 + kbA + i*4]), sa + i*4);
            CP16(s2u(&Al[mA*36 + kbA + i*4]), sal + i*4);
        }
        const uint32_t* sw  = &Wgh[(size_t)(h*64 + nW) * 384 + kb*32 + kbW];
        const uint32_t* swl = &Wgl[(size_t)(h*64 + nW) * 384 + kb*32 + kbW];
        CP16(s2u(&Wh[nW*36 + kbW]),     sw);
        CP16(s2u(&Wh[nW*36 + kbW + 4]), sw + 4);
        CP16(s2u(&Wl[nW*36 + kbW]),     swl);
        CP16(s2u(&Wl[nW*36 + kbW + 4]), swl + 4);
        CPCOMMIT();
    };

    issue(0);
    float acc[8][4] = {};

    #pragma unroll 1
    for (int kb = 0; kb < 12; kb++) {
        if (kb < 11) { issue(kb + 1); CPWAIT1(); } else { CPWAIT0(); }
        __syncthreads();
        uint32_t sbase = s2u(psm) + ((kb & 1) * PROJ_SET) * 4;
        uint32_t aaddr  = sbase + (rw*36 + loffA) * 4;
        uint32_t aaddrl = aaddr + 4608 * 4;
        uint32_t whaddr = sbase + (9216 + loffB) * 4;
        uint32_t wladdr = sbase + (11520 + loffB) * 4;
        #pragma unroll
        for (int j = 0; j < 4; j++) {
            uint32_t ah0, ah1, ah2, ah3, al0, al1, al2, al3;
            LDSM4(ah0, ah1, ah2, ah3, aaddr  + j*32);
            LDSM4(al0, al1, al2, al3, aaddrl + j*32);
            #pragma unroll
            for (int p = 0; p < 4; p++) {
                uint32_t wh0, wh1, wh2, wh3, wl0, wl1, wl2, wl3;
                LDSM4(wh0, wh1, wh2, wh3, whaddr + (p*576 + j*8)*4);
                LDSM4(wl0, wl1, wl2, wl3, wladdr + (p*576 + j*8)*4);
                mma16(acc[2*p],   ah0, ah1, ah2, ah3, wh0, wh1);
                mma16(acc[2*p],   ah0, ah1, ah2, ah3, wl0, wl1);
                mma16(acc[2*p],   al0, al1, al2, al3, wh0, wh1);
                mma16(acc[2*p+1], ah0, ah1, ah2, ah3, wh2, wh3);
                mma16(acc[2*p+1], ah0, ah1, ah2, ah3, wl2, wl3);
                mma16(acc[2*p+1], al0, al1, al2, al3, wh2, wh3);
            }
        }
        __syncthreads();
    }

    uint32_t* oh = qk ? g_kh : g_qh;
    uint32_t* ol = qk ? g_kl : g_ql;
    const int col0 = h * 64;
    #pragma unroll
    for (int jn = 0; jn < 8; jn++) {
        float2 bb = *(const float2*)&bias[col0 + jn*8 + 2*t];
        int row = row0 + rw + g;
        int b_ = row >> 11, l = row & (Ll - 1);
        size_t base = ((size_t)(b_ * Hh + h) * Ll + l) * 32 + jn*4 + t;
        uint32_t hh, llv;
        split2(acc[jn][0] + bb.x, acc[jn][1] + bb.y, hh, llv);
        oh[base] = hh; ol[base] = llv;
        int row2 = row + 8;
        int b2 = row2 >> 11, l2 = row2 & (Ll - 1);
        size_t base2 = ((size_t)(b2 * Hh + h) * Ll + l2) * 32 + jn*4 + t;
        split2(acc[jn][2] + bb.x, acc[jn][3] + bb.y, hh, llv);
        oh[base2] = hh; ol[base2] = llv;
    }
}

// ---------------------------------------------------------------------------
// Block reductions
// ---------------------------------------------------------------------------
__device__ __forceinline__ float warpSum(float v) {
    #pragma unroll
    for (int o = 16; o; o >>= 1) v += __shfl_xor_sync(0xffffffffu, v, o);
    return v;
}
__device__ __forceinline__ float warpMax(float v) {
    #pragma unroll
    for (int o = 16; o; o >>= 1) v = fmaxf(v, __shfl_xor_sync(0xffffffffu, v, o));
    return v;
}
__device__ float blockSum(float v, float* red) {
    int w = threadIdx.x >> 5, lane = threadIdx.x & 31;
    v = warpSum(v);
    if (lane == 0) red[w] = v;
    __syncthreads();
    if (w == 0) {
        float r = (lane < 8) ? red[lane] : 0.0f;
        r = warpSum(r);
        if (lane == 0) red[0] = r;
    }
    __syncthreads();
    float r = red[0];
    __syncthreads();
    return r;
}
__device__ float blockMax(float v, float* red) {
    int w = threadIdx.x >> 5, lane = threadIdx.x & 31;
    v = warpMax(v);
    if (lane == 0) red[w] = v;
    __syncthreads();
    if (w == 0) {
        float r = (lane < 8) ? red[lane] : -1e30f;
        r = warpMax(r);
        if (lane == 0) red[0] = r;
    }
    __syncthreads();
    float r = red[0];
    __syncthreads();
    return r;
}

// ---------------------------------------------------------------------------
// Sinkhorn OT (unchanged)
// ---------------------------------------------------------------------------
__global__ __launch_bounds__(256) void sinkhorn_kernel(
    const float* __restrict__ query, const float* __restrict__ aspect,
    const int* __restrict__ mask, const float* __restrict__ w_mu,
    const float* __restrict__ b_mu)
{
    const int h = blockIdx.x, b = blockIdx.y;
    const int tid = threadIdx.x;
    __shared__ float aspn[64];
    __shared__ float wmu[64];
    __shared__ float red[8];

    if (tid < 64) {
        aspn[tid] = aspect[b * Dd + h * DK + tid];
        wmu[tid]  = w_mu[tid];
    }
    __syncthreads();

    float ssa = 0.0f;
    #pragma unroll
    for (int d = 0; d < 64; d++) ssa += aspn[d] * aspn[d];
    const float inv_na = 1.0f / fmaxf(sqrtf(ssa), 1e-12f);
    const float bmu = b_mu[0];

    float Kl[8], mu[8], u[8];
    float lmax = -1e30f;
    #pragma unroll
    for (int j = 0; j < 8; j++) {
        int l = tid + j * 256;
        const float* sp = &query[((size_t)b * Ll + l) * Dd + h * DK];
        float sq = 0.0f, da = 0.0f, dm = 0.0f;
        #pragma unroll
        for (int d = 0; d < 64; d += 4) {
            float4 s4 = *(const float4*)&sp[d];
            sq += s4.x * s4.x + s4.y * s4.y + s4.z * s4.z + s4.w * s4.w;
            da += s4.x * aspn[d] + s4.y * aspn[d + 1] + s4.z * aspn[d + 2] + s4.w * aspn[d + 3];
            dm += s4.x * wmu[d]  + s4.y * wmu[d + 1]  + s4.z * wmu[d + 2]  + s4.w * wmu[d + 3];
        }
        float inv_ns = 1.0f / fmaxf(sqrtf(sq), 1e-12f);
        float cosv = da * inv_ns * inv_na;
        Kl[j] = __expf(cosv - 1.0f);
        float lg = dm + bmu;
        if (mask[b * Ll + l] == 0) lg = NEGV;
        mu[j] = lg;
        lmax = fmaxf(lmax, lg);
    }
    lmax = blockMax(lmax, red);
    float lsum = 0.0f;
    #pragma unroll
    for (int j = 0; j < 8; j++) { mu[j] = __expf(mu[j] - lmax); lsum += mu[j]; }
    lsum = blockSum(lsum, red);
    float inv = 1.0f / lsum;
    #pragma unroll
    for (int j = 0; j < 8; j++) mu[j] *= inv;

    float v = 1.0f;
    for (int it = 0; it < 50; it++) {
        float part = 0.0f;
        #pragma unroll
        for (int j = 0; j < 8; j++) {
            u[j] = mu[j] / (Kl[j] * v + 1e-8f);
            part += Kl[j] * u[j];
        }
        float S = blockSum(part, red);
        v = 1.0f / (S + 1e-8f);
    }
    #pragma unroll
    for (int j = 0; j < 8; j++)
        g_pi[((size_t)b * Hh + h) * Ll + tid + j * 256] = u[j] * Kl[j] * v;
}

// ---------------------------------------------------------------------------
// Attention: fp16 3x-split mma, LDSM fragments, double-buffered KV cp.async,
// short cp.async waited after QK. 2 barriers/chunk.
// ---------------------------------------------------------------------------
#define LS 68
#define KVSET 9216   // u32: Kh 2304 | Kl 2304 | Vh 2304 | Vl 2304
#define ATTN_SMEM (128*LS*4 + 2*KVSET*4 + 2*64*4)

__global__ __launch_bounds__(256, 2) void attn_mma_kernel(
    const float* __restrict__ query, const float* __restrict__ shortb,
    const int* __restrict__ mask, const float* __restrict__ bias_m,
    float* __restrict__ out)
{
    extern __shared__ float smb[];
    float* SBuf = smb;                          // [128][68] short tile
    uint32_t* KVr = (uint32_t*)(SBuf + 128 * LS);  // 2 stages x KVSET
    int* Msk = (int*)(KVr + 2 * KVSET);         // [2][64]

    const int tid = threadIdx.x;
    const int w = tid >> 5, lane = tid & 31;
    const int g = lane >> 2, t = lane & 3;
    const int rw = w * 16;
    const int m0 = blockIdx.x * 128;
    const int h = blockIdx.y, b = blockIdx.z;
    const size_t bh = (size_t)b * Hh + h;
    const float* sp = shortb + (bh * Ll + m0) * Ll;

    const int lm = lane >> 3, lr = lane & 7;
    const int loffB = ((lm >> 1) * 8 + lr) * 36 + (lm & 1) * 4;

    // staging coords: per plane 512 CP16 / 256 threads = 2 each
    const int kRow0 = tid >> 3, kSeg0 = (tid & 7) * 4;         // first of 2: rows 0..31
    // second: rows 32..63 (lin = tid + 256)

    auto issueKV = [&](int n0, int stage) {
        uint32_t* S = KVr + stage * KVSET;
        #pragma unroll
        for (int i = 0; i < 2; i++) {
            int row = kRow0 + i * 32;
            const uint32_t* skh = &g_kh[(bh * Ll + n0 + row) * 32 + kSeg0];
            const uint32_t* skl = &g_kl[(bh * Ll + n0 + row) * 32 + kSeg0];
            CP16(s2u(&S[row*36 + kSeg0]),        skh);
            CP16(s2u(&S[2304 + row*36 + kSeg0]), skl);
            const uint32_t* svh = &g_vth[(bh * 64 + row) * 1024 + (n0 >> 1) + kSeg0];
            const uint32_t* svl = &g_vtl[(bh * 64 + row) * 1024 + (n0 >> 1) + kSeg0];
            CP16(s2u(&S[4608 + row*36 + kSeg0]), svh);
            CP16(s2u(&S[6912 + row*36 + kSeg0]), svl);
        }
        if (tid < 16) CP16(s2u(&Msk[stage*64 + tid*4]), &mask[b * Ll + n0 + tid*4]);
        CPCOMMIT();
    };

    issueKV(0, 0);

    // ---- Q fragments from pre-split globals ----
    uint32_t qh[16], ql[16];
    {
        const uint32_t* qhp  = &g_qh[(bh * Ll + m0 + rw + g) * 32];
        const uint32_t* qhp8 = qhp + 8 * 32;
        const uint32_t* qlp  = &g_ql[(bh * Ll + m0 + rw + g) * 32];
        const uint32_t* qlp8 = qlp + 8 * 32;
        #pragma unroll
        for (int j = 0; j < 4; j++) {
            qh[j*4 + 0] = qhp [8*j + t];
            qh[j*4 + 1] = qhp8[8*j + t];
            qh[j*4 + 2] = qhp [8*j + t + 4];
            qh[j*4 + 3] = qlp [8*j + t + 4];  // placeholder, fixed below
        }
        // correct assignment (avoid aliasing mistakes): redo cleanly
        #pragma unroll
        for (int j = 0; j < 4; j++) {
            qh[j*4 + 0] = qhp [8*j + t];
            qh[j*4 + 1] = qhp8[8*j + t];
            qh[j*4 + 2] = qhp [8*j + t + 4];
            qh[j*4 + 3] = qhp8[8*j + t + 4];
            ql[j*4 + 0] = qlp [8*j + t];
            ql[j*4 + 1] = qlp8[8*j + t];
            ql[j*4 + 2] = qlp [8*j + t + 4];
            ql[j*4 + 3] = qlp8[8*j + t + 4];
        }
    }

    const float* SBw = SBuf + rw * LS;
    float accO[8][4] = {};
    float mrow[2] = {-1e30f, -1e30f};
    float lrow[2] = {0.0f, 0.0f};

    #pragma unroll 1
    for (int nb = 0; nb < 32; nb++) {
        const int n0 = nb * 64;
        CPWAIT0();              // KV[nb] (and everything older) complete
        __syncthreads();        // visible to all; SBuf + alt KV stage free

        // issue short[nb] (group 1) then KV[nb+1] (group 2)
        #pragma unroll
        for (int it = 0; it < 8; it++) {
            int lin = tid + it * 256, row = lin >> 4, c4 = (lin & 15) * 4;
            CP16(s2u(&SBuf[row * LS + c4]), &sp[(size_t)row * Ll + n0 + c4]);
        }
        CPCOMMIT();
        issueKV((nb < 31 ? nb + 1 : 31) * 64, (nb + 1) & 1);

        uint32_t kbase = s2u(KVr) + ((nb & 1) * KVSET + loffB) * 4;
        uint32_t klbase = kbase + 2304 * 4;
        uint32_t vbase_ = kbase + 4608 * 4;
        uint32_t vlbase = kbase + 6912 * 4;

        // ---- S = Q K^T ----
        float s[8][4] = {};
        #pragma unroll
        for (int j = 0; j < 4; j++) {
            #pragma unroll
            for (int p = 0; p < 4; p++) {
                uint32_t kh0, kh1, kh2, kh3, kl0, kl1, kl2, kl3;
                LDSM4(kh0, kh1, kh2, kh3, kbase  + (p*576 + j*8)*4);
                LDSM4(kl0, kl1, kl2, kl3, klbase + (p*576 + j*8)*4);
                mma16(s[2*p],   qh[j*4], qh[j*4+1], qh[j*4+2], qh[j*4+3], kh0, kh1);
                mma16(s[2*p],   qh[j*4], qh[j*4+1], qh[j*4+2], qh[j*4+3], kl0, kl1);
                mma16(s[2*p],   ql[j*4], ql[j*4+1], ql[j*4+2], ql[j*4+3], kh0, kh1);
                mma16(s[2*p+1], qh[j*4], qh[j*4+1], qh[j*4+2], qh[j*4+3], kh2, kh3);
                mma16(s[2*p+1], qh[j*4], qh[j*4+1], qh[j*4+2], qh[j*4+3], kl2, kl3);
                mma16(s[2*p+1], ql[j*4], ql[j*4+1], ql[j*4+2], ql[j*4+3], kh2, kh3);
            }
        }

        CPWAIT1();              // short[nb] done (KV[nb+1] still in flight)
        __syncthreads();        // short visible

        // ---- scale, mask, +short ----
        const int* Mc = Msk + (nb & 1) * 64;
        #pragma unroll
        for (int jn = 0; jn < 8; jn++) {
            int c0 = jn * 8 + 2 * t;
            int2 mk = *(const int2*)&Mc[c0];
            float2 sh0 = *(const float2*)&SBw[(g)     * LS + c0];
            float2 sh1 = *(const float2*)&SBw[(g + 8) * LS + c0];
            s[jn][0] = (mk.x ? s[jn][0] * 0.125f : NEGV) + sh0.x;
            s[jn][1] = (mk.y ? s[jn][1] * 0.125f : NEGV) + sh0.y;
            s[jn][2] = (mk.x ? s[jn][2] * 0.125f : NEGV) + sh1.x;
            s[jn][3] = (mk.y ? s[jn][3] * 0.125f : NEGV) + sh1.y;
        }

        // ---- online softmax (rows g and g+8) ----
        #pragma unroll
        for (int half = 0; half < 2; half++) {
            const int r0 = half * 2;
            float tm = -1e30f;
            #pragma unroll
            for (int jn = 0; jn < 8; jn++)
                tm = fmaxf(tm, fmaxf(s[jn][r0], s[jn][r0 + 1]));
            tm = fmaxf(tm, __shfl_xor_sync(0xffffffffu, tm, 1));
            tm = fmaxf(tm, __shfl_xor_sync(0xffffffffu, tm, 2));
            float mn = fmaxf(mrow[half], tm);
            float sc = __expf(mrow[half] - mn);
            float ps = 0.0f;
            #pragma unroll
            for (int jn = 0; jn < 8; jn++) {
                s[jn][r0]     = __expf(s[jn][r0]     - mn);
                s[jn][r0 + 1] = __expf(s[jn][r0 + 1] - mn);
                ps += s[jn][r0] + s[jn][r0 + 1];
            }
            ps += __shfl_xor_sync(0xffffffffu, ps, 1);
            ps += __shfl_xor_sync(0xffffffffu, ps, 2);
            lrow[half] = lrow[half] * sc + ps;
            mrow[half] = mn;
            #pragma unroll
            for (int jd = 0; jd < 8; jd++) {
                accO[jd][r0]     *= sc;
                accO[jd][r0 + 1] *= sc;
            }
        }

        // ---- accO += P V (split P in registers) ----
        #pragma unroll
        for (int j = 0; j < 4; j++) {
            uint32_t ph0, ph1, ph2, ph3, pl0, pl1, pl2, pl3;
            split2(s[2*j][0],   s[2*j][1],   ph0, pl0);
            split2(s[2*j][2],   s[2*j][3],   ph1, pl1);
            split2(s[2*j+1][0], s[2*j+1][1], ph2, pl2);
            split2(s[2*j+1][2], s[2*j+1][3], ph3, pl3);
            #pragma unroll
            for (int p = 0; p < 4; p++) {
                uint32_t vh0, vh1, vh2, vh3, vl0, vl1, vl2, vl3;
                LDSM4(vh0, vh1, vh2, vh3, vbase_ + (p*576 + j*8)*4);
                LDSM4(vl0, vl1, vl2, vl3, vlbase + (p*576 + j*8)*4);
                mma16(accO[2*p],   ph0, ph1, ph2, ph3, vh0, vh1);
                mma16(accO[2*p],   ph0, ph1, ph2, ph3, vl0, vl1);
                mma16(accO[2*p],   pl0, pl1, pl2, pl3, vh0, vh1);
                mma16(accO[2*p+1], ph0, ph1, ph2, ph3, vh2, vh3);
                mma16(accO[2*p+1], ph0, ph1, ph2, ph3, vl2, vl3);
                mma16(accO[2*p+1], pl0, pl1, pl2, pl3, vh2, vh3);
            }
        }
    }
    CPWAIT0();

    // ---- fused epilogue ----
    const float bm = bias_m[0];
    #pragma unroll
    for (int half = 0; half < 2; half++) {
        const int r0 = half * 2;
        int row = m0 + rw + g + half * 8;
        float piv = g_pi[bh * Ll + row] * 0.2f;
        float inv = 0.8f / lrow[half];
        #pragma unroll
        for (int jd = 0; jd < 8; jd++) {
            int c = jd * 8 + 2 * t;
            float2 sq = *(const float2*)&query[((size_t)b * Ll + row) * Dd + h * DK + c];
            float2 o;
            o.x = accO[jd][r0]     * inv + piv * sq.x + bm;
            o.y = accO[jd][r0 + 1] * inv + piv * sq.y + bm;
            *(float2*)&out[(bh * Ll + row) * DK + c] = o;
        }
    }
}

// ---------------------------------------------------------------------------
extern "C" void kernel_launch(void* const* d_in, const int* in_sizes, int n_in,
                              void* d_out, int out_size)
{
    const float* query  = (const float*)d_in[0];
    const float* key    = (const float*)d_in[1];
    const float* shortb = (const float*)d_in[2];
    const float* aspect = (const float*)d_in[3];
    const int*   mask   = (const int*)d_in[4];
    const float* Wq     = (const float*)d_in[5];
    const float* bq     = (const float*)d_in[6];
    const float* Wk     = (const float*)d_in[7];
    const float* bk     = (const float*)d_in[8];
    const float* w_mu   = (const float*)d_in[9];
    const float* b_mu   = (const float*)d_in[10];
    const float* bias_m = (const float*)d_in[11];
    float* out = (float*)d_out;

    cudaFuncSetAttribute(proj_mma_kernel, cudaFuncAttributeMaxDynamicSharedMemorySize, PROJ_SMEM);
    cudaFuncSetAttribute(attn_mma_kernel, cudaFuncAttributeMaxDynamicSharedMemorySize, ATTN_SMEM);

    prep_w_kernel<<<2304, 256>>>(Wq, Wk);
    prep_a_kernel<<<12288, 256>>>(query, key);
    prep_v_kernel<<<dim3(32, 24), 256>>>(query);
    proj_mma_kernel<<<dim3(32, 12, 2), 256, PROJ_SMEM>>>(bq, bk);
    sinkhorn_kernel<<<dim3(12, 2), 256>>>(query, aspect, mask, w_mu, b_mu);
    attn_mma_kernel<<<dim3(16, 12, 2), 256, ATTN_SMEM>>>(query, shortb, mask, bias_m, out);
}

// round 7
// speedup vs baseline: 3.0568x; 1.2307x over previous
#include <cuda_runtime.h>
#include <cuda_fp16.h>
#include <cstdint>

#define Bb 2
#define Hh 12
#define Ll 2048
#define Dd 768
#define DK 64
#define NEGV (-1000000000.0f)

// ---------------------------------------------------------------------------
// global scratch (pre-split half2 representations; 2-split: B-side hi only)
// ---------------------------------------------------------------------------
__device__ uint32_t g_qh[Bb*Hh*Ll*32], g_ql[Bb*Hh*Ll*32];   // proj q out [bh*L+l][k2]
__device__ uint32_t g_kh[Bb*Hh*Ll*32];                      // proj k out (hi only)
__device__ uint32_t g_wh[2][Hh*64*384];                     // [qk][h*64+n][k2] hi only
__device__ uint32_t g_ah[2][4096*384], g_al[2][4096*384];   // [qk][row][k2]
__device__ uint32_t g_vth[Bb*Hh*64*1024];                   // [bh*64+d][n2] hi only
__device__ float g_pi[Bb*Hh*Ll];

// ---------------------------------------------------------------------------
// helpers
// ---------------------------------------------------------------------------
__device__ __forceinline__ void split2(float x, float y, uint32_t& h, uint32_t& l) {
    __half2 hh = __floats2half2_rn(x, y);
    float rx = x - __low2float(hh);
    float ry = y - __high2float(hh);
    __half2 ll = __floats2half2_rn(rx, ry);
    h = *(uint32_t*)&hh;
    l = *(uint32_t*)&ll;
}
__device__ __forceinline__ uint32_t pack2(float x, float y) {
    __half2 hh = __floats2half2_rn(x, y);
    return *(uint32_t*)&hh;
}

__device__ __forceinline__ void mma16(float d[4], uint32_t a0, uint32_t a1, uint32_t a2,
                                      uint32_t a3, uint32_t b0, uint32_t b1) {
    asm volatile(
        "mma.sync.aligned.m16n8k16.row.col.f32.f16.f16.f32 "
        "{%0,%1,%2,%3},{%4,%5,%6,%7},{%8,%9},{%0,%1,%2,%3};\n"
        : "+f"(d[0]), "+f"(d[1]), "+f"(d[2]), "+f"(d[3])
        : "r"(a0), "r"(a1), "r"(a2), "r"(a3), "r"(b0), "r"(b1));
}

__device__ __forceinline__ uint32_t s2u(const void* p) {
    return (uint32_t)__cvta_generic_to_shared(p);
}
#define LDSM4(r0,r1,r2,r3,addr) \
    asm volatile("ldmatrix.sync.aligned.m8n8.x4.shared.b16 {%0,%1,%2,%3}, [%4];" \
                 : "=r"(r0), "=r"(r1), "=r"(r2), "=r"(r3) : "r"(addr))
#define CP16(dst, src) asm volatile("cp.async.cg.shared.global [%0], [%1], 16;\n" :: "r"(dst), "l"(src))
#define CPCOMMIT() asm volatile("cp.async.commit_group;\n" ::: "memory")
#define CPWAIT2()  asm volatile("cp.async.wait_group 2;\n" ::: "memory")
#define CPWAIT1()  asm volatile("cp.async.wait_group 1;\n" ::: "memory")
#define CPWAIT0()  asm volatile("cp.async.wait_group 0;\n" ::: "memory")

// ---------------------------------------------------------------------------
// prep kernels
// ---------------------------------------------------------------------------
__global__ __launch_bounds__(256) void prep_w_kernel(
    const float* __restrict__ Wq, const float* __restrict__ Wk)
{
    int idx = blockIdx.x * 256 + threadIdx.x;
    int qk = idx >= (Hh*64*384);
    int r = idx - qk * (Hh*64*384);
    int col = r / 384;
    int k2 = r % 384;
    const float* W = qk ? Wk : Wq;
    g_wh[qk][r] = pack2(W[(size_t)(2*k2) * Dd + col], W[(size_t)(2*k2+1) * Dd + col]);
}

__global__ __launch_bounds__(256) void prep_a_kernel(
    const float* __restrict__ query, const float* __restrict__ key)
{
    int idx = blockIdx.x * 256 + threadIdx.x;
    int qk = idx >= (4096*384);
    int r = idx - qk * (4096*384);
    int row = r / 384;
    int k2  = r % 384;
    const float* src = qk ? key : query;
    float2 f = *(const float2*)&src[(size_t)row * Dd + 2*k2];
    uint32_t hh, ll;
    split2(f.x, f.y, hh, ll);
    g_ah[qk][r] = hh;
    g_al[qk][r] = ll;
}

// V transposed: g_vth[bh*64 + d][n2] = half2(V[2n2][d], V[2n2+1][d])
__global__ __launch_bounds__(256) void prep_v_kernel(const float* __restrict__ query)
{
    __shared__ uint32_t th[64][33];
    const int tile = blockIdx.x;
    const int bh = blockIdx.y;
    const int b = bh / Hh, h = bh % Hh;
    const int n20 = tile * 32;
    const int tid = threadIdx.x;
    #pragma unroll
    for (int i = 0; i < 8; i++) {
        int lin = tid + 256 * i;
        int n2l = lin >> 6;
        int d = lin & 63;
        const float* q0 = &query[(size_t)(b * Ll + 2*(n20 + n2l)) * Dd + h * DK + d];
        th[d][n2l] = pack2(q0[0], q0[Dd]);
    }
    __syncthreads();
    #pragma unroll
    for (int i = 0; i < 8; i++) {
        int lin = tid + 256 * i;
        int d = lin >> 5;
        int n2l = lin & 31;
        g_vth[(size_t)(bh * 64 + d) * 1024 + n20 + n2l] = th[d][n2l];
    }
}

// ---------------------------------------------------------------------------
// Projection GEMM: 64 rows x 64 cols (one head) per block, 128 threads,
// fp16 2-split (A hi+lo, W hi), k-tile 64, double-buffered cp.async.
// ---------------------------------------------------------------------------
#define PROJ_SET 6912   // u32: Ah 2304 | Al 2304 | Wh 2304
#define PROJ_SMEM (2 * PROJ_SET * 4)

__global__ __launch_bounds__(128, 4) void proj_mma_kernel(
    const float* __restrict__ bq, const float* __restrict__ bk)
{
    extern __shared__ uint32_t psm[];
    const int qk = blockIdx.z;
    const int tid = threadIdx.x;
    const int w = tid >> 5, lane = tid & 31, g = lane >> 2, t = lane & 3;
    const int rw = w * 16;
    const int row0 = blockIdx.x * 64;
    const int h = blockIdx.y;

    const uint32_t* Agh = g_ah[qk];
    const uint32_t* Agl = g_al[qk];
    const uint32_t* Wgh = g_wh[qk];
    const float* bias = qk ? bk : bq;

    const int mA = tid >> 1, kbA = (tid & 1) * 16;

    const int lm = lane >> 3, lr = lane & 7;
    const int loffA = ((lm & 1) * 8 + lr) * 36 + (lm >> 1) * 4;
    const int loffB = ((lm >> 1) * 8 + lr) * 36 + (lm & 1) * 4;

    auto issue = [&](int kb) {
        uint32_t* S  = psm + (kb & 1) * PROJ_SET;
        const uint32_t* sa  = &Agh[(size_t)(row0 + mA) * 384 + kb*32 + kbA];
        const uint32_t* sal = &Agl[(size_t)(row0 + mA) * 384 + kb*32 + kbA];
        const uint32_t* sw  = &Wgh[(size_t)(h*64 + mA) * 384 + kb*32 + kbA];
        #pragma unroll
        for (int i = 0; i < 4; i++) {
            CP16(s2u(&S[mA*36 + kbA + i*4]),        sa  + i*4);
            CP16(s2u(&S[2304 + mA*36 + kbA + i*4]), sal + i*4);
            CP16(s2u(&S[4608 + mA*36 + kbA + i*4]), sw  + i*4);
        }
        CPCOMMIT();
    };

    issue(0);
    float acc[8][4] = {};

    #pragma unroll 1
    for (int kb = 0; kb < 12; kb++) {
        if (kb < 11) { issue(kb + 1); CPWAIT1(); } else { CPWAIT0(); }
        __syncthreads();
        uint32_t sbase = s2u(psm) + ((kb & 1) * PROJ_SET) * 4;
        uint32_t aaddr  = sbase + (rw*36 + loffA) * 4;
        uint32_t aaddrl = aaddr + 2304 * 4;
        uint32_t whaddr = sbase + (4608 + loffB) * 4;
        #pragma unroll
        for (int j = 0; j < 4; j++) {
            uint32_t ah0, ah1, ah2, ah3, al0, al1, al2, al3;
            LDSM4(ah0, ah1, ah2, ah3, aaddr  + j*32);
            LDSM4(al0, al1, al2, al3, aaddrl + j*32);
            #pragma unroll
            for (int p = 0; p < 4; p++) {
                uint32_t wh0, wh1, wh2, wh3;
                LDSM4(wh0, wh1, wh2, wh3, whaddr + (p*576 + j*8)*4);
                mma16(acc[2*p],   ah0, ah1, ah2, ah3, wh0, wh1);
                mma16(acc[2*p],   al0, al1, al2, al3, wh0, wh1);
                mma16(acc[2*p+1], ah0, ah1, ah2, ah3, wh2, wh3);
                mma16(acc[2*p+1], al0, al1, al2, al3, wh2, wh3);
            }
        }
        __syncthreads();
    }

    const int col0 = h * 64;
    #pragma unroll
    for (int jn = 0; jn < 8; jn++) {
        float2 bb = *(const float2*)&bias[col0 + jn*8 + 2*t];
        #pragma unroll
        for (int half = 0; half < 2; half++) {
            int row = row0 + rw + g + half * 8;
            int b_ = row >> 11, l = row & (Ll - 1);
            size_t base = ((size_t)(b_ * Hh + h) * Ll + l) * 32 + jn*4 + t;
            float vx = acc[jn][2*half]     + bb.x;
            float vy = acc[jn][2*half + 1] + bb.y;
            if (qk == 0) {
                uint32_t hh, llv;
                split2(vx, vy, hh, llv);
                g_qh[base] = hh; g_ql[base] = llv;
            } else {
                g_kh[base] = pack2(vx, vy);
            }
        }
    }
}

// ---------------------------------------------------------------------------
// mu (= pi) kernel: pi = softmax over L of (seq_h @ w_mu + b_mu), masked.
// (Sinkhorn with nu==1 and sum(mu)==1 fixes v≈1 ⇒ pi = mu to ~1e-7.)
// ---------------------------------------------------------------------------
__global__ __launch_bounds__(256) void mu_kernel(
    const float* __restrict__ query, const int* __restrict__ mask,
    const float* __restrict__ w_mu, const float* __restrict__ b_mu)
{
    const int h = blockIdx.x, b = blockIdx.y;
    const int tid = threadIdx.x;
    __shared__ float wmu[64];
    __shared__ float red[8];
    if (tid < 64) wmu[tid] = w_mu[tid];
    __syncthreads();
    const float bmu = b_mu[0];

    float lg[8];
    float lmax = -1e30f;
    #pragma unroll
    for (int j = 0; j < 8; j++) {
        int l = tid + j * 256;
        const float* sp = &query[((size_t)b * Ll + l) * Dd + h * DK];
        float dm = 0.0f;
        #pragma unroll
        for (int d = 0; d < 64; d += 4) {
            float4 s4 = *(const float4*)&sp[d];
            dm += s4.x * wmu[d] + s4.y * wmu[d+1] + s4.z * wmu[d+2] + s4.w * wmu[d+3];
        }
        float v = dm + bmu;
        if (mask[b * Ll + l] == 0) v = NEGV;
        lg[j] = v;
        lmax = fmaxf(lmax, v);
    }
    {
        int wi = tid >> 5, lane = tid & 31;
        #pragma unroll
        for (int o = 16; o; o >>= 1) lmax = fmaxf(lmax, __shfl_xor_sync(~0u, lmax, o));
        if (lane == 0) red[wi] = lmax;
        __syncthreads();
        if (wi == 0) {
            float r = (lane < 8) ? red[lane] : -1e30f;
            #pragma unroll
            for (int o = 16; o; o >>= 1) r = fmaxf(r, __shfl_xor_sync(~0u, r, o));
            if (lane == 0) red[0] = r;
        }
        __syncthreads();
        lmax = red[0];
        __syncthreads();
    }
    float lsum = 0.0f;
    #pragma unroll
    for (int j = 0; j < 8; j++) { lg[j] = __expf(lg[j] - lmax); lsum += lg[j]; }
    {
        int wi = tid >> 5, lane = tid & 31;
        #pragma unroll
        for (int o = 16; o; o >>= 1) lsum += __shfl_xor_sync(~0u, lsum, o);
        if (lane == 0) red[wi] = lsum;
        __syncthreads();
        if (wi == 0) {
            float r = (lane < 8) ? red[lane] : 0.0f;
            #pragma unroll
            for (int o = 16; o; o >>= 1) r += __shfl_xor_sync(~0u, r, o);
            if (lane == 0) red[0] = r;
        }
        __syncthreads();
        lsum = red[0];
    }
    float inv = 1.0f / lsum;
    #pragma unroll
    for (int j = 0; j < 8; j++)
        g_pi[((size_t)b * Hh + h) * Ll + tid + j * 256] = lg[j] * inv;
}

// ---------------------------------------------------------------------------
// Attention: 64-row tiles, 128 threads (4 warps x 16 rows), fp16 2-split,
// single-buffered K/short/V with 3-group staggered cp.async rotation.
// ---------------------------------------------------------------------------
#define LS 68
#define ATTN_SMEM (64*LS*4 + 2304*4 + 2304*4 + 64*4)

__global__ __launch_bounds__(128, 4) void attn_mma_kernel(
    const float* __restrict__ query, const float* __restrict__ shortb,
    const int* __restrict__ mask, const float* __restrict__ bias_m,
    float* __restrict__ out)
{
    extern __shared__ float smb[];
    float* SBuf = smb;                          // [64][68] short tile
    uint32_t* Ks = (uint32_t*)(SBuf + 64 * LS); // [64][36]
    uint32_t* Vs = Ks + 2304;                   // [64][36]
    int* Msk = (int*)(Vs + 2304);               // [64]

    const int tid = threadIdx.x;
    const int w = tid >> 5, lane = tid & 31;
    const int g = lane >> 2, t = lane & 3;
    const int rw = w * 16;
    const int m0 = blockIdx.x * 64;
    const int h = blockIdx.y, b = blockIdx.z;
    const size_t bh = (size_t)b * Hh + h;
    const float* sp = shortb + (bh * Ll + m0) * Ll;

    const int lm = lane >> 3, lr = lane & 7;
    const int loffB = ((lm >> 1) * 8 + lr) * 36 + (lm & 1) * 4;

    const int rS = tid >> 1, sS = (tid & 1) * 16;   // K/V staging: row, seg

    auto issueK = [&](int n0) {
        const uint32_t* skh = &g_kh[(bh * Ll + n0 + rS) * 32 + sS];
        #pragma unroll
        for (int i = 0; i < 4; i++)
            CP16(s2u(&Ks[rS*36 + sS + i*4]), skh + i*4);
        CPCOMMIT();
    };
    auto issueShort = [&](int n0) {
        #pragma unroll
        for (int it = 0; it < 8; it++) {
            int lin = tid + it * 128, row = lin >> 4, c4 = (lin & 15) * 4;
            CP16(s2u(&SBuf[row * LS + c4]), &sp[(size_t)row * Ll + n0 + c4]);
        }
        if (tid < 16) CP16(s2u(&Msk[tid * 4]), &mask[b * Ll + n0 + tid * 4]);
        CPCOMMIT();
    };
    auto issueV = [&](int n0) {
        const uint32_t* svh = &g_vth[(bh * 64 + rS) * 1024 + (n0 >> 1) + sS];
        #pragma unroll
        for (int i = 0; i < 4; i++)
            CP16(s2u(&Vs[rS*36 + sS + i*4]), svh + i*4);
        CPCOMMIT();
    };

    // ---- Q fragments from pre-split globals ----
    uint32_t qh[16], ql[16];
    {
        const uint32_t* qhp  = &g_qh[(bh * Ll + m0 + rw + g) * 32];
        const uint32_t* qhp8 = qhp + 8 * 32;
        const uint32_t* qlp  = &g_ql[(bh * Ll + m0 + rw + g) * 32];
        const uint32_t* qlp8 = qlp + 8 * 32;
        #pragma unroll
        for (int j = 0; j < 4; j++) {
            qh[j*4 + 0] = qhp [8*j + t];
            qh[j*4 + 1] = qhp8[8*j + t];
            qh[j*4 + 2] = qhp [8*j + t + 4];
            qh[j*4 + 3] = qhp8[8*j + t + 4];
            ql[j*4 + 0] = qlp [8*j + t];
            ql[j*4 + 1] = qlp8[8*j + t];
            ql[j*4 + 2] = qlp [8*j + t + 4];
            ql[j*4 + 3] = qlp8[8*j + t + 4];
        }
    }

    // prologue: rotation K, short, V
    issueK(0);
    issueShort(0);
    issueV(0);
    CPWAIT2();          // K[0] done
    __syncthreads();

    float accO[8][4] = {};
    float mrow[2] = {-1e30f, -1e30f};
    float lrow[2] = {0.0f, 0.0f};
    const float* SBw = SBuf + rw * LS;

    #pragma unroll 1
    for (int nb = 0; nb < 32; nb++) {
        const int n1 = (nb < 31 ? nb + 1 : 31) * 64;
        uint32_t kbase = s2u(Ks) + loffB * 4;
        uint32_t vbase = s2u(Vs) + loffB * 4;

        // ---- S = Q K^T (2-split) ----
        float s[8][4] = {};
        #pragma unroll
        for (int j = 0; j < 4; j++) {
            #pragma unroll
            for (int p = 0; p < 4; p++) {
                uint32_t kh0, kh1, kh2, kh3;
                LDSM4(kh0, kh1, kh2, kh3, kbase + (p*576 + j*8)*4);
                mma16(s[2*p],   qh[j*4], qh[j*4+1], qh[j*4+2], qh[j*4+3], kh0, kh1);
                mma16(s[2*p],   ql[j*4], ql[j*4+1], ql[j*4+2], ql[j*4+3], kh0, kh1);
                mma16(s[2*p+1], qh[j*4], qh[j*4+1], qh[j*4+2], qh[j*4+3], kh2, kh3);
                mma16(s[2*p+1], ql[j*4], ql[j*4+1], ql[j*4+2], ql[j*4+3], kh2, kh3);
            }
        }

        CPWAIT1();          // short[nb] done (V[nb] may pend)
        __syncthreads();    // K reads finished everywhere; short visible
        issueK(n1);

        // ---- scale, mask, +short ----
        #pragma unroll
        for (int jn = 0; jn < 8; jn++) {
            int c0 = jn * 8 + 2 * t;
            int2 mk = *(const int2*)&Msk[c0];
            float2 sh0 = *(const float2*)&SBw[(g)     * LS + c0];
            float2 sh1 = *(const float2*)&SBw[(g + 8) * LS + c0];
            s[jn][0] = (mk.x ? s[jn][0] * 0.125f : NEGV) + sh0.x;
            s[jn][1] = (mk.y ? s[jn][1] * 0.125f : NEGV) + sh0.y;
            s[jn][2] = (mk.x ? s[jn][2] * 0.125f : NEGV) + sh1.x;
            s[jn][3] = (mk.y ? s[jn][3] * 0.125f : NEGV) + sh1.y;
        }

        // ---- online softmax ----
        #pragma unroll
        for (int half = 0; half < 2; half++) {
            const int r0 = half * 2;
            float tm = -1e30f;
            #pragma unroll
            for (int jn = 0; jn < 8; jn++)
                tm = fmaxf(tm, fmaxf(s[jn][r0], s[jn][r0 + 1]));
            tm = fmaxf(tm, __shfl_xor_sync(0xffffffffu, tm, 1));
            tm = fmaxf(tm, __shfl_xor_sync(0xffffffffu, tm, 2));
            float mn = fmaxf(mrow[half], tm);
            float sc = __expf(mrow[half] - mn);
            float ps = 0.0f;
            #pragma unroll
            for (int jn = 0; jn < 8; jn++) {
                s[jn][r0]     = __expf(s[jn][r0]     - mn);
                s[jn][r0 + 1] = __expf(s[jn][r0 + 1] - mn);
                ps += s[jn][r0] + s[jn][r0 + 1];
            }
            ps += __shfl_xor_sync(0xffffffffu, ps, 1);
            ps += __shfl_xor_sync(0xffffffffu, ps, 2);
            lrow[half] = lrow[half] * sc + ps;
            mrow[half] = mn;
            #pragma unroll
            for (int jd = 0; jd < 8; jd++) {
                accO[jd][r0]     *= sc;
                accO[jd][r0 + 1] *= sc;
            }
        }

        CPWAIT1();          // V[nb] done (K[n1] may pend)
        __syncthreads();    // short reads finished everywhere; V visible
        issueShort(n1);

        // ---- accO += P V (2-split: P hi+lo, V hi) ----
        #pragma unroll
        for (int j = 0; j < 4; j++) {
            uint32_t ph0, ph1, ph2, ph3, pl0, pl1, pl2, pl3;
            split2(s[2*j][0],   s[2*j][1],   ph0, pl0);
            split2(s[2*j][2],   s[2*j][3],   ph1, pl1);
            split2(s[2*j+1][0], s[2*j+1][1], ph2, pl2);
            split2(s[2*j+1][2], s[2*j+1][3], ph3, pl3);
            #pragma unroll
            for (int p = 0; p < 4; p++) {
                uint32_t vh0, vh1, vh2, vh3;
                LDSM4(vh0, vh1, vh2, vh3, vbase + (p*576 + j*8)*4);
                mma16(accO[2*p],   ph0, ph1, ph2, ph3, vh0, vh1);
                mma16(accO[2*p],   pl0, pl1, pl2, pl3, vh0, vh1);
                mma16(accO[2*p+1], ph0, ph1, ph2, ph3, vh2, vh3);
                mma16(accO[2*p+1], pl0, pl1, pl2, pl3, vh2, vh3);
            }
        }

        CPWAIT1();          // K[n1] done (short[n1] may pend)
        __syncthreads();    // V reads finished everywhere; K[n1] visible
        issueV(n1);
    }

    // ---- fused epilogue ----
    const float bm = bias_m[0];
    #pragma unroll
    for (int half = 0; half < 2; half++) {
        const int r0 = half * 2;
        int row = m0 + rw + g + half * 8;
        float piv = g_pi[bh * Ll + row] * 0.2f;
        float inv = 0.8f / lrow[half];
        #pragma unroll
        for (int jd = 0; jd < 8; jd++) {
            int c = jd * 8 + 2 * t;
            float2 sq = *(const float2*)&query[((size_t)b * Ll + row) * Dd + h * DK + c];
            float2 o;
            o.x = accO[jd][r0]     * inv + piv * sq.x + bm;
            o.y = accO[jd][r0 + 1] * inv + piv * sq.y + bm;
            *(float2*)&out[(bh * Ll + row) * DK + c] = o;
        }
    }
}

// ---------------------------------------------------------------------------
extern "C" void kernel_launch(void* const* d_in, const int* in_sizes, int n_in,
                              void* d_out, int out_size)
{
    const float* query  = (const float*)d_in[0];
    const float* key    = (const float*)d_in[1];
    const float* shortb = (const float*)d_in[2];
    const int*   mask   = (const int*)d_in[4];
    const float* Wq     = (const float*)d_in[5];
    const float* bq     = (const float*)d_in[6];
    const float* Wk     = (const float*)d_in[7];
    const float* bk     = (const float*)d_in[8];
    const float* w_mu   = (const float*)d_in[9];
    const float* b_mu   = (const float*)d_in[10];
    const float* bias_m = (const float*)d_in[11];
    float* out = (float*)d_out;

    cudaFuncSetAttribute(proj_mma_kernel, cudaFuncAttributeMaxDynamicSharedMemorySize, PROJ_SMEM);
    cudaFuncSetAttribute(attn_mma_kernel, cudaFuncAttributeMaxDynamicSharedMemorySize, ATTN_SMEM);

    prep_w_kernel<<<2304, 256>>>(Wq, Wk);
    prep_a_kernel<<<12288, 256>>>(query, key);
    prep_v_kernel<<<dim3(32, 24), 256>>>(query);
    proj_mma_kernel<<<dim3(64, 12, 2), 128, PROJ_SMEM>>>(bq, bk);
    mu_kernel<<<dim3(12, 2), 256>>>(query, mask, w_mu, b_mu);
    attn_mma_kernel<<<dim3(32, 12, 2), 128, ATTN_SMEM>>>(query, shortb, mask, bias_m, out);
}

// round 9
// speedup vs baseline: 3.3319x; 1.0900x over previous
#include <cuda_runtime.h>
#include <cuda_fp16.h>
#include <cstdint>

#define Bb 2
#define Hh 12
#define Ll 2048
#define Dd 768
#define DK 64
#define NEGV (-1000000000.0f)

// ---------------------------------------------------------------------------
// global scratch (pre-split half2; 2-split: B-side hi only)
// ---------------------------------------------------------------------------
__device__ uint32_t g_qh[Bb*Hh*Ll*32], g_ql[Bb*Hh*Ll*32];   // proj q out [bh*L+l][k2]
__device__ uint32_t g_kh[Bb*Hh*Ll*32];                      // proj k out (hi only)
__device__ uint32_t g_wh[2][Hh*64*384];                     // [qk][h*64+n][k2] hi only
__device__ uint32_t g_ah[2][4096*384], g_al[2][4096*384];   // [qk][row][k2]
__device__ uint32_t g_vth[Bb*Hh*64*1024];                   // [bh*64+d][n2] hi only
__device__ float g_pi[Bb*Hh*Ll];

// ---------------------------------------------------------------------------
// helpers
// ---------------------------------------------------------------------------
__device__ __forceinline__ void split2(float x, float y, uint32_t& h, uint32_t& l) {
    __half2 hh = __floats2half2_rn(x, y);
    float rx = x - __low2float(hh);
    float ry = y - __high2float(hh);
    __half2 ll = __floats2half2_rn(rx, ry);
    h = *(uint32_t*)&hh;
    l = *(uint32_t*)&ll;
}
__device__ __forceinline__ uint32_t pack2(float x, float y) {
    __half2 hh = __floats2half2_rn(x, y);
    return *(uint32_t*)&hh;
}

__device__ __forceinline__ void mma16(float d[4], uint32_t a0, uint32_t a1, uint32_t a2,
                                      uint32_t a3, uint32_t b0, uint32_t b1) {
    asm volatile(
        "mma.sync.aligned.m16n8k16.row.col.f32.f16.f16.f32 "
        "{%0,%1,%2,%3},{%4,%5,%6,%7},{%8,%9},{%0,%1,%2,%3};\n"
        : "+f"(d[0]), "+f"(d[1]), "+f"(d[2]), "+f"(d[3])
        : "r"(a0), "r"(a1), "r"(a2), "r"(a3), "r"(b0), "r"(b1));
}

__device__ __forceinline__ uint32_t s2u(const void* p) {
    return (uint32_t)__cvta_generic_to_shared(p);
}
#define LDSM4(r0,r1,r2,r3,addr) \
    asm volatile("ldmatrix.sync.aligned.m8n8.x4.shared.b16 {%0,%1,%2,%3}, [%4];" \
                 : "=r"(r0), "=r"(r1), "=r"(r2), "=r"(r3) : "r"(addr))
#define CP16(dst, src) asm volatile("cp.async.cg.shared.global [%0], [%1], 16;\n" :: "r"(dst), "l"(src))
#define CPCOMMIT() asm volatile("cp.async.commit_group;\n" ::: "memory")
#define CPWAIT1()  asm volatile("cp.async.wait_group 1;\n" ::: "memory")
#define CPWAIT0()  asm volatile("cp.async.wait_group 0;\n" ::: "memory")

// ---------------------------------------------------------------------------
// prep kernels
// ---------------------------------------------------------------------------
__global__ __launch_bounds__(256) void prep_w_kernel(
    const float* __restrict__ Wq, const float* __restrict__ Wk)
{
    int idx = blockIdx.x * 256 + threadIdx.x;
    int qk = idx >= (Hh*64*384);
    int r = idx - qk * (Hh*64*384);
    int col = r / 384;
    int k2 = r % 384;
    const float* W = qk ? Wk : Wq;
    g_wh[qk][r] = pack2(W[(size_t)(2*k2) * Dd + col], W[(size_t)(2*k2+1) * Dd + col]);
}

__global__ __launch_bounds__(256) void prep_a_kernel(
    const float* __restrict__ query, const float* __restrict__ key)
{
    int idx = blockIdx.x * 256 + threadIdx.x;
    int qk = idx >= (4096*384);
    int r = idx - qk * (4096*384);
    int row = r / 384;
    int k2  = r % 384;
    const float* src = qk ? key : query;
    float2 f = *(const float2*)&src[(size_t)row * Dd + 2*k2];
    uint32_t hh, ll;
    split2(f.x, f.y, hh, ll);
    g_ah[qk][r] = hh;
    g_al[qk][r] = ll;
}

// V transposed: g_vth[bh*64 + d][n2] = half2(V[2n2][d], V[2n2+1][d])
__global__ __launch_bounds__(256) void prep_v_kernel(const float* __restrict__ query)
{
    __shared__ uint32_t th[64][33];
    const int tile = blockIdx.x;
    const int bh = blockIdx.y;
    const int b = bh / Hh, h = bh % Hh;
    const int n20 = tile * 32;
    const int tid = threadIdx.x;
    #pragma unroll
    for (int i = 0; i < 8; i++) {
        int lin = tid + 256 * i;
        int n2l = lin >> 6;
        int d = lin & 63;
        const float* q0 = &query[(size_t)(b * Ll + 2*(n20 + n2l)) * Dd + h * DK + d];
        th[d][n2l] = pack2(q0[0], q0[Dd]);
    }
    __syncthreads();
    #pragma unroll
    for (int i = 0; i < 8; i++) {
        int lin = tid + 256 * i;
        int d = lin >> 5;
        int n2l = lin & 31;
        g_vth[(size_t)(bh * 64 + d) * 1024 + n20 + n2l] = th[d][n2l];
    }
}

// ---------------------------------------------------------------------------
// Projection GEMM: 128 rows x 128 cols (2 heads) per block, 256 threads,
// fp16 2-split (A hi+lo, W hi), k-tile 64, double-buffered cp.async.
// 8 warps = 4 row-groups (32 rows: two m16 blocks) x 2 col-groups (64 cols).
// ---------------------------------------------------------------------------
#define PJ_SET 13824   // u32 per stage: Ah 4608 | Al 4608 | Wh 4608
#define PROJ_SMEM (2 * PJ_SET * 4)

__global__ __launch_bounds__(256, 2) void proj_mma_kernel(
    const float* __restrict__ bq, const float* __restrict__ bk)
{
    extern __shared__ uint32_t psm[];
    const int qk = blockIdx.z;
    const int tid = threadIdx.x;
    const int w = tid >> 5, lane = tid & 31, g = lane >> 2, t = lane & 3;
    const int rowg = w >> 1, colg = w & 1;
    const int rb0 = rowg * 32;
    const int row0 = blockIdx.x * 128;
    const int hp = blockIdx.y;

    const uint32_t* Agh = g_ah[qk];
    const uint32_t* Agl = g_al[qk];
    const uint32_t* Wgh = &g_wh[qk][(size_t)hp * 128 * 384];
    const float* bias = qk ? bk : bq;

    const int mA = tid >> 1, kbA = (tid & 1) * 16;

    const int lm = lane >> 3, lr = lane & 7;
    const int loffA = ((lm & 1) * 8 + lr) * 36 + (lm >> 1) * 4;
    const int loffB = ((lm >> 1) * 8 + lr) * 36 + (lm & 1) * 4;

    auto stagep = [&](int kb) {
        uint32_t* S = psm + (kb & 1) * PJ_SET;
        const int koff = kb * 32 + kbA;
        const uint32_t* sa  = &Agh[(size_t)(row0 + mA) * 384 + koff];
        const uint32_t* sal = &Agl[(size_t)(row0 + mA) * 384 + koff];
        const uint32_t* sw  = &Wgh[(size_t)mA * 384 + koff];
        #pragma unroll
        for (int i = 0; i < 4; i++) {
            CP16(s2u(&S[mA*36 + kbA + i*4]),        sa  + i*4);
            CP16(s2u(&S[4608 + mA*36 + kbA + i*4]), sal + i*4);
            CP16(s2u(&S[9216 + mA*36 + kbA + i*4]), sw  + i*4);
        }
        CPCOMMIT();
    };

    stagep(0);
    float acc0[8][4] = {};   // row-block rb0
    float acc1[8][4] = {};   // row-block rb0+16

    #pragma unroll 1
    for (int kb = 0; kb < 12; kb++) {
        if (kb < 11) { stagep(kb + 1); CPWAIT1(); } else { CPWAIT0(); }
        __syncthreads();
        uint32_t sbase = s2u(psm) + ((kb & 1) * PJ_SET) * 4;
        uint32_t a0h = sbase + (rb0*36 + loffA) * 4;
        uint32_t a1h = a0h + 16*36*4;
        uint32_t a0l = a0h + 4608*4;
        uint32_t a1l = a1h + 4608*4;
        uint32_t wb  = sbase + (9216 + colg*64*36 + loffB) * 4;
        #pragma unroll
        for (int j = 0; j < 4; j++) {
            uint32_t p0h0,p0h1,p0h2,p0h3, p1h0,p1h1,p1h2,p1h3;
            uint32_t p0l0,p0l1,p0l2,p0l3, p1l0,p1l1,p1l2,p1l3;
            LDSM4(p0h0,p0h1,p0h2,p0h3, a0h + j*32);
            LDSM4(p1h0,p1h1,p1h2,p1h3, a1h + j*32);
            LDSM4(p0l0,p0l1,p0l2,p0l3, a0l + j*32);
            LDSM4(p1l0,p1l1,p1l2,p1l3, a1l + j*32);
            #pragma unroll
            for (int p = 0; p < 4; p++) {
                uint32_t wh0, wh1, wh2, wh3;
                LDSM4(wh0, wh1, wh2, wh3, wb + (p*576 + j*8)*4);
                mma16(acc0[2*p],   p0h0,p0h1,p0h2,p0h3, wh0, wh1);
                mma16(acc0[2*p],   p0l0,p0l1,p0l2,p0l3, wh0, wh1);
                mma16(acc0[2*p+1], p0h0,p0h1,p0h2,p0h3, wh2, wh3);
                mma16(acc0[2*p+1], p0l0,p0l1,p0l2,p0l3, wh2, wh3);
                mma16(acc1[2*p],   p1h0,p1h1,p1h2,p1h3, wh0, wh1);
                mma16(acc1[2*p],   p1l0,p1l1,p1l2,p1l3, wh0, wh1);
                mma16(acc1[2*p+1], p1h0,p1h1,p1h2,p1h3, wh2, wh3);
                mma16(acc1[2*p+1], p1l0,p1l1,p1l2,p1l3, wh2, wh3);
            }
        }
        __syncthreads();
    }

    const int hglob = hp * 2 + colg;
    const float* bp = &bias[hglob * 64];
    uint32_t* oqh = g_qh;
    uint32_t* oql = g_ql;
    #pragma unroll
    for (int rb2 = 0; rb2 < 2; rb2++) {
        float (*acc)[4] = rb2 ? acc1 : acc0;
        #pragma unroll
        for (int half = 0; half < 2; half++) {
            int row = row0 + rb0 + rb2*16 + g + half*8;
            int b_ = row >> 11, l = row & (Ll - 1);
            size_t base = ((size_t)(b_ * Hh + hglob) * Ll + l) * 32;
            #pragma unroll
            for (int jn = 0; jn < 8; jn++) {
                float2 bb = *(const float2*)&bp[jn*8 + 2*t];
                float x = acc[jn][2*half]     + bb.x;
                float y = acc[jn][2*half + 1] + bb.y;
                size_t o = base + jn*4 + t;
                if (qk == 0) {
                    uint32_t hh, llv;
                    split2(x, y, hh, llv);
                    oqh[o] = hh; oql[o] = llv;
                } else {
                    g_kh[o] = pack2(x, y);
                }
            }
        }
    }
}

// ---------------------------------------------------------------------------
// mu (= pi) kernel: pi = softmax over L of (seq_h @ w_mu + b_mu), masked.
// ---------------------------------------------------------------------------
__global__ __launch_bounds__(256) void mu_kernel(
    const float* __restrict__ query, const int* __restrict__ mask,
    const float* __restrict__ w_mu, const float* __restrict__ b_mu)
{
    const int h = blockIdx.x, b = blockIdx.y;
    const int tid = threadIdx.x;
    __shared__ float wmu[64];
    __shared__ float red[8];
    if (tid < 64) wmu[tid] = w_mu[tid];
    __syncthreads();
    const float bmu = b_mu[0];

    float lg[8];
    float lmax = -1e30f;
    #pragma unroll
    for (int j = 0; j < 8; j++) {
        int l = tid + j * 256;
        const float* sp = &query[((size_t)b * Ll + l) * Dd + h * DK];
        float dm = 0.0f;
        #pragma unroll
        for (int d = 0; d < 64; d += 4) {
            float4 s4 = *(const float4*)&sp[d];
            dm += s4.x * wmu[d] + s4.y * wmu[d+1] + s4.z * wmu[d+2] + s4.w * wmu[d+3];
        }
        float v = dm + bmu;
        if (mask[b * Ll + l] == 0) v = NEGV;
        lg[j] = v;
        lmax = fmaxf(lmax, v);
    }
    {
        int wi = tid >> 5, lane = tid & 31;
        #pragma unroll
        for (int o = 16; o; o >>= 1) lmax = fmaxf(lmax, __shfl_xor_sync(~0u, lmax, o));
        if (lane == 0) red[wi] = lmax;
        __syncthreads();
        if (wi == 0) {
            float r = (lane < 8) ? red[lane] : -1e30f;
            #pragma unroll
            for (int o = 16; o; o >>= 1) r = fmaxf(r, __shfl_xor_sync(~0u, r, o));
            if (lane == 0) red[0] = r;
        }
        __syncthreads();
        lmax = red[0];
        __syncthreads();
    }
    float lsum = 0.0f;
    #pragma unroll
    for (int j = 0; j < 8; j++) { lg[j] = __expf(lg[j] - lmax); lsum += lg[j]; }
    {
        int wi = tid >> 5, lane = tid & 31;
        #pragma unroll
        for (int o = 16; o; o >>= 1) lsum += __shfl_xor_sync(~0u, lsum, o);
        if (lane == 0) red[wi] = lsum;
        __syncthreads();
        if (wi == 0) {
            float r = (lane < 8) ? red[lane] : 0.0f;
            #pragma unroll
            for (int o = 16; o; o >>= 1) r += __shfl_xor_sync(~0u, r, o);
            if (lane == 0) red[0] = r;
        }
        __syncthreads();
        lsum = red[0];
    }
    float inv = 1.0f / lsum;
    #pragma unroll
    for (int j = 0; j < 8; j++)
        g_pi[((size_t)b * Hh + h) * Ll + tid + j * 256] = lg[j] * inv;
}

// ---------------------------------------------------------------------------
// Attention: 64-row tiles, 128 threads (4 warps x 16 rows), fp16 2-split.
// FULL double-buffered stages (short+K+V+mask in ONE cp.async group each),
// prefetch distance = 1 full chunk; body has no internal waits.
// ---------------------------------------------------------------------------
#define LS 68
#define STAGE_F 9024   // floats: SBuf 4352 | K 2304 | V 2304 | mask 64
#define ATTN_SMEM (2 * STAGE_F * 4)

__global__ __launch_bounds__(128, 3) void attn_mma_kernel(
    const float* __restrict__ query, const float* __restrict__ shortb,
    const int* __restrict__ mask, const float* __restrict__ bias_m,
    float* __restrict__ out)
{
    extern __shared__ float smb[];

    const int tid = threadIdx.x;
    const int w = tid >> 5, lane = tid & 31;
    const int g = lane >> 2, t = lane & 3;
    const int rw = w * 16;
    const int m0 = blockIdx.x * 64;
    const int h = blockIdx.y, b = blockIdx.z;
    const size_t bh = (size_t)b * Hh + h;
    const float* sp = shortb + (bh * Ll + m0) * Ll;

    const int lm = lane >> 3, lr = lane & 7;
    const int loffB = ((lm >> 1) * 8 + lr) * 36 + (lm & 1) * 4;

    const int rS = tid >> 1, sS = (tid & 1) * 16;

    auto stageA = [&](int n0, int bi) {
        float* SB = smb + bi * STAGE_F;
        uint32_t* K = (uint32_t*)(SB + 4352);
        uint32_t* V = K + 2304;
        int* M = (int*)(V + 2304);
        #pragma unroll
        for (int it = 0; it < 8; it++) {
            int lin = tid + it * 128, row = lin >> 4, c4 = (lin & 15) * 4;
            CP16(s2u(&SB[row * LS + c4]), &sp[(size_t)row * Ll + n0 + c4]);
        }
        const uint32_t* skh = &g_kh[(bh * Ll + n0 + rS) * 32 + sS];
        const uint32_t* svh = &g_vth[(bh * 64 + rS) * 1024 + (n0 >> 1) + sS];
        #pragma unroll
        for (int i = 0; i < 4; i++) {
            CP16(s2u(&K[rS*36 + sS + i*4]), skh + i*4);
            CP16(s2u(&V[rS*36 + sS + i*4]), svh + i*4);
        }
        if (tid < 16) CP16(s2u(&M[tid * 4]), &mask[b * Ll + n0 + tid * 4]);
        CPCOMMIT();
    };

    // ---- Q fragments from pre-split globals ----
    uint32_t qh[16], ql[16];
    {
        const uint32_t* qhp  = &g_qh[(bh * Ll + m0 + rw + g) * 32];
        const uint32_t* qhp8 = qhp + 8 * 32;
        const uint32_t* qlp  = &g_ql[(bh * Ll + m0 + rw + g) * 32];
        const uint32_t* qlp8 = qlp + 8 * 32;
        #pragma unroll
        for (int j = 0; j < 4; j++) {
            qh[j*4 + 0] = qhp [8*j + t];
            qh[j*4 + 1] = qhp8[8*j + t];
            qh[j*4 + 2] = qhp [8*j + t + 4];
            qh[j*4 + 3] = qhp8[8*j + t + 4];
            ql[j*4 + 0] = qlp [8*j + t];
            ql[j*4 + 1] = qlp8[8*j + t];
            ql[j*4 + 2] = qlp [8*j + t + 4];
            ql[j*4 + 3] = qlp8[8*j + t + 4];
        }
    }

    // prologue: stages 0 and 1 in flight
    stageA(0, 0);
    stageA(64, 1);
    CPWAIT1();          // stage 0 complete
    __syncthreads();

    float accO[8][4] = {};
    float mrow[2] = {-1e30f, -1e30f};
    float lrow[2] = {0.0f, 0.0f};

    #pragma unroll 1
    for (int nb = 0; nb < 32; nb++) {
        const int bi = nb & 1;
        float* SB = smb + bi * STAGE_F;
        const float* SBw = SB + rw * LS;
        uint32_t kbase = s2u(SB + 4352) + loffB * 4;
        uint32_t vbase = kbase + 2304 * 4;
        const int* Mc = (const int*)(SB + 4352 + 4608);

        // ---- S = Q K^T (2-split) ----
        float s[8][4] = {};
        #pragma unroll
        for (int j = 0; j < 4; j++) {
            #pragma unroll
            for (int p = 0; p < 4; p++) {
                uint32_t kh0, kh1, kh2, kh3;
                LDSM4(kh0, kh1, kh2, kh3, kbase + (p*576 + j*8)*4);
                mma16(s[2*p],   qh[j*4], qh[j*4+1], qh[j*4+2], qh[j*4+3], kh0, kh1);
                mma16(s[2*p],   ql[j*4], ql[j*4+1], ql[j*4+2], ql[j*4+3], kh0, kh1);
                mma16(s[2*p+1], qh[j*4], qh[j*4+1], qh[j*4+2], qh[j*4+3], kh2, kh3);
                mma16(s[2*p+1], ql[j*4], ql[j*4+1], ql[j*4+2], ql[j*4+3], kh2, kh3);
            }
        }

        // ---- scale, mask, +short ----
        #pragma unroll
        for (int jn = 0; jn < 8; jn++) {
            int c0 = jn * 8 + 2 * t;
            int2 mk = *(const int2*)&Mc[c0];
            float2 sh0 = *(const float2*)&SBw[(g)     * LS + c0];
            float2 sh1 = *(const float2*)&SBw[(g + 8) * LS + c0];
            s[jn][0] = (mk.x ? s[jn][0] * 0.125f : NEGV) + sh0.x;
            s[jn][1] = (mk.y ? s[jn][1] * 0.125f : NEGV) + sh0.y;
            s[jn][2] = (mk.x ? s[jn][2] * 0.125f : NEGV) + sh1.x;
            s[jn][3] = (mk.y ? s[jn][3] * 0.125f : NEGV) + sh1.y;
        }

        // ---- online softmax ----
        #pragma unroll
        for (int half = 0; half < 2; half++) {
            const int r0 = half * 2;
            float tm = -1e30f;
            #pragma unroll
            for (int jn = 0; jn < 8; jn++)
                tm = fmaxf(tm, fmaxf(s[jn][r0], s[jn][r0 + 1]));
            tm = fmaxf(tm, __shfl_xor_sync(0xffffffffu, tm, 1));
            tm = fmaxf(tm, __shfl_xor_sync(0xffffffffu, tm, 2));
            float mn = fmaxf(mrow[half], tm);
            float sc = __expf(mrow[half] - mn);
            float ps = 0.0f;
            #pragma unroll
            for (int jn = 0; jn < 8; jn++) {
                s[jn][r0]     = __expf(s[jn][r0]     - mn);
                s[jn][r0 + 1] = __expf(s[jn][r0 + 1] - mn);
                ps += s[jn][r0] + s[jn][r0 + 1];
            }
            ps += __shfl_xor_sync(0xffffffffu, ps, 1);
            ps += __shfl_xor_sync(0xffffffffu, ps, 2);
            lrow[half] = lrow[half] * sc + ps;
            mrow[half] = mn;
            #pragma unroll
            for (int jd = 0; jd < 8; jd++) {
                accO[jd][r0]     *= sc;
                accO[jd][r0 + 1] *= sc;
            }
        }

        // ---- accO += P V (split P in registers) ----
        #pragma unroll
        for (int j = 0; j < 4; j++) {
            uint32_t ph0, ph1, ph2, ph3, pl0, pl1, pl2, pl3;
            split2(s[2*j][0],   s[2*j][1],   ph0, pl0);
            split2(s[2*j][2],   s[2*j][3],   ph1, pl1);
            split2(s[2*j+1][0], s[2*j+1][1], ph2, pl2);
            split2(s[2*j+1][2], s[2*j+1][3], ph3, pl3);
            #pragma unroll
            for (int p = 0; p < 4; p++) {
                uint32_t vh0, vh1, vh2, vh3;
                LDSM4(vh0, vh1, vh2, vh3, vbase + (p*576 + j*8)*4);
                mma16(accO[2*p],   ph0, ph1, ph2, ph3, vh0, vh1);
                mma16(accO[2*p],   pl0, pl1, pl2, pl3, vh0, vh1);
                mma16(accO[2*p+1], ph0, ph1, ph2, ph3, vh2, vh3);
                mma16(accO[2*p+1], pl0, pl1, pl2, pl3, vh2, vh3);
            }
        }

        // ---- rotate buffers ----
        __syncthreads();                       // everyone done reading stage nb
        if (nb < 31) {
            int n2 = (nb + 2 < 32 ? nb + 2 : 31) * 64;
            stageA(n2, bi);                    // reuse this buffer
            CPWAIT1();                         // stage nb+1 complete
            __syncthreads();                   // ...and visible
        }
    }

    // ---- fused epilogue ----
    const float bm = bias_m[0];
    #pragma unroll
    for (int half = 0; half < 2; half++) {
        const int r0 = half * 2;
        int row = m0 + rw + g + half * 8;
        float piv = g_pi[bh * Ll + row] * 0.2f;
        float inv = 0.8f / lrow[half];
        #pragma unroll
        for (int jd = 0; jd < 8; jd++) {
            int c = jd * 8 + 2 * t;
            float2 sq = *(const float2*)&query[((size_t)b * Ll + row) * Dd + h * DK + c];
            float2 o;
            o.x = accO[jd][r0]     * inv + piv * sq.x + bm;
            o.y = accO[jd][r0 + 1] * inv + piv * sq.y + bm;
            *(float2*)&out[(bh * Ll + row) * DK + c] = o;
        }
    }
}

// ---------------------------------------------------------------------------
extern "C" void kernel_launch(void* const* d_in, const int* in_sizes, int n_in,
                              void* d_out, int out_size)
{
    const float* query  = (const float*)d_in[0];
    const float* key    = (const float*)d_in[1];
    const float* shortb = (const float*)d_in[2];
    const int*   mask   = (const int*)d_in[4];
    const float* Wq     = (const float*)d_in[5];
    const float* bq     = (const float*)d_in[6];
    const float* Wk     = (const float*)d_in[7];
    const float* bk     = (const float*)d_in[8];
    const float* w_mu   = (const float*)d_in[9];
    const float* b_mu   = (const float*)d_in[10];
    const float* bias_m = (const float*)d_in[11];
    float* out = (float*)d_out;

    cudaFuncSetAttribute(proj_mma_kernel, cudaFuncAttributeMaxDynamicSharedMemorySize, PROJ_SMEM);
    cudaFuncSetAttribute(attn_mma_kernel, cudaFuncAttributeMaxDynamicSharedMemorySize, ATTN_SMEM);

    prep_w_kernel<<<2304, 256>>>(Wq, Wk);
    prep_a_kernel<<<12288, 256>>>(query, key);
    prep_v_kernel<<<dim3(32, 24), 256>>>(query);
    proj_mma_kernel<<<dim3(32, 6, 2), 256, PROJ_SMEM>>>(bq, bk);
    mu_kernel<<<dim3(12, 2), 256>>>(query, mask, w_mu, b_mu);
    attn_mma_kernel<<<dim3(32, 12, 2), 128, ATTN_SMEM>>>(query, shortb, mask, bias_m, out);
}

// round 10
// speedup vs baseline: 3.5845x; 1.0758x over previous
#include <cuda_runtime.h>
#include <cuda_fp16.h>
#include <cstdint>

#define Bb 2
#define Hh 12
#define Ll 2048
#define Dd 768
#define DK 64
#define NEGV (-1000000000.0f)

// ---------------------------------------------------------------------------
// global scratch (pre-split half2; 2-split: B-side hi only)
// ---------------------------------------------------------------------------
__device__ uint32_t g_qh[Bb*Hh*Ll*32], g_ql[Bb*Hh*Ll*32];   // proj q out [bh*L+l][k2]
__device__ uint32_t g_kh[Bb*Hh*Ll*32];                      // proj k out (hi only)
__device__ uint32_t g_wh[2][Hh*64*384];                     // [qk][h*64+n][k2] hi only
__device__ uint32_t g_ah[2][4096*384], g_al[2][4096*384];   // [qk][row][k2]
__device__ uint32_t g_vth[Bb*Hh*64*1024];                   // [bh*64+d][n2] hi only
__device__ float g_pi[Bb*Hh*Ll];

// ---------------------------------------------------------------------------
// helpers
// ---------------------------------------------------------------------------
__device__ __forceinline__ void split2(float x, float y, uint32_t& h, uint32_t& l) {
    __half2 hh = __floats2half2_rn(x, y);
    float rx = x - __low2float(hh);
    float ry = y - __high2float(hh);
    __half2 ll = __floats2half2_rn(rx, ry);
    h = *(uint32_t*)&hh;
    l = *(uint32_t*)&ll;
}
__device__ __forceinline__ uint32_t pack2(float x, float y) {
    __half2 hh = __floats2half2_rn(x, y);
    return *(uint32_t*)&hh;
}

__device__ __forceinline__ void mma16(float d[4], uint32_t a0, uint32_t a1, uint32_t a2,
                                      uint32_t a3, uint32_t b0, uint32_t b1) {
    asm volatile(
        "mma.sync.aligned.m16n8k16.row.col.f32.f16.f16.f32 "
        "{%0,%1,%2,%3},{%4,%5,%6,%7},{%8,%9},{%0,%1,%2,%3};\n"
        : "+f"(d[0]), "+f"(d[1]), "+f"(d[2]), "+f"(d[3])
        : "r"(a0), "r"(a1), "r"(a2), "r"(a3), "r"(b0), "r"(b1));
}

__device__ __forceinline__ uint32_t s2u(const void* p) {
    return (uint32_t)__cvta_generic_to_shared(p);
}
#define LDSM4(r0,r1,r2,r3,addr) \
    asm volatile("ldmatrix.sync.aligned.m8n8.x4.shared.b16 {%0,%1,%2,%3}, [%4];" \
                 : "=r"(r0), "=r"(r1), "=r"(r2), "=r"(r3) : "r"(addr))
#define CP16(dst, src) asm volatile("cp.async.cg.shared.global [%0], [%1], 16;\n" :: "r"(dst), "l"(src))
#define CPCOMMIT() asm volatile("cp.async.commit_group;\n" ::: "memory")
#define CPWAIT1()  asm volatile("cp.async.wait_group 1;\n" ::: "memory")
#define CPWAIT0()  asm volatile("cp.async.wait_group 0;\n" ::: "memory")

// ---------------------------------------------------------------------------
// prep kernels
// ---------------------------------------------------------------------------
__global__ __launch_bounds__(256) void prep_w_kernel(
    const float* __restrict__ Wq, const float* __restrict__ Wk)
{
    int idx = blockIdx.x * 256 + threadIdx.x;
    int qk = idx >= (Hh*64*384);
    int r = idx - qk * (Hh*64*384);
    int col = r / 384;
    int k2 = r % 384;
    const float* W = qk ? Wk : Wq;
    g_wh[qk][r] = pack2(W[(size_t)(2*k2) * Dd + col], W[(size_t)(2*k2+1) * Dd + col]);
}

__global__ __launch_bounds__(256) void prep_a_kernel(
    const float* __restrict__ query, const float* __restrict__ key)
{
    int idx = blockIdx.x * 256 + threadIdx.x;
    int qk = idx >= (4096*384);
    int r = idx - qk * (4096*384);
    int row = r / 384;
    int k2  = r % 384;
    const float* src = qk ? key : query;
    float2 f = *(const float2*)&src[(size_t)row * Dd + 2*k2];
    uint32_t hh, ll;
    split2(f.x, f.y, hh, ll);
    g_ah[qk][r] = hh;
    g_al[qk][r] = ll;
}

// V transposed: g_vth[bh*64 + d][n2] = half2(V[2n2][d], V[2n2+1][d])
__global__ __launch_bounds__(256) void prep_v_kernel(const float* __restrict__ query)
{
    __shared__ uint32_t th[64][33];
    const int tile = blockIdx.x;
    const int bh = blockIdx.y;
    const int b = bh / Hh, h = bh % Hh;
    const int n20 = tile * 32;
    const int tid = threadIdx.x;
    #pragma unroll
    for (int i = 0; i < 8; i++) {
        int lin = tid + 256 * i;
        int n2l = lin >> 6;
        int d = lin & 63;
        const float* q0 = &query[(size_t)(b * Ll + 2*(n20 + n2l)) * Dd + h * DK + d];
        th[d][n2l] = pack2(q0[0], q0[Dd]);
    }
    __syncthreads();
    #pragma unroll
    for (int i = 0; i < 8; i++) {
        int lin = tid + 256 * i;
        int d = lin >> 5;
        int n2l = lin & 31;
        g_vth[(size_t)(bh * 64 + d) * 1024 + n20 + n2l] = th[d][n2l];
    }
}

// ---------------------------------------------------------------------------
// Projection GEMM: 128 rows x 128 cols (2 heads) per block, 256 threads,
// fp16 2-split (A hi+lo, W hi), k-tile 64, double-buffered cp.async.
// ---------------------------------------------------------------------------
#define PJ_SET 13824   // u32 per stage: Ah 4608 | Al 4608 | Wh 4608
#define PROJ_SMEM (2 * PJ_SET * 4)

__global__ __launch_bounds__(256, 2) void proj_mma_kernel(
    const float* __restrict__ bq, const float* __restrict__ bk)
{
    extern __shared__ uint32_t psm[];
    const int qk = blockIdx.z;
    const int tid = threadIdx.x;
    const int w = tid >> 5, lane = tid & 31, g = lane >> 2, t = lane & 3;
    const int rowg = w >> 1, colg = w & 1;
    const int rb0 = rowg * 32;
    const int row0 = blockIdx.x * 128;
    const int hp = blockIdx.y;

    const uint32_t* Agh = g_ah[qk];
    const uint32_t* Agl = g_al[qk];
    const uint32_t* Wgh = &g_wh[qk][(size_t)hp * 128 * 384];
    const float* bias = qk ? bk : bq;

    const int mA = tid >> 1, kbA = (tid & 1) * 16;

    const int lm = lane >> 3, lr = lane & 7;
    const int loffA = ((lm & 1) * 8 + lr) * 36 + (lm >> 1) * 4;
    const int loffB = ((lm >> 1) * 8 + lr) * 36 + (lm & 1) * 4;

    auto stagep = [&](int kb) {
        uint32_t* S = psm + (kb & 1) * PJ_SET;
        const int koff = kb * 32 + kbA;
        const uint32_t* sa  = &Agh[(size_t)(row0 + mA) * 384 + koff];
        const uint32_t* sal = &Agl[(size_t)(row0 + mA) * 384 + koff];
        const uint32_t* sw  = &Wgh[(size_t)mA * 384 + koff];
        #pragma unroll
        for (int i = 0; i < 4; i++) {
            CP16(s2u(&S[mA*36 + kbA + i*4]),        sa  + i*4);
            CP16(s2u(&S[4608 + mA*36 + kbA + i*4]), sal + i*4);
            CP16(s2u(&S[9216 + mA*36 + kbA + i*4]), sw  + i*4);
        }
        CPCOMMIT();
    };

    stagep(0);
    float acc0[8][4] = {};
    float acc1[8][4] = {};

    #pragma unroll 1
    for (int kb = 0; kb < 12; kb++) {
        if (kb < 11) { stagep(kb + 1); CPWAIT1(); } else { CPWAIT0(); }
        __syncthreads();
        uint32_t sbase = s2u(psm) + ((kb & 1) * PJ_SET) * 4;
        uint32_t a0h = sbase + (rb0*36 + loffA) * 4;
        uint32_t a1h = a0h + 16*36*4;
        uint32_t a0l = a0h + 4608*4;
        uint32_t a1l = a1h + 4608*4;
        uint32_t wb  = sbase + (9216 + colg*64*36 + loffB) * 4;
        #pragma unroll
        for (int j = 0; j < 4; j++) {
            uint32_t p0h0,p0h1,p0h2,p0h3, p1h0,p1h1,p1h2,p1h3;
            uint32_t p0l0,p0l1,p0l2,p0l3, p1l0,p1l1,p1l2,p1l3;
            LDSM4(p0h0,p0h1,p0h2,p0h3, a0h + j*32);
            LDSM4(p1h0,p1h1,p1h2,p1h3, a1h + j*32);
            LDSM4(p0l0,p0l1,p0l2,p0l3, a0l + j*32);
            LDSM4(p1l0,p1l1,p1l2,p1l3, a1l + j*32);
            #pragma unroll
            for (int p = 0; p < 4; p++) {
                uint32_t wh0, wh1, wh2, wh3;
                LDSM4(wh0, wh1, wh2, wh3, wb + (p*576 + j*8)*4);
                mma16(acc0[2*p],   p0h0,p0h1,p0h2,p0h3, wh0, wh1);
                mma16(acc0[2*p],   p0l0,p0l1,p0l2,p0l3, wh0, wh1);
                mma16(acc0[2*p+1], p0h0,p0h1,p0h2,p0h3, wh2, wh3);
                mma16(acc0[2*p+1], p0l0,p0l1,p0l2,p0l3, wh2, wh3);
                mma16(acc1[2*p],   p1h0,p1h1,p1h2,p1h3, wh0, wh1);
                mma16(acc1[2*p],   p1l0,p1l1,p1l2,p1l3, wh0, wh1);
                mma16(acc1[2*p+1], p1h0,p1h1,p1h2,p1h3, wh2, wh3);
                mma16(acc1[2*p+1], p1l0,p1l1,p1l2,p1l3, wh2, wh3);
            }
        }
        __syncthreads();
    }

    const int hglob = hp * 2 + colg;
    const float* bp = &bias[hglob * 64];
    #pragma unroll
    for (int rb2 = 0; rb2 < 2; rb2++) {
        float (*acc)[4] = rb2 ? acc1 : acc0;
        #pragma unroll
        for (int half = 0; half < 2; half++) {
            int row = row0 + rb0 + rb2*16 + g + half*8;
            int b_ = row >> 11, l = row & (Ll - 1);
            size_t base = ((size_t)(b_ * Hh + hglob) * Ll + l) * 32;
            #pragma unroll
            for (int jn = 0; jn < 8; jn++) {
                float2 bb = *(const float2*)&bp[jn*8 + 2*t];
                float x = acc[jn][2*half]     + bb.x;
                float y = acc[jn][2*half + 1] + bb.y;
                size_t o = base + jn*4 + t;
                if (qk == 0) {
                    uint32_t hh, llv;
                    split2(x, y, hh, llv);
                    g_qh[o] = hh; g_ql[o] = llv;
                } else {
                    g_kh[o] = pack2(x, y);
                }
            }
        }
    }
}

// ---------------------------------------------------------------------------
// mu (= pi) kernel: pi = softmax over L of (seq_h @ w_mu + b_mu), masked.
// ---------------------------------------------------------------------------
__global__ __launch_bounds__(256) void mu_kernel(
    const float* __restrict__ query, const int* __restrict__ mask,
    const float* __restrict__ w_mu, const float* __restrict__ b_mu)
{
    const int h = blockIdx.x, b = blockIdx.y;
    const int tid = threadIdx.x;
    __shared__ float wmu[64];
    __shared__ float red[8];
    if (tid < 64) wmu[tid] = w_mu[tid];
    __syncthreads();
    const float bmu = b_mu[0];

    float lg[8];
    float lmax = -1e30f;
    #pragma unroll
    for (int j = 0; j < 8; j++) {
        int l = tid + j * 256;
        const float* sp = &query[((size_t)b * Ll + l) * Dd + h * DK];
        float dm = 0.0f;
        #pragma unroll
        for (int d = 0; d < 64; d += 4) {
            float4 s4 = *(const float4*)&sp[d];
            dm += s4.x * wmu[d] + s4.y * wmu[d+1] + s4.z * wmu[d+2] + s4.w * wmu[d+3];
        }
        float v = dm + bmu;
        if (mask[b * Ll + l] == 0) v = NEGV;
        lg[j] = v;
        lmax = fmaxf(lmax, v);
    }
    {
        int wi = tid >> 5, lane = tid & 31;
        #pragma unroll
        for (int o = 16; o; o >>= 1) lmax = fmaxf(lmax, __shfl_xor_sync(~0u, lmax, o));
        if (lane == 0) red[wi] = lmax;
        __syncthreads();
        if (wi == 0) {
            float r = (lane < 8) ? red[lane] : -1e30f;
            #pragma unroll
            for (int o = 16; o; o >>= 1) r = fmaxf(r, __shfl_xor_sync(~0u, r, o));
            if (lane == 0) red[0] = r;
        }
        __syncthreads();
        lmax = red[0];
        __syncthreads();
    }
    float lsum = 0.0f;
    #pragma unroll
    for (int j = 0; j < 8; j++) { lg[j] = __expf(lg[j] - lmax); lsum += lg[j]; }
    {
        int wi = tid >> 5, lane = tid & 31;
        #pragma unroll
        for (int o = 16; o; o >>= 1) lsum += __shfl_xor_sync(~0u, lsum, o);
        if (lane == 0) red[wi] = lsum;
        __syncthreads();
        if (wi == 0) {
            float r = (lane < 8) ? red[lane] : 0.0f;
            #pragma unroll
            for (int o = 16; o; o >>= 1) r += __shfl_xor_sync(~0u, r, o);
            if (lane == 0) red[0] = r;
        }
        __syncthreads();
        lsum = red[0];
    }
    float inv = 1.0f / lsum;
    #pragma unroll
    for (int j = 0; j < 8; j++)
        g_pi[((size_t)b * Hh + h) * Ll + tid + j * 256] = lg[j] * inv;
}

// ---------------------------------------------------------------------------
// Attention: 128-row tiles, 256 threads (8 warps x 16 rows), fp16.
// QK: Q 2-split x K-hi (64 mma). PV: P-hi x V-hi (32 mma).
// Full double-buffered stages (short+K+V+mask in ONE group each).
// ---------------------------------------------------------------------------
#define LS 68
#define STAGE_F 13376   // floats: SBuf 128*68=8704 | K 2304 | V 2304 | mask 64
#define ATTN_SMEM (2 * STAGE_F * 4)

__global__ __launch_bounds__(256, 2) void attn_mma_kernel(
    const float* __restrict__ query, const float* __restrict__ shortb,
    const int* __restrict__ mask, const float* __restrict__ bias_m,
    float* __restrict__ out)
{
    extern __shared__ float smb[];

    const int tid = threadIdx.x;
    const int w = tid >> 5, lane = tid & 31;
    const int g = lane >> 2, t = lane & 3;
    const int rw = w * 16;
    const int m0 = blockIdx.x * 128;
    const int h = blockIdx.y, b = blockIdx.z;
    const size_t bh = (size_t)b * Hh + h;
    const float* sp = shortb + (bh * Ll + m0) * Ll;

    const int lm = lane >> 3, lr = lane & 7;
    const int loffB = ((lm >> 1) * 8 + lr) * 36 + (lm & 1) * 4;

    const int rS = tid >> 2, sS = (tid & 3) * 8;   // K/V staging: 64 rows x 32 u32

    auto stageA = [&](int n0, int bi) {
        float* SB = smb + bi * STAGE_F;
        uint32_t* K = (uint32_t*)(SB + 8704);
        uint32_t* V = K + 2304;
        int* M = (int*)(V + 2304);
        #pragma unroll
        for (int it = 0; it < 8; it++) {
            int lin = tid + it * 256, row = lin >> 4, c4 = (lin & 15) * 4;
            CP16(s2u(&SB[row * LS + c4]), &sp[(size_t)row * Ll + n0 + c4]);
        }
        const uint32_t* skh = &g_kh[(bh * Ll + n0 + rS) * 32 + sS];
        const uint32_t* svh = &g_vth[(bh * 64 + rS) * 1024 + (n0 >> 1) + sS];
        CP16(s2u(&K[rS*36 + sS]),     skh);
        CP16(s2u(&K[rS*36 + sS + 4]), skh + 4);
        CP16(s2u(&V[rS*36 + sS]),     svh);
        CP16(s2u(&V[rS*36 + sS + 4]), svh + 4);
        if (tid < 16) CP16(s2u(&M[tid * 4]), &mask[b * Ll + n0 + tid * 4]);
        CPCOMMIT();
    };

    // ---- Q fragments from pre-split globals ----
    uint32_t qh[16], ql[16];
    {
        const uint32_t* qhp  = &g_qh[(bh * Ll + m0 + rw + g) * 32];
        const uint32_t* qhp8 = qhp + 8 * 32;
        const uint32_t* qlp  = &g_ql[(bh * Ll + m0 + rw + g) * 32];
        const uint32_t* qlp8 = qlp + 8 * 32;
        #pragma unroll
        for (int j = 0; j < 4; j++) {
            qh[j*4 + 0] = qhp [8*j + t];
            qh[j*4 + 1] = qhp8[8*j + t];
            qh[j*4 + 2] = qhp [8*j + t + 4];
            qh[j*4 + 3] = qhp8[8*j + t + 4];
            ql[j*4 + 0] = qlp [8*j + t];
            ql[j*4 + 1] = qlp8[8*j + t];
            ql[j*4 + 2] = qlp [8*j + t + 4];
            ql[j*4 + 3] = qlp8[8*j + t + 4];
        }
    }

    // prologue: stages 0 and 1 in flight
    stageA(0, 0);
    stageA(64, 1);
    CPWAIT1();
    __syncthreads();

    float accO[8][4] = {};
    float mrow[2] = {-1e30f, -1e30f};
    float lrow[2] = {0.0f, 0.0f};

    #pragma unroll 1
    for (int nb = 0; nb < 32; nb++) {
        const int bi = nb & 1;
        float* SB = smb + bi * STAGE_F;
        const float* SBw = SB + rw * LS;
        uint32_t kbase = s2u(SB + 8704) + loffB * 4;
        uint32_t vbase = kbase + 2304 * 4;
        const int* Mc = (const int*)(SB + 8704 + 4608);

        // ---- S = Q K^T (Q 2-split x K-hi) ----
        float s[8][4] = {};
        #pragma unroll
        for (int j = 0; j < 4; j++) {
            #pragma unroll
            for (int p = 0; p < 4; p++) {
                uint32_t kh0, kh1, kh2, kh3;
                LDSM4(kh0, kh1, kh2, kh3, kbase + (p*576 + j*8)*4);
                mma16(s[2*p],   qh[j*4], qh[j*4+1], qh[j*4+2], qh[j*4+3], kh0, kh1);
                mma16(s[2*p],   ql[j*4], ql[j*4+1], ql[j*4+2], ql[j*4+3], kh0, kh1);
                mma16(s[2*p+1], qh[j*4], qh[j*4+1], qh[j*4+2], qh[j*4+3], kh2, kh3);
                mma16(s[2*p+1], ql[j*4], ql[j*4+1], ql[j*4+2], ql[j*4+3], kh2, kh3);
            }
        }

        // ---- scale, mask, +short ----
        #pragma unroll
        for (int jn = 0; jn < 8; jn++) {
            int c0 = jn * 8 + 2 * t;
            int2 mk = *(const int2*)&Mc[c0];
            float2 sh0 = *(const float2*)&SBw[(g)     * LS + c0];
            float2 sh1 = *(const float2*)&SBw[(g + 8) * LS + c0];
            s[jn][0] = (mk.x ? s[jn][0] * 0.125f : NEGV) + sh0.x;
            s[jn][1] = (mk.y ? s[jn][1] * 0.125f : NEGV) + sh0.y;
            s[jn][2] = (mk.x ? s[jn][2] * 0.125f : NEGV) + sh1.x;
            s[jn][3] = (mk.y ? s[jn][3] * 0.125f : NEGV) + sh1.y;
        }

        // ---- online softmax ----
        #pragma unroll
        for (int half = 0; half < 2; half++) {
            const int r0 = half * 2;
            float tm = -1e30f;
            #pragma unroll
            for (int jn = 0; jn < 8; jn++)
                tm = fmaxf(tm, fmaxf(s[jn][r0], s[jn][r0 + 1]));
            tm = fmaxf(tm, __shfl_xor_sync(0xffffffffu, tm, 1));
            tm = fmaxf(tm, __shfl_xor_sync(0xffffffffu, tm, 2));
            float mn = fmaxf(mrow[half], tm);
            float sc = __expf(mrow[half] - mn);
            float ps = 0.0f;
            #pragma unroll
            for (int jn = 0; jn < 8; jn++) {
                s[jn][r0]     = __expf(s[jn][r0]     - mn);
                s[jn][r0 + 1] = __expf(s[jn][r0 + 1] - mn);
                ps += s[jn][r0] + s[jn][r0 + 1];
            }
            ps += __shfl_xor_sync(0xffffffffu, ps, 1);
            ps += __shfl_xor_sync(0xffffffffu, ps, 2);
            lrow[half] = lrow[half] * sc + ps;
            mrow[half] = mn;
            #pragma unroll
            for (int jd = 0; jd < 8; jd++) {
                accO[jd][r0]     *= sc;
                accO[jd][r0 + 1] *= sc;
            }
        }

        // ---- accO += P V (P-hi only x V-hi) ----
        #pragma unroll
        for (int j = 0; j < 4; j++) {
            uint32_t ph0 = pack2(s[2*j][0],   s[2*j][1]);
            uint32_t ph1 = pack2(s[2*j][2],   s[2*j][3]);
            uint32_t ph2 = pack2(s[2*j+1][0], s[2*j+1][1]);
            uint32_t ph3 = pack2(s[2*j+1][2], s[2*j+1][3]);
            #pragma unroll
            for (int p = 0; p < 4; p++) {
                uint32_t vh0, vh1, vh2, vh3;
                LDSM4(vh0, vh1, vh2, vh3, vbase + (p*576 + j*8)*4);
                mma16(accO[2*p],   ph0, ph1, ph2, ph3, vh0, vh1);
                mma16(accO[2*p+1], ph0, ph1, ph2, ph3, vh2, vh3);
            }
        }

        // ---- rotate buffers ----
        __syncthreads();
        if (nb < 31) {
            int n2 = (nb + 2 < 32 ? nb + 2 : 31) * 64;
            stageA(n2, bi);
            CPWAIT1();
            __syncthreads();
        }
    }

    // ---- fused epilogue ----
    const float bm = bias_m[0];
    #pragma unroll
    for (int half = 0; half < 2; half++) {
        const int r0 = half * 2;
        int row = m0 + rw + g + half * 8;
        float piv = g_pi[bh * Ll + row] * 0.2f;
        float inv = 0.8f / lrow[half];
        #pragma unroll
        for (int jd = 0; jd < 8; jd++) {
            int c = jd * 8 + 2 * t;
            float2 sq = *(const float2*)&query[((size_t)b * Ll + row) * Dd + h * DK + c];
            float2 o;
            o.x = accO[jd][r0]     * inv + piv * sq.x + bm;
            o.y = accO[jd][r0 + 1] * inv + piv * sq.y + bm;
            *(float2*)&out[(bh * Ll + row) * DK + c] = o;
        }
    }
}

// ---------------------------------------------------------------------------
extern "C" void kernel_launch(void* const* d_in, const int* in_sizes, int n_in,
                              void* d_out, int out_size)
{
    const float* query  = (const float*)d_in[0];
    const float* key    = (const float*)d_in[1];
    const float* shortb = (const float*)d_in[2];
    const int*   mask   = (const int*)d_in[4];
    const float* Wq     = (const float*)d_in[5];
    const float* bq     = (const float*)d_in[6];
    const float* Wk     = (const float*)d_in[7];
    const float* bk     = (const float*)d_in[8];
    const float* w_mu   = (const float*)d_in[9];
    const float* b_mu   = (const float*)d_in[10];
    const float* bias_m = (const float*)d_in[11];
    float* out = (float*)d_out;

    cudaFuncSetAttribute(proj_mma_kernel, cudaFuncAttributeMaxDynamicSharedMemorySize, PROJ_SMEM);
    cudaFuncSetAttribute(attn_mma_kernel, cudaFuncAttributeMaxDynamicSharedMemorySize, ATTN_SMEM);

    prep_w_kernel<<<2304, 256>>>(Wq, Wk);
    prep_a_kernel<<<12288, 256>>>(query, key);
    prep_v_kernel<<<dim3(32, 24), 256>>>(query);
    proj_mma_kernel<<<dim3(32, 6, 2), 256, PROJ_SMEM>>>(bq, bk);
    mu_kernel<<<dim3(12, 2), 256>>>(query, mask, w_mu, b_mu);
    attn_mma_kernel<<<dim3(16, 12, 2), 256, ATTN_SMEM>>>(query, shortb, mask, bias_m, out);
}

// round 11
// speedup vs baseline: 3.5862x; 1.0005x over previous
#include <cuda_runtime.h>
#include <cuda_fp16.h>
#include <cstdint>

#define Bb 2
#define Hh 12
#define Ll 2048
#define Dd 768
#define DK 64
#define NEGV (-1000000000.0f)

// ---------------------------------------------------------------------------
// global scratch (pre-split half2; 2-split: B-side hi only)
// ---------------------------------------------------------------------------
__device__ uint32_t g_qh[Bb*Hh*Ll*32], g_ql[Bb*Hh*Ll*32];   // proj q out [bh*L+l][k2]
__device__ uint32_t g_kh[Bb*Hh*Ll*32];                      // proj k out (hi only)
__device__ uint32_t g_wh[2][Hh*64*384];                     // [qk][h*64+n][k2] hi only
__device__ uint32_t g_ah[2][4096*384], g_al[2][4096*384];   // [qk][row][k2]
__device__ uint32_t g_vth[Bb*Hh*64*1024];                   // [bh*64+d][n2] hi only
__device__ float g_pi[Bb*Hh*Ll];

// ---------------------------------------------------------------------------
// helpers
// ---------------------------------------------------------------------------
__device__ __forceinline__ void split2(float x, float y, uint32_t& h, uint32_t& l) {
    __half2 hh = __floats2half2_rn(x, y);
    float rx = x - __low2float(hh);
    float ry = y - __high2float(hh);
    __half2 ll = __floats2half2_rn(rx, ry);
    h = *(uint32_t*)&hh;
    l = *(uint32_t*)&ll;
}
__device__ __forceinline__ uint32_t pack2(float x, float y) {
    __half2 hh = __floats2half2_rn(x, y);
    return *(uint32_t*)&hh;
}

// NOTE: intentionally NOT volatile — pure register op; lets ptxas schedule
// around the ~19-20 cyc HMMA accumulate latency.
__device__ __forceinline__ void mma16(float d[4], uint32_t a0, uint32_t a1, uint32_t a2,
                                      uint32_t a3, uint32_t b0, uint32_t b1) {
    asm("mma.sync.aligned.m16n8k16.row.col.f32.f16.f16.f32 "
        "{%0,%1,%2,%3},{%4,%5,%6,%7},{%8,%9},{%0,%1,%2,%3};\n"
        : "+f"(d[0]), "+f"(d[1]), "+f"(d[2]), "+f"(d[3])
        : "r"(a0), "r"(a1), "r"(a2), "r"(a3), "r"(b0), "r"(b1));
}

__device__ __forceinline__ uint32_t s2u(const void* p) {
    return (uint32_t)__cvta_generic_to_shared(p);
}
#define LDSM4(r0,r1,r2,r3,addr) \
    asm volatile("ldmatrix.sync.aligned.m8n8.x4.shared.b16 {%0,%1,%2,%3}, [%4];" \
                 : "=r"(r0), "=r"(r1), "=r"(r2), "=r"(r3) : "r"(addr))
#define CP16(dst, src) asm volatile("cp.async.cg.shared.global [%0], [%1], 16;\n" :: "r"(dst), "l"(src))
#define CPCOMMIT() asm volatile("cp.async.commit_group;\n" ::: "memory")
#define CPWAIT1()  asm volatile("cp.async.wait_group 1;\n" ::: "memory")
#define CPWAIT0()  asm volatile("cp.async.wait_group 0;\n" ::: "memory")

// ---------------------------------------------------------------------------
// prep kernels
// ---------------------------------------------------------------------------
__global__ __launch_bounds__(256) void prep_w_kernel(
    const float* __restrict__ Wq, const float* __restrict__ Wk)
{
    int idx = blockIdx.x * 256 + threadIdx.x;
    int qk = idx >= (Hh*64*384);
    int r = idx - qk * (Hh*64*384);
    int col = r / 384;
    int k2 = r % 384;
    const float* W = qk ? Wk : Wq;
    g_wh[qk][r] = pack2(W[(size_t)(2*k2) * Dd + col], W[(size_t)(2*k2+1) * Dd + col]);
}

__global__ __launch_bounds__(256) void prep_a_kernel(
    const float* __restrict__ query, const float* __restrict__ key)
{
    int idx = blockIdx.x * 256 + threadIdx.x;
    int qk = idx >= (4096*384);
    int r = idx - qk * (4096*384);
    int row = r / 384;
    int k2  = r % 384;
    const float* src = qk ? key : query;
    float2 f = *(const float2*)&src[(size_t)row * Dd + 2*k2];
    uint32_t hh, ll;
    split2(f.x, f.y, hh, ll);
    g_ah[qk][r] = hh;
    g_al[qk][r] = ll;
}

// V transposed: g_vth[bh*64 + d][n2] = half2(V[2n2][d], V[2n2+1][d])
__global__ __launch_bounds__(256) void prep_v_kernel(const float* __restrict__ query)
{
    __shared__ uint32_t th[64][33];
    const int tile = blockIdx.x;
    const int bh = blockIdx.y;
    const int b = bh / Hh, h = bh % Hh;
    const int n20 = tile * 32;
    const int tid = threadIdx.x;
    #pragma unroll
    for (int i = 0; i < 8; i++) {
        int lin = tid + 256 * i;
        int n2l = lin >> 6;
        int d = lin & 63;
        const float* q0 = &query[(size_t)(b * Ll + 2*(n20 + n2l)) * Dd + h * DK + d];
        th[d][n2l] = pack2(q0[0], q0[Dd]);
    }
    __syncthreads();
    #pragma unroll
    for (int i = 0; i < 8; i++) {
        int lin = tid + 256 * i;
        int d = lin >> 5;
        int n2l = lin & 31;
        g_vth[(size_t)(bh * 64 + d) * 1024 + n20 + n2l] = th[d][n2l];
    }
}

// ---------------------------------------------------------------------------
// Projection GEMM: 128 rows x 128 cols (2 heads) per block, 256 threads,
// fp16 2-split (A hi+lo, W hi), k-tile 64, double-buffered cp.async.
// mma order: hi x4 then lo x4 per W-fragment (RAW separation 3).
// ---------------------------------------------------------------------------
#define PJ_SET 13824   // u32 per stage: Ah 4608 | Al 4608 | Wh 4608
#define PROJ_SMEM (2 * PJ_SET * 4)

__global__ __launch_bounds__(256, 2) void proj_mma_kernel(
    const float* __restrict__ bq, const float* __restrict__ bk)
{
    extern __shared__ uint32_t psm[];
    const int qk = blockIdx.z;
    const int tid = threadIdx.x;
    const int w = tid >> 5, lane = tid & 31, g = lane >> 2, t = lane & 3;
    const int rowg = w >> 1, colg = w & 1;
    const int rb0 = rowg * 32;
    const int row0 = blockIdx.x * 128;
    const int hp = blockIdx.y;

    const uint32_t* Agh = g_ah[qk];
    const uint32_t* Agl = g_al[qk];
    const uint32_t* Wgh = &g_wh[qk][(size_t)hp * 128 * 384];
    const float* bias = qk ? bk : bq;

    const int mA = tid >> 1, kbA = (tid & 1) * 16;

    const int lm = lane >> 3, lr = lane & 7;
    const int loffA = ((lm & 1) * 8 + lr) * 36 + (lm >> 1) * 4;
    const int loffB = ((lm >> 1) * 8 + lr) * 36 + (lm & 1) * 4;

    auto stagep = [&](int kb) {
        uint32_t* S = psm + (kb & 1) * PJ_SET;
        const int koff = kb * 32 + kbA;
        const uint32_t* sa  = &Agh[(size_t)(row0 + mA) * 384 + koff];
        const uint32_t* sal = &Agl[(size_t)(row0 + mA) * 384 + koff];
        const uint32_t* sw  = &Wgh[(size_t)mA * 384 + koff];
        #pragma unroll
        for (int i = 0; i < 4; i++) {
            CP16(s2u(&S[mA*36 + kbA + i*4]),        sa  + i*4);
            CP16(s2u(&S[4608 + mA*36 + kbA + i*4]), sal + i*4);
            CP16(s2u(&S[9216 + mA*36 + kbA + i*4]), sw  + i*4);
        }
        CPCOMMIT();
    };

    stagep(0);
    float acc0[8][4] = {};
    float acc1[8][4] = {};

    #pragma unroll 1
    for (int kb = 0; kb < 12; kb++) {
        if (kb < 11) { stagep(kb + 1); CPWAIT1(); } else { CPWAIT0(); }
        __syncthreads();
        uint32_t sbase = s2u(psm) + ((kb & 1) * PJ_SET) * 4;
        uint32_t a0h = sbase + (rb0*36 + loffA) * 4;
        uint32_t a1h = a0h + 16*36*4;
        uint32_t a0l = a0h + 4608*4;
        uint32_t a1l = a1h + 4608*4;
        uint32_t wb  = sbase + (9216 + colg*64*36 + loffB) * 4;
        #pragma unroll
        for (int j = 0; j < 4; j++) {
            uint32_t p0h0,p0h1,p0h2,p0h3, p1h0,p1h1,p1h2,p1h3;
            uint32_t p0l0,p0l1,p0l2,p0l3, p1l0,p1l1,p1l2,p1l3;
            LDSM4(p0h0,p0h1,p0h2,p0h3, a0h + j*32);
            LDSM4(p1h0,p1h1,p1h2,p1h3, a1h + j*32);
            LDSM4(p0l0,p0l1,p0l2,p0l3, a0l + j*32);
            LDSM4(p1l0,p1l1,p1l2,p1l3, a1l + j*32);
            #pragma unroll
            for (int p = 0; p < 4; p++) {
                uint32_t wh0, wh1, wh2, wh3;
                LDSM4(wh0, wh1, wh2, wh3, wb + (p*576 + j*8)*4);
                // all hi (4 independent accs), then all lo — RAW sep 3
                mma16(acc0[2*p],   p0h0,p0h1,p0h2,p0h3, wh0, wh1);
                mma16(acc0[2*p+1], p0h0,p0h1,p0h2,p0h3, wh2, wh3);
                mma16(acc1[2*p],   p1h0,p1h1,p1h2,p1h3, wh0, wh1);
                mma16(acc1[2*p+1], p1h0,p1h1,p1h2,p1h3, wh2, wh3);
                mma16(acc0[2*p],   p0l0,p0l1,p0l2,p0l3, wh0, wh1);
                mma16(acc0[2*p+1], p0l0,p0l1,p0l2,p0l3, wh2, wh3);
                mma16(acc1[2*p],   p1l0,p1l1,p1l2,p1l3, wh0, wh1);
                mma16(acc1[2*p+1], p1l0,p1l1,p1l2,p1l3, wh2, wh3);
            }
        }
        __syncthreads();
    }

    const int hglob = hp * 2 + colg;
    const float* bp = &bias[hglob * 64];
    #pragma unroll
    for (int rb2 = 0; rb2 < 2; rb2++) {
        float (*acc)[4] = rb2 ? acc1 : acc0;
        #pragma unroll
        for (int half = 0; half < 2; half++) {
            int row = row0 + rb0 + rb2*16 + g + half*8;
            int b_ = row >> 11, l = row & (Ll - 1);
            size_t base = ((size_t)(b_ * Hh + hglob) * Ll + l) * 32;
            #pragma unroll
            for (int jn = 0; jn < 8; jn++) {
                float2 bb = *(const float2*)&bp[jn*8 + 2*t];
                float x = acc[jn][2*half]     + bb.x;
                float y = acc[jn][2*half + 1] + bb.y;
                size_t o = base + jn*4 + t;
                if (qk == 0) {
                    uint32_t hh, llv;
                    split2(x, y, hh, llv);
                    g_qh[o] = hh; g_ql[o] = llv;
                } else {
                    g_kh[o] = pack2(x, y);
                }
            }
        }
    }
}

// ---------------------------------------------------------------------------
// mu (= pi) kernel
// ---------------------------------------------------------------------------
__global__ __launch_bounds__(256) void mu_kernel(
    const float* __restrict__ query, const int* __restrict__ mask,
    const float* __restrict__ w_mu, const float* __restrict__ b_mu)
{
    const int h = blockIdx.x, b = blockIdx.y;
    const int tid = threadIdx.x;
    __shared__ float wmu[64];
    __shared__ float red[8];
    if (tid < 64) wmu[tid] = w_mu[tid];
    __syncthreads();
    const float bmu = b_mu[0];

    float lg[8];
    float lmax = -1e30f;
    #pragma unroll
    for (int j = 0; j < 8; j++) {
        int l = tid + j * 256;
        const float* sp = &query[((size_t)b * Ll + l) * Dd + h * DK];
        float dm = 0.0f;
        #pragma unroll
        for (int d = 0; d < 64; d += 4) {
            float4 s4 = *(const float4*)&sp[d];
            dm += s4.x * wmu[d] + s4.y * wmu[d+1] + s4.z * wmu[d+2] + s4.w * wmu[d+3];
        }
        float v = dm + bmu;
        if (mask[b * Ll + l] == 0) v = NEGV;
        lg[j] = v;
        lmax = fmaxf(lmax, v);
    }
    {
        int wi = tid >> 5, lane = tid & 31;
        #pragma unroll
        for (int o = 16; o; o >>= 1) lmax = fmaxf(lmax, __shfl_xor_sync(~0u, lmax, o));
        if (lane == 0) red[wi] = lmax;
        __syncthreads();
        if (wi == 0) {
            float r = (lane < 8) ? red[lane] : -1e30f;
            #pragma unroll
            for (int o = 16; o; o >>= 1) r = fmaxf(r, __shfl_xor_sync(~0u, r, o));
            if (lane == 0) red[0] = r;
        }
        __syncthreads();
        lmax = red[0];
        __syncthreads();
    }
    float lsum = 0.0f;
    #pragma unroll
    for (int j = 0; j < 8; j++) { lg[j] = __expf(lg[j] - lmax); lsum += lg[j]; }
    {
        int wi = tid >> 5, lane = tid & 31;
        #pragma unroll
        for (int o = 16; o; o >>= 1) lsum += __shfl_xor_sync(~0u, lsum, o);
        if (lane == 0) red[wi] = lsum;
        __syncthreads();
        if (wi == 0) {
            float r = (lane < 8) ? red[lane] : 0.0f;
            #pragma unroll
            for (int o = 16; o; o >>= 1) r += __shfl_xor_sync(~0u, r, o);
            if (lane == 0) red[0] = r;
        }
        __syncthreads();
        lsum = red[0];
    }
    float inv = 1.0f / lsum;
    #pragma unroll
    for (int j = 0; j < 8; j++)
        g_pi[((size_t)b * Hh + h) * Ll + tid + j * 256] = lg[j] * inv;
}

// ---------------------------------------------------------------------------
// Attention: 128-row tiles, 256 threads (8 warps x 16 rows), fp16.
// QK: per j, preload 4 K-frag sets, then 8 hi mmas + 8 lo mmas (RAW sep 8).
// PV: P-hi x V-hi. Full double-buffered stages.
// ---------------------------------------------------------------------------
#define LS 68
#define STAGE_F 13376   // floats: SBuf 128*68=8704 | K 2304 | V 2304 | mask 64
#define ATTN_SMEM (2 * STAGE_F * 4)

__global__ __launch_bounds__(256, 2) void attn_mma_kernel(
    const float* __restrict__ query, const float* __restrict__ shortb,
    const int* __restrict__ mask, const float* __restrict__ bias_m,
    float* __restrict__ out)
{
    extern __shared__ float smb[];

    const int tid = threadIdx.x;
    const int w = tid >> 5, lane = tid & 31;
    const int g = lane >> 2, t = lane & 3;
    const int rw = w * 16;
    const int m0 = blockIdx.x * 128;
    const int h = blockIdx.y, b = blockIdx.z;
    const size_t bh = (size_t)b * Hh + h;
    const float* sp = shortb + (bh * Ll + m0) * Ll;

    const int lm = lane >> 3, lr = lane & 7;
    const int loffB = ((lm >> 1) * 8 + lr) * 36 + (lm & 1) * 4;

    const int rS = tid >> 2, sS = (tid & 3) * 8;

    auto stageA = [&](int n0, int bi) {
        float* SB = smb + bi * STAGE_F;
        uint32_t* K = (uint32_t*)(SB + 8704);
        uint32_t* V = K + 2304;
        int* M = (int*)(V + 2304);
        #pragma unroll
        for (int it = 0; it < 8; it++) {
            int lin = tid + it * 256, row = lin >> 4, c4 = (lin & 15) * 4;
            CP16(s2u(&SB[row * LS + c4]), &sp[(size_t)row * Ll + n0 + c4]);
        }
        const uint32_t* skh = &g_kh[(bh * Ll + n0 + rS) * 32 + sS];
        const uint32_t* svh = &g_vth[(bh * 64 + rS) * 1024 + (n0 >> 1) + sS];
        CP16(s2u(&K[rS*36 + sS]),     skh);
        CP16(s2u(&K[rS*36 + sS + 4]), skh + 4);
        CP16(s2u(&V[rS*36 + sS]),     svh);
        CP16(s2u(&V[rS*36 + sS + 4]), svh + 4);
        if (tid < 16) CP16(s2u(&M[tid * 4]), &mask[b * Ll + n0 + tid * 4]);
        CPCOMMIT();
    };

    // ---- Q fragments from pre-split globals ----
    uint32_t qh[16], ql[16];
    {
        const uint32_t* qhp  = &g_qh[(bh * Ll + m0 + rw + g) * 32];
        const uint32_t* qhp8 = qhp + 8 * 32;
        const uint32_t* qlp  = &g_ql[(bh * Ll + m0 + rw + g) * 32];
        const uint32_t* qlp8 = qlp + 8 * 32;
        #pragma unroll
        for (int j = 0; j < 4; j++) {
            qh[j*4 + 0] = qhp [8*j + t];
            qh[j*4 + 1] = qhp8[8*j + t];
            qh[j*4 + 2] = qhp [8*j + t + 4];
            qh[j*4 + 3] = qhp8[8*j + t + 4];
            ql[j*4 + 0] = qlp [8*j + t];
            ql[j*4 + 1] = qlp8[8*j + t];
            ql[j*4 + 2] = qlp [8*j + t + 4];
            ql[j*4 + 3] = qlp8[8*j + t + 4];
        }
    }

    stageA(0, 0);
    stageA(64, 1);
    CPWAIT1();
    __syncthreads();

    float accO[8][4] = {};
    float mrow[2] = {-1e30f, -1e30f};
    float lrow[2] = {0.0f, 0.0f};

    #pragma unroll 1
    for (int nb = 0; nb < 32; nb++) {
        const int bi = nb & 1;
        float* SB = smb + bi * STAGE_F;
        const float* SBw = SB + rw * LS;
        uint32_t kbase = s2u(SB + 8704) + loffB * 4;
        uint32_t vbase = kbase + 2304 * 4;
        const int* Mc = (const int*)(SB + 8704 + 4608);

        // ---- S = Q K^T: 8 independent hi mmas, then 8 lo (RAW sep 8) ----
        float s[8][4] = {};
        #pragma unroll
        for (int j = 0; j < 4; j++) {
            uint32_t kf[16];
            #pragma unroll
            for (int p = 0; p < 4; p++)
                LDSM4(kf[p*4], kf[p*4+1], kf[p*4+2], kf[p*4+3],
                      kbase + (p*576 + j*8)*4);
            #pragma unroll
            for (int p = 0; p < 4; p++) {
                mma16(s[2*p],   qh[j*4], qh[j*4+1], qh[j*4+2], qh[j*4+3], kf[p*4],   kf[p*4+1]);
                mma16(s[2*p+1], qh[j*4], qh[j*4+1], qh[j*4+2], qh[j*4+3], kf[p*4+2], kf[p*4+3]);
            }
            #pragma unroll
            for (int p = 0; p < 4; p++) {
                mma16(s[2*p],   ql[j*4], ql[j*4+1], ql[j*4+2], ql[j*4+3], kf[p*4],   kf[p*4+1]);
                mma16(s[2*p+1], ql[j*4], ql[j*4+1], ql[j*4+2], ql[j*4+3], kf[p*4+2], kf[p*4+3]);
            }
        }

        // ---- scale, mask, +short ----
        #pragma unroll
        for (int jn = 0; jn < 8; jn++) {
            int c0 = jn * 8 + 2 * t;
            int2 mk = *(const int2*)&Mc[c0];
            float2 sh0 = *(const float2*)&SBw[(g)     * LS + c0];
            float2 sh1 = *(const float2*)&SBw[(g + 8) * LS + c0];
            s[jn][0] = (mk.x ? s[jn][0] * 0.125f : NEGV) + sh0.x;
            s[jn][1] = (mk.y ? s[jn][1] * 0.125f : NEGV) + sh0.y;
            s[jn][2] = (mk.x ? s[jn][2] * 0.125f : NEGV) + sh1.x;
            s[jn][3] = (mk.y ? s[jn][3] * 0.125f : NEGV) + sh1.y;
        }

        // ---- online softmax ----
        #pragma unroll
        for (int half = 0; half < 2; half++) {
            const int r0 = half * 2;
            float tm = -1e30f;
            #pragma unroll
            for (int jn = 0; jn < 8; jn++)
                tm = fmaxf(tm, fmaxf(s[jn][r0], s[jn][r0 + 1]));
            tm = fmaxf(tm, __shfl_xor_sync(0xffffffffu, tm, 1));
            tm = fmaxf(tm, __shfl_xor_sync(0xffffffffu, tm, 2));
            float mn = fmaxf(mrow[half], tm);
            float sc = __expf(mrow[half] - mn);
            float ps = 0.0f;
            #pragma unroll
            for (int jn = 0; jn < 8; jn++) {
                s[jn][r0]     = __expf(s[jn][r0]     - mn);
                s[jn][r0 + 1] = __expf(s[jn][r0 + 1] - mn);
                ps += s[jn][r0] + s[jn][r0 + 1];
            }
            ps += __shfl_xor_sync(0xffffffffu, ps, 1);
            ps += __shfl_xor_sync(0xffffffffu, ps, 2);
            lrow[half] = lrow[half] * sc + ps;
            mrow[half] = mn;
            #pragma unroll
            for (int jd = 0; jd < 8; jd++) {
                accO[jd][r0]     *= sc;
                accO[jd][r0 + 1] *= sc;
            }
        }

        // ---- accO += P V (P-hi x V-hi; 8 independent accs per j) ----
        #pragma unroll
        for (int j = 0; j < 4; j++) {
            uint32_t ph0 = pack2(s[2*j][0],   s[2*j][1]);
            uint32_t ph1 = pack2(s[2*j][2],   s[2*j][3]);
            uint32_t ph2 = pack2(s[2*j+1][0], s[2*j+1][1]);
            uint32_t ph3 = pack2(s[2*j+1][2], s[2*j+1][3]);
            #pragma unroll
            for (int p = 0; p < 4; p++) {
                uint32_t vh0, vh1, vh2, vh3;
                LDSM4(vh0, vh1, vh2, vh3, vbase + (p*576 + j*8)*4);
                mma16(accO[2*p],   ph0, ph1, ph2, ph3, vh0, vh1);
                mma16(accO[2*p+1], ph0, ph1, ph2, ph3, vh2, vh3);
            }
        }

        // ---- rotate buffers ----
        __syncthreads();
        if (nb < 31) {
            int n2 = (nb + 2 < 32 ? nb + 2 : 31) * 64;
            stageA(n2, bi);
            CPWAIT1();
            __syncthreads();
        }
    }

    // ---- fused epilogue ----
    const float bm = bias_m[0];
    #pragma unroll
    for (int half = 0; half < 2; half++) {
        const int r0 = half * 2;
        int row = m0 + rw + g + half * 8;
        float piv = g_pi[bh * Ll + row] * 0.2f;
        float inv = 0.8f / lrow[half];
        #pragma unroll
        for (int jd = 0; jd < 8; jd++) {
            int c = jd * 8 + 2 * t;
            float2 sq = *(const float2*)&query[((size_t)b * Ll + row) * Dd + h * DK + c];
            float2 o;
            o.x = accO[jd][r0]     * inv + piv * sq.x + bm;
            o.y = accO[jd][r0 + 1] * inv + piv * sq.y + bm;
            *(float2*)&out[(bh * Ll + row) * DK + c] = o;
        }
    }
}

// ---------------------------------------------------------------------------
extern "C" void kernel_launch(void* const* d_in, const int* in_sizes, int n_in,
                              void* d_out, int out_size)
{
    const float* query  = (const float*)d_in[0];
    const float* key    = (const float*)d_in[1];
    const float* shortb = (const float*)d_in[2];
    const int*   mask   = (const int*)d_in[4];
    const float* Wq     = (const float*)d_in[5];
    const float* bq     = (const float*)d_in[6];
    const float* Wk     = (const float*)d_in[7];
    const float* bk     = (const float*)d_in[8];
    const float* w_mu   = (const float*)d_in[9];
    const float* b_mu   = (const float*)d_in[10];
    const float* bias_m = (const float*)d_in[11];
    float* out = (float*)d_out;

    cudaFuncSetAttribute(proj_mma_kernel, cudaFuncAttributeMaxDynamicSharedMemorySize, PROJ_SMEM);
    cudaFuncSetAttribute(attn_mma_kernel, cudaFuncAttributeMaxDynamicSharedMemorySize, ATTN_SMEM);

    prep_w_kernel<<<2304, 256>>>(Wq, Wk);
    prep_a_kernel<<<12288, 256>>>(query, key);
    prep_v_kernel<<<dim3(32, 24), 256>>>(query);
    proj_mma_kernel<<<dim3(32, 6, 2), 256, PROJ_SMEM>>>(bq, bk);
    mu_kernel<<<dim3(12, 2), 256>>>(query, mask, w_mu, b_mu);
    attn_mma_kernel<<<dim3(16, 12, 2), 256, ATTN_SMEM>>>(query, shortb, mask, bias_m, out);
}

// round 12
// speedup vs baseline: 4.0949x; 1.1419x over previous
#include <cuda_runtime.h>
#include <cuda_fp16.h>
#include <cstdint>

#define Bb 2
#define Hh 12
#define Ll 2048
#define Dd 768
#define DK 64
#define NEGV (-1000000000.0f)

// ---------------------------------------------------------------------------
// global scratch (pre-split half2; QK consumes hi planes only)
// ---------------------------------------------------------------------------
__device__ uint32_t g_qh[Bb*Hh*Ll*32];                      // proj q out (hi only)
__device__ uint32_t g_kh[Bb*Hh*Ll*32];                      // proj k out (hi only)
__device__ uint32_t g_wh[2][Hh*64*384];                     // [qk][h*64+n][k2] hi only
__device__ uint32_t g_ah[2][4096*384], g_al[2][4096*384];   // [qk][row][k2]
__device__ uint32_t g_vth[Bb*Hh*64*1024];                   // [bh*64+d][n2] hi only
__device__ float g_pi[Bb*Hh*Ll];

// ---------------------------------------------------------------------------
// helpers
// ---------------------------------------------------------------------------
__device__ __forceinline__ void split2(float x, float y, uint32_t& h, uint32_t& l) {
    __half2 hh = __floats2half2_rn(x, y);
    float rx = x - __low2float(hh);
    float ry = y - __high2float(hh);
    __half2 ll = __floats2half2_rn(rx, ry);
    h = *(uint32_t*)&hh;
    l = *(uint32_t*)&ll;
}
__device__ __forceinline__ uint32_t pack2(float x, float y) {
    __half2 hh = __floats2half2_rn(x, y);
    return *(uint32_t*)&hh;
}

__device__ __forceinline__ void mma16(float d[4], uint32_t a0, uint32_t a1, uint32_t a2,
                                      uint32_t a3, uint32_t b0, uint32_t b1) {
    asm("mma.sync.aligned.m16n8k16.row.col.f32.f16.f16.f32 "
        "{%0,%1,%2,%3},{%4,%5,%6,%7},{%8,%9},{%0,%1,%2,%3};\n"
        : "+f"(d[0]), "+f"(d[1]), "+f"(d[2]), "+f"(d[3])
        : "r"(a0), "r"(a1), "r"(a2), "r"(a3), "r"(b0), "r"(b1));
}

__device__ __forceinline__ uint32_t s2u(const void* p) {
    return (uint32_t)__cvta_generic_to_shared(p);
}
#define LDSM4(r0,r1,r2,r3,addr) \
    asm volatile("ldmatrix.sync.aligned.m8n8.x4.shared.b16 {%0,%1,%2,%3}, [%4];" \
                 : "=r"(r0), "=r"(r1), "=r"(r2), "=r"(r3) : "r"(addr))
#define CP16(dst, src) asm volatile("cp.async.cg.shared.global [%0], [%1], 16;\n" :: "r"(dst), "l"(src))
#define CPCOMMIT() asm volatile("cp.async.commit_group;\n" ::: "memory")
#define CPWAIT1()  asm volatile("cp.async.wait_group 1;\n" ::: "memory")
#define CPWAIT0()  asm volatile("cp.async.wait_group 0;\n" ::: "memory")

// ---------------------------------------------------------------------------
// prep kernels
// ---------------------------------------------------------------------------
__global__ __launch_bounds__(256) void prep_w_kernel(
    const float* __restrict__ Wq, const float* __restrict__ Wk)
{
    int idx = blockIdx.x * 256 + threadIdx.x;
    int qk = idx >= (Hh*64*384);
    int r = idx - qk * (Hh*64*384);
    int col = r / 384;
    int k2 = r % 384;
    const float* W = qk ? Wk : Wq;
    g_wh[qk][r] = pack2(W[(size_t)(2*k2) * Dd + col], W[(size_t)(2*k2+1) * Dd + col]);
}

__global__ __launch_bounds__(256) void prep_a_kernel(
    const float* __restrict__ query, const float* __restrict__ key)
{
    int idx = blockIdx.x * 256 + threadIdx.x;
    int qk = idx >= (4096*384);
    int r = idx - qk * (4096*384);
    int row = r / 384;
    int k2  = r % 384;
    const float* src = qk ? key : query;
    float2 f = *(const float2*)&src[(size_t)row * Dd + 2*k2];
    uint32_t hh, ll;
    split2(f.x, f.y, hh, ll);
    g_ah[qk][r] = hh;
    g_al[qk][r] = ll;
}

// V transposed: g_vth[bh*64 + d][n2] = half2(V[2n2][d], V[2n2+1][d])
__global__ __launch_bounds__(256) void prep_v_kernel(const float* __restrict__ query)
{
    __shared__ uint32_t th[64][33];
    const int tile = blockIdx.x;
    const int bh = blockIdx.y;
    const int b = bh / Hh, h = bh % Hh;
    const int n20 = tile * 32;
    const int tid = threadIdx.x;
    #pragma unroll
    for (int i = 0; i < 8; i++) {
        int lin = tid + 256 * i;
        int n2l = lin >> 6;
        int d = lin & 63;
        const float* q0 = &query[(size_t)(b * Ll + 2*(n20 + n2l)) * Dd + h * DK + d];
        th[d][n2l] = pack2(q0[0], q0[Dd]);
    }
    __syncthreads();
    #pragma unroll
    for (int i = 0; i < 8; i++) {
        int lin = tid + 256 * i;
        int d = lin >> 5;
        int n2l = lin & 31;
        g_vth[(size_t)(bh * 64 + d) * 1024 + n20 + n2l] = th[d][n2l];
    }
}

// ---------------------------------------------------------------------------
// Projection GEMM: 128 rows x 128 cols (2 heads) per block, 256 threads,
// fp16 2-split (A hi+lo, W hi), k-tile 64, double-buffered cp.async.
// ---------------------------------------------------------------------------
#define PJ_SET 13824   // u32 per stage: Ah 4608 | Al 4608 | Wh 4608
#define PROJ_SMEM (2 * PJ_SET * 4)

__global__ __launch_bounds__(256, 2) void proj_mma_kernel(
    const float* __restrict__ bq, const float* __restrict__ bk)
{
    extern __shared__ uint32_t psm[];
    const int qk = blockIdx.z;
    const int tid = threadIdx.x;
    const int w = tid >> 5, lane = tid & 31, g = lane >> 2, t = lane & 3;
    const int rowg = w >> 1, colg = w & 1;
    const int rb0 = rowg * 32;
    const int row0 = blockIdx.x * 128;
    const int hp = blockIdx.y;

    const uint32_t* Agh = g_ah[qk];
    const uint32_t* Agl = g_al[qk];
    const uint32_t* Wgh = &g_wh[qk][(size_t)hp * 128 * 384];
    const float* bias = qk ? bk : bq;

    const int mA = tid >> 1, kbA = (tid & 1) * 16;

    const int lm = lane >> 3, lr = lane & 7;
    const int loffA = ((lm & 1) * 8 + lr) * 36 + (lm >> 1) * 4;
    const int loffB = ((lm >> 1) * 8 + lr) * 36 + (lm & 1) * 4;

    auto stagep = [&](int kb) {
        uint32_t* S = psm + (kb & 1) * PJ_SET;
        const int koff = kb * 32 + kbA;
        const uint32_t* sa  = &Agh[(size_t)(row0 + mA) * 384 + koff];
        const uint32_t* sal = &Agl[(size_t)(row0 + mA) * 384 + koff];
        const uint32_t* sw  = &Wgh[(size_t)mA * 384 + koff];
        #pragma unroll
        for (int i = 0; i < 4; i++) {
            CP16(s2u(&S[mA*36 + kbA + i*4]),        sa  + i*4);
            CP16(s2u(&S[4608 + mA*36 + kbA + i*4]), sal + i*4);
            CP16(s2u(&S[9216 + mA*36 + kbA + i*4]), sw  + i*4);
        }
        CPCOMMIT();
    };

    stagep(0);
    float acc0[8][4] = {};
    float acc1[8][4] = {};

    #pragma unroll 1
    for (int kb = 0; kb < 12; kb++) {
        if (kb < 11) { stagep(kb + 1); CPWAIT1(); } else { CPWAIT0(); }
        __syncthreads();
        uint32_t sbase = s2u(psm) + ((kb & 1) * PJ_SET) * 4;
        uint32_t a0h = sbase + (rb0*36 + loffA) * 4;
        uint32_t a1h = a0h + 16*36*4;
        uint32_t a0l = a0h + 4608*4;
        uint32_t a1l = a1h + 4608*4;
        uint32_t wb  = sbase + (9216 + colg*64*36 + loffB) * 4;
        #pragma unroll
        for (int j = 0; j < 4; j++) {
            uint32_t p0h0,p0h1,p0h2,p0h3, p1h0,p1h1,p1h2,p1h3;
            uint32_t p0l0,p0l1,p0l2,p0l3, p1l0,p1l1,p1l2,p1l3;
            LDSM4(p0h0,p0h1,p0h2,p0h3, a0h + j*32);
            LDSM4(p1h0,p1h1,p1h2,p1h3, a1h + j*32);
            LDSM4(p0l0,p0l1,p0l2,p0l3, a0l + j*32);
            LDSM4(p1l0,p1l1,p1l2,p1l3, a1l + j*32);
            #pragma unroll
            for (int p = 0; p < 4; p++) {
                uint32_t wh0, wh1, wh2, wh3;
                LDSM4(wh0, wh1, wh2, wh3, wb + (p*576 + j*8)*4);
                mma16(acc0[2*p],   p0h0,p0h1,p0h2,p0h3, wh0, wh1);
                mma16(acc0[2*p+1], p0h0,p0h1,p0h2,p0h3, wh2, wh3);
                mma16(acc1[2*p],   p1h0,p1h1,p1h2,p1h3, wh0, wh1);
                mma16(acc1[2*p+1], p1h0,p1h1,p1h2,p1h3, wh2, wh3);
                mma16(acc0[2*p],   p0l0,p0l1,p0l2,p0l3, wh0, wh1);
                mma16(acc0[2*p+1], p0l0,p0l1,p0l2,p0l3, wh2, wh3);
                mma16(acc1[2*p],   p1l0,p1l1,p1l2,p1l3, wh0, wh1);
                mma16(acc1[2*p+1], p1l0,p1l1,p1l2,p1l3, wh2, wh3);
            }
        }
        __syncthreads();
    }

    const int hglob = hp * 2 + colg;
    const float* bp = &bias[hglob * 64];
    uint32_t* outp = qk ? g_kh : g_qh;
    #pragma unroll
    for (int rb2 = 0; rb2 < 2; rb2++) {
        float (*acc)[4] = rb2 ? acc1 : acc0;
        #pragma unroll
        for (int half = 0; half < 2; half++) {
            int row = row0 + rb0 + rb2*16 + g + half*8;
            int b_ = row >> 11, l = row & (Ll - 1);
            size_t base = ((size_t)(b_ * Hh + hglob) * Ll + l) * 32;
            #pragma unroll
            for (int jn = 0; jn < 8; jn++) {
                float2 bb = *(const float2*)&bp[jn*8 + 2*t];
                outp[base + jn*4 + t] =
                    pack2(acc[jn][2*half] + bb.x, acc[jn][2*half + 1] + bb.y);
            }
        }
    }
}

// ---------------------------------------------------------------------------
// mu (= pi) kernel
// ---------------------------------------------------------------------------
__global__ __launch_bounds__(256) void mu_kernel(
    const float* __restrict__ query, const int* __restrict__ mask,
    const float* __restrict__ w_mu, const float* __restrict__ b_mu)
{
    const int h = blockIdx.x, b = blockIdx.y;
    const int tid = threadIdx.x;
    __shared__ float wmu[64];
    __shared__ float red[8];
    if (tid < 64) wmu[tid] = w_mu[tid];
    __syncthreads();
    const float bmu = b_mu[0];

    float lg[8];
    float lmax = -1e30f;
    #pragma unroll
    for (int j = 0; j < 8; j++) {
        int l = tid + j * 256;
        const float* sp = &query[((size_t)b * Ll + l) * Dd + h * DK];
        float dm = 0.0f;
        #pragma unroll
        for (int d = 0; d < 64; d += 4) {
            float4 s4 = *(const float4*)&sp[d];
            dm += s4.x * wmu[d] + s4.y * wmu[d+1] + s4.z * wmu[d+2] + s4.w * wmu[d+3];
        }
        float v = dm + bmu;
        if (mask[b * Ll + l] == 0) v = NEGV;
        lg[j] = v;
        lmax = fmaxf(lmax, v);
    }
    {
        int wi = tid >> 5, lane = tid & 31;
        #pragma unroll
        for (int o = 16; o; o >>= 1) lmax = fmaxf(lmax, __shfl_xor_sync(~0u, lmax, o));
        if (lane == 0) red[wi] = lmax;
        __syncthreads();
        if (wi == 0) {
            float r = (lane < 8) ? red[lane] : -1e30f;
            #pragma unroll
            for (int o = 16; o; o >>= 1) r = fmaxf(r, __shfl_xor_sync(~0u, r, o));
            if (lane == 0) red[0] = r;
        }
        __syncthreads();
        lmax = red[0];
        __syncthreads();
    }
    float lsum = 0.0f;
    #pragma unroll
    for (int j = 0; j < 8; j++) { lg[j] = __expf(lg[j] - lmax); lsum += lg[j]; }
    {
        int wi = tid >> 5, lane = tid & 31;
        #pragma unroll
        for (int o = 16; o; o >>= 1) lsum += __shfl_xor_sync(~0u, lsum, o);
        if (lane == 0) red[wi] = lsum;
        __syncthreads();
        if (wi == 0) {
            float r = (lane < 8) ? red[lane] : 0.0f;
            #pragma unroll
            for (int o = 16; o; o >>= 1) r += __shfl_xor_sync(~0u, r, o);
            if (lane == 0) red[0] = r;
        }
        __syncthreads();
        lsum = red[0];
    }
    float inv = 1.0f / lsum;
    #pragma unroll
    for (int j = 0; j < 8; j++)
        g_pi[((size_t)b * Hh + h) * Ll + tid + j * 256] = lg[j] * inv;
}

// ---------------------------------------------------------------------------
// Attention: 128-row tiles, 256 threads (8 warps x 16 rows), fp16.
// QK: Q-hi x K-hi (32 mma). PV: P-hi x V-hi (32 mma). Double-buffered stages.
// ---------------------------------------------------------------------------
#define LS 68
#define STAGE_F 13376   // floats: SBuf 128*68=8704 | K 2304 | V 2304 | mask 64
#define ATTN_SMEM (2 * STAGE_F * 4)

__global__ __launch_bounds__(256, 2) void attn_mma_kernel(
    const float* __restrict__ query, const float* __restrict__ shortb,
    const int* __restrict__ mask, const float* __restrict__ bias_m,
    float* __restrict__ out)
{
    extern __shared__ float smb[];

    const int tid = threadIdx.x;
    const int w = tid >> 5, lane = tid & 31;
    const int g = lane >> 2, t = lane & 3;
    const int rw = w * 16;
    const int m0 = blockIdx.x * 128;
    const int h = blockIdx.y, b = blockIdx.z;
    const size_t bh = (size_t)b * Hh + h;
    const float* sp = shortb + (bh * Ll + m0) * Ll;

    const int lm = lane >> 3, lr = lane & 7;
    const int loffB = ((lm >> 1) * 8 + lr) * 36 + (lm & 1) * 4;

    const int rS = tid >> 2, sS = (tid & 3) * 8;

    auto stageA = [&](int n0, int bi) {
        float* SB = smb + bi * STAGE_F;
        uint32_t* K = (uint32_t*)(SB + 8704);
        uint32_t* V = K + 2304;
        int* M = (int*)(V + 2304);
        #pragma unroll
        for (int it = 0; it < 8; it++) {
            int lin = tid + it * 256, row = lin >> 4, c4 = (lin & 15) * 4;
            CP16(s2u(&SB[row * LS + c4]), &sp[(size_t)row * Ll + n0 + c4]);
        }
        const uint32_t* skh = &g_kh[(bh * Ll + n0 + rS) * 32 + sS];
        const uint32_t* svh = &g_vth[(bh * 64 + rS) * 1024 + (n0 >> 1) + sS];
        CP16(s2u(&K[rS*36 + sS]),     skh);
        CP16(s2u(&K[rS*36 + sS + 4]), skh + 4);
        CP16(s2u(&V[rS*36 + sS]),     svh);
        CP16(s2u(&V[rS*36 + sS + 4]), svh + 4);
        if (tid < 16) CP16(s2u(&M[tid * 4]), &mask[b * Ll + n0 + tid * 4]);
        CPCOMMIT();
    };

    // ---- Q fragments (hi plane only) ----
    uint32_t qh[16];
    {
        const uint32_t* qhp  = &g_qh[(bh * Ll + m0 + rw + g) * 32];
        const uint32_t* qhp8 = qhp + 8 * 32;
        #pragma unroll
        for (int j = 0; j < 4; j++) {
            qh[j*4 + 0] = qhp [8*j + t];
            qh[j*4 + 1] = qhp8[8*j + t];
            qh[j*4 + 2] = qhp [8*j + t + 4];
            qh[j*4 + 3] = qhp8[8*j + t + 4];
        }
    }

    stageA(0, 0);
    stageA(64, 1);
    CPWAIT1();
    __syncthreads();

    float accO[8][4] = {};
    float mrow[2] = {-1e30f, -1e30f};
    float lrow[2] = {0.0f, 0.0f};

    #pragma unroll 1
    for (int nb = 0; nb < 32; nb++) {
        const int bi = nb & 1;
        float* SB = smb + bi * STAGE_F;
        const float* SBw = SB + rw * LS;
        uint32_t kbase = s2u(SB + 8704) + loffB * 4;
        uint32_t vbase = kbase + 2304 * 4;
        const int* Mc = (const int*)(SB + 8704 + 4608);

        // ---- S = Q-hi K-hi ----
        float s[8][4] = {};
        #pragma unroll
        for (int j = 0; j < 4; j++) {
            uint32_t kf[16];
            #pragma unroll
            for (int p = 0; p < 4; p++)
                LDSM4(kf[p*4], kf[p*4+1], kf[p*4+2], kf[p*4+3],
                      kbase + (p*576 + j*8)*4);
            #pragma unroll
            for (int p = 0; p < 4; p++) {
                mma16(s[2*p],   qh[j*4], qh[j*4+1], qh[j*4+2], qh[j*4+3], kf[p*4],   kf[p*4+1]);
                mma16(s[2*p+1], qh[j*4], qh[j*4+1], qh[j*4+2], qh[j*4+3], kf[p*4+2], kf[p*4+3]);
            }
        }

        // ---- scale, mask, +short ----
        #pragma unroll
        for (int jn = 0; jn < 8; jn++) {
            int c0 = jn * 8 + 2 * t;
            int2 mk = *(const int2*)&Mc[c0];
            float2 sh0 = *(const float2*)&SBw[(g)     * LS + c0];
            float2 sh1 = *(const float2*)&SBw[(g + 8) * LS + c0];
            s[jn][0] = (mk.x ? s[jn][0] * 0.125f : NEGV) + sh0.x;
            s[jn][1] = (mk.y ? s[jn][1] * 0.125f : NEGV) + sh0.y;
            s[jn][2] = (mk.x ? s[jn][2] * 0.125f : NEGV) + sh1.x;
            s[jn][3] = (mk.y ? s[jn][3] * 0.125f : NEGV) + sh1.y;
        }

        // ---- online softmax ----
        #pragma unroll
        for (int half = 0; half < 2; half++) {
            const int r0 = half * 2;
            float tm = -1e30f;
            #pragma unroll
            for (int jn = 0; jn < 8; jn++)
                tm = fmaxf(tm, fmaxf(s[jn][r0], s[jn][r0 + 1]));
            tm = fmaxf(tm, __shfl_xor_sync(0xffffffffu, tm, 1));
            tm = fmaxf(tm, __shfl_xor_sync(0xffffffffu, tm, 2));
            float mn = fmaxf(mrow[half], tm);
            float sc = __expf(mrow[half] - mn);
            float ps = 0.0f;
            #pragma unroll
            for (int jn = 0; jn < 8; jn++) {
                s[jn][r0]     = __expf(s[jn][r0]     - mn);
                s[jn][r0 + 1] = __expf(s[jn][r0 + 1] - mn);
                ps += s[jn][r0] + s[jn][r0 + 1];
            }
            ps += __shfl_xor_sync(0xffffffffu, ps, 1);
            ps += __shfl_xor_sync(0xffffffffu, ps, 2);
            lrow[half] = lrow[half] * sc + ps;
            mrow[half] = mn;
            #pragma unroll
            for (int jd = 0; jd < 8; jd++) {
                accO[jd][r0]     *= sc;
                accO[jd][r0 + 1] *= sc;
            }
        }

        // ---- accO += P V (P-hi x V-hi) ----
        #pragma unroll
        for (int j = 0; j < 4; j++) {
            uint32_t ph0 = pack2(s[2*j][0],   s[2*j][1]);
            uint32_t ph1 = pack2(s[2*j][2],   s[2*j][3]);
            uint32_t ph2 = pack2(s[2*j+1][0], s[2*j+1][1]);
            uint32_t ph3 = pack2(s[2*j+1][2], s[2*j+1][3]);
            #pragma unroll
            for (int p = 0; p < 4; p++) {
                uint32_t vh0, vh1, vh2, vh3;
                LDSM4(vh0, vh1, vh2, vh3, vbase + (p*576 + j*8)*4);
                mma16(accO[2*p],   ph0, ph1, ph2, ph3, vh0, vh1);
                mma16(accO[2*p+1], ph0, ph1, ph2, ph3, vh2, vh3);
            }
        }

        // ---- rotate buffers ----
        __syncthreads();
        if (nb < 31) {
            int n2 = (nb + 2 < 32 ? nb + 2 : 31) * 64;
            stageA(n2, bi);
            CPWAIT1();
            __syncthreads();
        }
    }

    // ---- fused epilogue ----
    const float bm = bias_m[0];
    #pragma unroll
    for (int half = 0; half < 2; half++) {
        const int r0 = half * 2;
        int row = m0 + rw + g + half * 8;
        float piv = g_pi[bh * Ll + row] * 0.2f;
        float inv = 0.8f / lrow[half];
        #pragma unroll
        for (int jd = 0; jd < 8; jd++) {
            int c = jd * 8 + 2 * t;
            float2 sq = *(const float2*)&query[((size_t)b * Ll + row) * Dd + h * DK + c];
            float2 o;
            o.x = accO[jd][r0]     * inv + piv * sq.x + bm;
            o.y = accO[jd][r0 + 1] * inv + piv * sq.y + bm;
            *(float2*)&out[(bh * Ll + row) * DK + c] = o;
        }
    }
}

// ---------------------------------------------------------------------------
extern "C" void kernel_launch(void* const* d_in, const int* in_sizes, int n_in,
                              void* d_out, int out_size)
{
    const float* query  = (const float*)d_in[0];
    const float* key    = (const float*)d_in[1];
    const float* shortb = (const float*)d_in[2];
    const int*   mask   = (const int*)d_in[4];
    const float* Wq     = (const float*)d_in[5];
    const float* bq     = (const float*)d_in[6];
    const float* Wk     = (const float*)d_in[7];
    const float* bk     = (const float*)d_in[8];
    const float* w_mu   = (const float*)d_in[9];
    const float* b_mu   = (const float*)d_in[10];
    const float* bias_m = (const float*)d_in[11];
    float* out = (float*)d_out;

    cudaFuncSetAttribute(proj_mma_kernel, cudaFuncAttributeMaxDynamicSharedMemorySize, PROJ_SMEM);
    cudaFuncSetAttribute(attn_mma_kernel, cudaFuncAttributeMaxDynamicSharedMemorySize, ATTN_SMEM);

    prep_w_kernel<<<2304, 256>>>(Wq, Wk);
    prep_a_kernel<<<12288, 256>>>(query, key);
    prep_v_kernel<<<dim3(32, 24), 256>>>(query);
    proj_mma_kernel<<<dim3(32, 6, 2), 256, PROJ_SMEM>>>(bq, bk);
    mu_kernel<<<dim3(12, 2), 256>>>(query, mask, w_mu, b_mu);
    attn_mma_kernel<<<dim3(16, 12, 2), 256, ATTN_SMEM>>>(query, shortb, mask, bias_m, out);
}

// round 13
// speedup vs baseline: 4.5505x; 1.1113x over previous
#include <cuda_runtime.h>
#include <cuda_fp16.h>
#include <cstdint>

#define Bb 2
#define Hh 12
#define Ll 2048
#define Dd 768
#define DK 64
#define NEGV (-1000000000.0f)

// ---------------------------------------------------------------------------
// global scratch (all planes fp16-hi; pure fp16 GEMMs with fp32 accum)
// ---------------------------------------------------------------------------
__device__ uint32_t g_qh[Bb*Hh*Ll*32];                      // proj q out
__device__ uint32_t g_kh[Bb*Hh*Ll*32];                      // proj k out
__device__ uint32_t g_wh[2][Hh*64*384];                     // [qk][h*64+n][k2]
__device__ uint32_t g_ah[2][4096*384];                      // [qk][row][k2]
__device__ uint32_t g_vth[Bb*Hh*64*1024];                   // [bh*64+d][n2]
__device__ float g_pi[Bb*Hh*Ll];

// ---------------------------------------------------------------------------
// helpers
// ---------------------------------------------------------------------------
__device__ __forceinline__ uint32_t pack2(float x, float y) {
    __half2 hh = __floats2half2_rn(x, y);
    return *(uint32_t*)&hh;
}

__device__ __forceinline__ void mma16(float d[4], uint32_t a0, uint32_t a1, uint32_t a2,
                                      uint32_t a3, uint32_t b0, uint32_t b1) {
    asm("mma.sync.aligned.m16n8k16.row.col.f32.f16.f16.f32 "
        "{%0,%1,%2,%3},{%4,%5,%6,%7},{%8,%9},{%0,%1,%2,%3};\n"
        : "+f"(d[0]), "+f"(d[1]), "+f"(d[2]), "+f"(d[3])
        : "r"(a0), "r"(a1), "r"(a2), "r"(a3), "r"(b0), "r"(b1));
}

__device__ __forceinline__ uint32_t s2u(const void* p) {
    return (uint32_t)__cvta_generic_to_shared(p);
}
#define LDSM4(r0,r1,r2,r3,addr) \
    asm volatile("ldmatrix.sync.aligned.m8n8.x4.shared.b16 {%0,%1,%2,%3}, [%4];" \
                 : "=r"(r0), "=r"(r1), "=r"(r2), "=r"(r3) : "r"(addr))
#define CP16(dst, src) asm volatile("cp.async.cg.shared.global [%0], [%1], 16;\n" :: "r"(dst), "l"(src))
#define CPCOMMIT() asm volatile("cp.async.commit_group;\n" ::: "memory")
#define CPWAIT1()  asm volatile("cp.async.wait_group 1;\n" ::: "memory")
#define CPWAIT0()  asm volatile("cp.async.wait_group 0;\n" ::: "memory")

// ---------------------------------------------------------------------------
// prep kernels
// ---------------------------------------------------------------------------
__global__ __launch_bounds__(256) void prep_w_kernel(
    const float* __restrict__ Wq, const float* __restrict__ Wk)
{
    int idx = blockIdx.x * 256 + threadIdx.x;
    int qk = idx >= (Hh*64*384);
    int r = idx - qk * (Hh*64*384);
    int col = r / 384;
    int k2 = r % 384;
    const float* W = qk ? Wk : Wq;
    g_wh[qk][r] = pack2(W[(size_t)(2*k2) * Dd + col], W[(size_t)(2*k2+1) * Dd + col]);
}

__global__ __launch_bounds__(256) void prep_a_kernel(
    const float* __restrict__ query, const float* __restrict__ key)
{
    int idx = blockIdx.x * 256 + threadIdx.x;
    int qk = idx >= (4096*384);
    int r = idx - qk * (4096*384);
    int row = r / 384;
    int k2  = r % 384;
    const float* src = qk ? key : query;
    float2 f = *(const float2*)&src[(size_t)row * Dd + 2*k2];
    g_ah[qk][r] = pack2(f.x, f.y);
}

// V transposed: g_vth[bh*64 + d][n2] = half2(V[2n2][d], V[2n2+1][d])
__global__ __launch_bounds__(256) void prep_v_kernel(const float* __restrict__ query)
{
    __shared__ uint32_t th[64][33];
    const int tile = blockIdx.x;
    const int bh = blockIdx.y;
    const int b = bh / Hh, h = bh % Hh;
    const int n20 = tile * 32;
    const int tid = threadIdx.x;
    #pragma unroll
    for (int i = 0; i < 8; i++) {
        int lin = tid + 256 * i;
        int n2l = lin >> 6;
        int d = lin & 63;
        const float* q0 = &query[(size_t)(b * Ll + 2*(n20 + n2l)) * Dd + h * DK + d];
        th[d][n2l] = pack2(q0[0], q0[Dd]);
    }
    __syncthreads();
    #pragma unroll
    for (int i = 0; i < 8; i++) {
        int lin = tid + 256 * i;
        int d = lin >> 5;
        int n2l = lin & 31;
        g_vth[(size_t)(bh * 64 + d) * 1024 + n20 + n2l] = th[d][n2l];
    }
}

// ---------------------------------------------------------------------------
// Projection GEMM: 128 rows x 128 cols (2 heads) per block, 256 threads,
// pure fp16 (A hi, W hi), k-tile 64, double-buffered cp.async.
// ---------------------------------------------------------------------------
#define PJ_SET 9216   // u32 per stage: Ah 4608 | Wh 4608
#define PROJ_SMEM (2 * PJ_SET * 4)

__global__ __launch_bounds__(256, 2) void proj_mma_kernel(
    const float* __restrict__ bq, const float* __restrict__ bk)
{
    extern __shared__ uint32_t psm[];
    const int qk = blockIdx.z;
    const int tid = threadIdx.x;
    const int w = tid >> 5, lane = tid & 31, g = lane >> 2, t = lane & 3;
    const int rowg = w >> 1, colg = w & 1;
    const int rb0 = rowg * 32;
    const int row0 = blockIdx.x * 128;
    const int hp = blockIdx.y;

    const uint32_t* Agh = g_ah[qk];
    const uint32_t* Wgh = &g_wh[qk][(size_t)hp * 128 * 384];
    const float* bias = qk ? bk : bq;

    const int mA = tid >> 1, kbA = (tid & 1) * 16;

    const int lm = lane >> 3, lr = lane & 7;
    const int loffA = ((lm & 1) * 8 + lr) * 36 + (lm >> 1) * 4;
    const int loffB = ((lm >> 1) * 8 + lr) * 36 + (lm & 1) * 4;

    auto stagep = [&](int kb) {
        uint32_t* S = psm + (kb & 1) * PJ_SET;
        const int koff = kb * 32 + kbA;
        const uint32_t* sa = &Agh[(size_t)(row0 + mA) * 384 + koff];
        const uint32_t* sw = &Wgh[(size_t)mA * 384 + koff];
        #pragma unroll
        for (int i = 0; i < 4; i++) {
            CP16(s2u(&S[mA*36 + kbA + i*4]),        sa + i*4);
            CP16(s2u(&S[4608 + mA*36 + kbA + i*4]), sw + i*4);
        }
        CPCOMMIT();
    };

    stagep(0);
    float acc0[8][4] = {};
    float acc1[8][4] = {};

    #pragma unroll 1
    for (int kb = 0; kb < 12; kb++) {
        if (kb < 11) { stagep(kb + 1); CPWAIT1(); } else { CPWAIT0(); }
        __syncthreads();
        uint32_t sbase = s2u(psm) + ((kb & 1) * PJ_SET) * 4;
        uint32_t a0h = sbase + (rb0*36 + loffA) * 4;
        uint32_t a1h = a0h + 16*36*4;
        uint32_t wb  = sbase + (4608 + colg*64*36 + loffB) * 4;
        #pragma unroll
        for (int j = 0; j < 4; j++) {
            uint32_t p0h0,p0h1,p0h2,p0h3, p1h0,p1h1,p1h2,p1h3;
            LDSM4(p0h0,p0h1,p0h2,p0h3, a0h + j*32);
            LDSM4(p1h0,p1h1,p1h2,p1h3, a1h + j*32);
            #pragma unroll
            for (int p = 0; p < 4; p++) {
                uint32_t wh0, wh1, wh2, wh3;
                LDSM4(wh0, wh1, wh2, wh3, wb + (p*576 + j*8)*4);
                mma16(acc0[2*p],   p0h0,p0h1,p0h2,p0h3, wh0, wh1);
                mma16(acc0[2*p+1], p0h0,p0h1,p0h2,p0h3, wh2, wh3);
                mma16(acc1[2*p],   p1h0,p1h1,p1h2,p1h3, wh0, wh1);
                mma16(acc1[2*p+1], p1h0,p1h1,p1h2,p1h3, wh2, wh3);
            }
        }
        __syncthreads();
    }

    const int hglob = hp * 2 + colg;
    const float* bp = &bias[hglob * 64];
    uint32_t* outp = qk ? g_kh : g_qh;
    #pragma unroll
    for (int rb2 = 0; rb2 < 2; rb2++) {
        float (*acc)[4] = rb2 ? acc1 : acc0;
        #pragma unroll
        for (int half = 0; half < 2; half++) {
            int row = row0 + rb0 + rb2*16 + g + half*8;
            int b_ = row >> 11, l = row & (Ll - 1);
            size_t base = ((size_t)(b_ * Hh + hglob) * Ll + l) * 32;
            #pragma unroll
            for (int jn = 0; jn < 8; jn++) {
                float2 bb = *(const float2*)&bp[jn*8 + 2*t];
                outp[base + jn*4 + t] =
                    pack2(acc[jn][2*half] + bb.x, acc[jn][2*half + 1] + bb.y);
            }
        }
    }
}

// ---------------------------------------------------------------------------
// mu (= pi) kernel
// ---------------------------------------------------------------------------
__global__ __launch_bounds__(256) void mu_kernel(
    const float* __restrict__ query, const int* __restrict__ mask,
    const float* __restrict__ w_mu, const float* __restrict__ b_mu)
{
    const int h = blockIdx.x, b = blockIdx.y;
    const int tid = threadIdx.x;
    __shared__ float wmu[64];
    __shared__ float red[8];
    if (tid < 64) wmu[tid] = w_mu[tid];
    __syncthreads();
    const float bmu = b_mu[0];

    float lg[8];
    float lmax = -1e30f;
    #pragma unroll
    for (int j = 0; j < 8; j++) {
        int l = tid + j * 256;
        const float* sp = &query[((size_t)b * Ll + l) * Dd + h * DK];
        float dm = 0.0f;
        #pragma unroll
        for (int d = 0; d < 64; d += 4) {
            float4 s4 = *(const float4*)&sp[d];
            dm += s4.x * wmu[d] + s4.y * wmu[d+1] + s4.z * wmu[d+2] + s4.w * wmu[d+3];
        }
        float v = dm + bmu;
        if (mask[b * Ll + l] == 0) v = NEGV;
        lg[j] = v;
        lmax = fmaxf(lmax, v);
    }
    {
        int wi = tid >> 5, lane = tid & 31;
        #pragma unroll
        for (int o = 16; o; o >>= 1) lmax = fmaxf(lmax, __shfl_xor_sync(~0u, lmax, o));
        if (lane == 0) red[wi] = lmax;
        __syncthreads();
        if (wi == 0) {
            float r = (lane < 8) ? red[lane] : -1e30f;
            #pragma unroll
            for (int o = 16; o; o >>= 1) r = fmaxf(r, __shfl_xor_sync(~0u, r, o));
            if (lane == 0) red[0] = r;
        }
        __syncthreads();
        lmax = red[0];
        __syncthreads();
    }
    float lsum = 0.0f;
    #pragma unroll
    for (int j = 0; j < 8; j++) { lg[j] = __expf(lg[j] - lmax); lsum += lg[j]; }
    {
        int wi = tid >> 5, lane = tid & 31;
        #pragma unroll
        for (int o = 16; o; o >>= 1) lsum += __shfl_xor_sync(~0u, lsum, o);
        if (lane == 0) red[wi] = lsum;
        __syncthreads();
        if (wi == 0) {
            float r = (lane < 8) ? red[lane] : 0.0f;
            #pragma unroll
            for (int o = 16; o; o >>= 1) r += __shfl_xor_sync(~0u, r, o);
            if (lane == 0) red[0] = r;
        }
        __syncthreads();
        lsum = red[0];
    }
    float inv = 1.0f / lsum;
    #pragma unroll
    for (int j = 0; j < 8; j++)
        g_pi[((size_t)b * Hh + h) * Ll + tid + j * 256] = lg[j] * inv;
}

// ---------------------------------------------------------------------------
// Attention: 128-row tiles, 256 threads (8 warps x 16 rows), fp16.
// QK: Q-hi x K-hi (32 mma). PV: P-hi x V-hi (32 mma). Double-buffered stages.
// ---------------------------------------------------------------------------
#define LS 68
#define STAGE_F 13376   // floats: SBuf 128*68=8704 | K 2304 | V 2304 | mask 64
#define ATTN_SMEM (2 * STAGE_F * 4)

__global__ __launch_bounds__(256, 2) void attn_mma_kernel(
    const float* __restrict__ query, const float* __restrict__ shortb,
    const int* __restrict__ mask, const float* __restrict__ bias_m,
    float* __restrict__ out)
{
    extern __shared__ float smb[];

    const int tid = threadIdx.x;
    const int w = tid >> 5, lane = tid & 31;
    const int g = lane >> 2, t = lane & 3;
    const int rw = w * 16;
    const int m0 = blockIdx.x * 128;
    const int h = blockIdx.y, b = blockIdx.z;
    const size_t bh = (size_t)b * Hh + h;
    const float* sp = shortb + (bh * Ll + m0) * Ll;

    const int lm = lane >> 3, lr = lane & 7;
    const int loffB = ((lm >> 1) * 8 + lr) * 36 + (lm & 1) * 4;

    const int rS = tid >> 2, sS = (tid & 3) * 8;

    auto stageA = [&](int n0, int bi) {
        float* SB = smb + bi * STAGE_F;
        uint32_t* K = (uint32_t*)(SB + 8704);
        uint32_t* V = K + 2304;
        int* M = (int*)(V + 2304);
        #pragma unroll
        for (int it = 0; it < 8; it++) {
            int lin = tid + it * 256, row = lin >> 4, c4 = (lin & 15) * 4;
            CP16(s2u(&SB[row * LS + c4]), &sp[(size_t)row * Ll + n0 + c4]);
        }
        const uint32_t* skh = &g_kh[(bh * Ll + n0 + rS) * 32 + sS];
        const uint32_t* svh = &g_vth[(bh * 64 + rS) * 1024 + (n0 >> 1) + sS];
        CP16(s2u(&K[rS*36 + sS]),     skh);
        CP16(s2u(&K[rS*36 + sS + 4]), skh + 4);
        CP16(s2u(&V[rS*36 + sS]),     svh);
        CP16(s2u(&V[rS*36 + sS + 4]), svh + 4);
        if (tid < 16) CP16(s2u(&M[tid * 4]), &mask[b * Ll + n0 + tid * 4]);
        CPCOMMIT();
    };

    // ---- Q fragments (hi plane) ----
    uint32_t qh[16];
    {
        const uint32_t* qhp  = &g_qh[(bh * Ll + m0 + rw + g) * 32];
        const uint32_t* qhp8 = qhp + 8 * 32;
        #pragma unroll
        for (int j = 0; j < 4; j++) {
            qh[j*4 + 0] = qhp [8*j + t];
            qh[j*4 + 1] = qhp8[8*j + t];
            qh[j*4 + 2] = qhp [8*j + t + 4];
            qh[j*4 + 3] = qhp8[8*j + t + 4];
        }
    }

    stageA(0, 0);
    stageA(64, 1);
    CPWAIT1();
    __syncthreads();

    float accO[8][4] = {};
    float mrow[2] = {-1e30f, -1e30f};
    float lrow[2] = {0.0f, 0.0f};

    #pragma unroll 1
    for (int nb = 0; nb < 32; nb++) {
        const int bi = nb & 1;
        float* SB = smb + bi * STAGE_F;
        const float* SBw = SB + rw * LS;
        uint32_t kbase = s2u(SB + 8704) + loffB * 4;
        uint32_t vbase = kbase + 2304 * 4;
        const int* Mc = (const int*)(SB + 8704 + 4608);

        // ---- S = Q-hi K-hi ----
        float s[8][4] = {};
        #pragma unroll
        for (int j = 0; j < 4; j++) {
            uint32_t kf[16];
            #pragma unroll
            for (int p = 0; p < 4; p++)
                LDSM4(kf[p*4], kf[p*4+1], kf[p*4+2], kf[p*4+3],
                      kbase + (p*576 + j*8)*4);
            #pragma unroll
            for (int p = 0; p < 4; p++) {
                mma16(s[2*p],   qh[j*4], qh[j*4+1], qh[j*4+2], qh[j*4+3], kf[p*4],   kf[p*4+1]);
                mma16(s[2*p+1], qh[j*4], qh[j*4+1], qh[j*4+2], qh[j*4+3], kf[p*4+2], kf[p*4+3]);
            }
        }

        // ---- scale, mask, +short ----
        #pragma unroll
        for (int jn = 0; jn < 8; jn++) {
            int c0 = jn * 8 + 2 * t;
            int2 mk = *(const int2*)&Mc[c0];
            float2 sh0 = *(const float2*)&SBw[(g)     * LS + c0];
            float2 sh1 = *(const float2*)&SBw[(g + 8) * LS + c0];
            s[jn][0] = (mk.x ? s[jn][0] * 0.125f : NEGV) + sh0.x;
            s[jn][1] = (mk.y ? s[jn][1] * 0.125f : NEGV) + sh0.y;
            s[jn][2] = (mk.x ? s[jn][2] * 0.125f : NEGV) + sh1.x;
            s[jn][3] = (mk.y ? s[jn][3] * 0.125f : NEGV) + sh1.y;
        }

        // ---- online softmax ----
        #pragma unroll
        for (int half = 0; half < 2; half++) {
            const int r0 = half * 2;
            float tm = -1e30f;
            #pragma unroll
            for (int jn = 0; jn < 8; jn++)
                tm = fmaxf(tm, fmaxf(s[jn][r0], s[jn][r0 + 1]));
            tm = fmaxf(tm, __shfl_xor_sync(0xffffffffu, tm, 1));
            tm = fmaxf(tm, __shfl_xor_sync(0xffffffffu, tm, 2));
            float mn = fmaxf(mrow[half], tm);
            float sc = __expf(mrow[half] - mn);
            float ps = 0.0f;
            #pragma unroll
            for (int jn = 0; jn < 8; jn++) {
                s[jn][r0]     = __expf(s[jn][r0]     - mn);
                s[jn][r0 + 1] = __expf(s[jn][r0 + 1] - mn);
                ps += s[jn][r0] + s[jn][r0 + 1];
            }
            ps += __shfl_xor_sync(0xffffffffu, ps, 1);
            ps += __shfl_xor_sync(0xffffffffu, ps, 2);
            lrow[half] = lrow[half] * sc + ps;
            mrow[half] = mn;
            #pragma unroll
            for (int jd = 0; jd < 8; jd++) {
                accO[jd][r0]     *= sc;
                accO[jd][r0 + 1] *= sc;
            }
        }

        // ---- accO += P V (P-hi x V-hi) ----
        #pragma unroll
        for (int j = 0; j < 4; j++) {
            uint32_t ph0 = pack2(s[2*j][0],   s[2*j][1]);
            uint32_t ph1 = pack2(s[2*j][2],   s[2*j][3]);
            uint32_t ph2 = pack2(s[2*j+1][0], s[2*j+1][1]);
            uint32_t ph3 = pack2(s[2*j+1][2], s[2*j+1][3]);
            #pragma unroll
            for (int p = 0; p < 4; p++) {
                uint32_t vh0, vh1, vh2, vh3;
                LDSM4(vh0, vh1, vh2, vh3, vbase + (p*576 + j*8)*4);
                mma16(accO[2*p],   ph0, ph1, ph2, ph3, vh0, vh1);
                mma16(accO[2*p+1], ph0, ph1, ph2, ph3, vh2, vh3);
            }
        }

        // ---- rotate buffers ----
        __syncthreads();
        if (nb < 31) {
            int n2 = (nb + 2 < 32 ? nb + 2 : 31) * 64;
            stageA(n2, bi);
            CPWAIT1();
            __syncthreads();
        }
    }

    // ---- fused epilogue ----
    const float bm = bias_m[0];
    #pragma unroll
    for (int half = 0; half < 2; half++) {
        const int r0 = half * 2;
        int row = m0 + rw + g + half * 8;
        float piv = g_pi[bh * Ll + row] * 0.2f;
        float inv = 0.8f / lrow[half];
        #pragma unroll
        for (int jd = 0; jd < 8; jd++) {
            int c = jd * 8 + 2 * t;
            float2 sq = *(const float2*)&query[((size_t)b * Ll + row) * Dd + h * DK + c];
            float2 o;
            o.x = accO[jd][r0]     * inv + piv * sq.x + bm;
            o.y = accO[jd][r0 + 1] * inv + piv * sq.y + bm;
            *(float2*)&out[(bh * Ll + row) * DK + c] = o;
        }
    }
}

// ---------------------------------------------------------------------------
extern "C" void kernel_launch(void* const* d_in, const int* in_sizes, int n_in,
                              void* d_out, int out_size)
{
    const float* query  = (const float*)d_in[0];
    const float* key    = (const float*)d_in[1];
    const float* shortb = (const float*)d_in[2];
    const int*   mask   = (const int*)d_in[4];
    const float* Wq     = (const float*)d_in[5];
    const float* bq     = (const float*)d_in[6];
    const float* Wk     = (const float*)d_in[7];
    const float* bk     = (const float*)d_in[8];
    const float* w_mu   = (const float*)d_in[9];
    const float* b_mu   = (const float*)d_in[10];
    const float* bias_m = (const float*)d_in[11];
    float* out = (float*)d_out;

    cudaFuncSetAttribute(proj_mma_kernel, cudaFuncAttributeMaxDynamicSharedMemorySize, PROJ_SMEM);
    cudaFuncSetAttribute(attn_mma_kernel, cudaFuncAttributeMaxDynamicSharedMemorySize, ATTN_SMEM);

    prep_w_kernel<<<2304, 256>>>(Wq, Wk);
    prep_a_kernel<<<12288, 256>>>(query, key);
    prep_v_kernel<<<dim3(32, 24), 256>>>(query);
    proj_mma_kernel<<<dim3(32, 6, 2), 256, PROJ_SMEM>>>(bq, bk);
    mu_kernel<<<dim3(12, 2), 256>>>(query, mask, w_mu, b_mu);
    attn_mma_kernel<<<dim3(16, 12, 2), 256, ATTN_SMEM>>>(query, shortb, mask, bias_m, out);
}

// round 15
// speedup vs baseline: 4.9684x; 1.0918x over previous
#include <cuda_runtime.h>
#include <cuda_fp16.h>
#include <cstdint>

#define Bb 2
#define Hh 12
#define Ll 2048
#define Dd 768
#define DK 64
#define NEGV (-1000000000.0f)
#define SOFT_OFF 8.0f   // fixed softmax base: keeps fp16 P in normal range

// ---------------------------------------------------------------------------
// global scratch (all planes fp16; q pre-scaled by 1/8 — exact in fp16)
// ---------------------------------------------------------------------------
__device__ uint32_t g_qh[Bb*Hh*Ll*32];                      // proj q out (x0.125)
__device__ uint32_t g_kh[Bb*Hh*Ll*32];                      // proj k out
__device__ uint32_t g_wh[2][Hh*64*384];                     // [qk][h*64+n][k2]
__device__ uint32_t g_ah[2][4096*384];                      // [qk][row][k2]
__device__ uint32_t g_vth[Bb*Hh*64*1024];                   // [bh*64+d][n2]
__device__ float g_pi[Bb*Hh*Ll];

// ---------------------------------------------------------------------------
// helpers
// ---------------------------------------------------------------------------
__device__ __forceinline__ uint32_t pack2(float x, float y) {
    __half2 hh = __floats2half2_rn(x, y);
    return *(uint32_t*)&hh;
}

__device__ __forceinline__ void mma16(float d[4], uint32_t a0, uint32_t a1, uint32_t a2,
                                      uint32_t a3, uint32_t b0, uint32_t b1) {
    asm("mma.sync.aligned.m16n8k16.row.col.f32.f16.f16.f32 "
        "{%0,%1,%2,%3},{%4,%5,%6,%7},{%8,%9},{%0,%1,%2,%3};\n"
        : "+f"(d[0]), "+f"(d[1]), "+f"(d[2]), "+f"(d[3])
        : "r"(a0), "r"(a1), "r"(a2), "r"(a3), "r"(b0), "r"(b1));
}

__device__ __forceinline__ uint32_t s2u(const void* p) {
    return (uint32_t)__cvta_generic_to_shared(p);
}
#define LDSM4(r0,r1,r2,r3,addr) \
    asm volatile("ldmatrix.sync.aligned.m8n8.x4.shared.b16 {%0,%1,%2,%3}, [%4];" \
                 : "=r"(r0), "=r"(r1), "=r"(r2), "=r"(r3) : "r"(addr))
#define CP16(dst, src) asm volatile("cp.async.cg.shared.global [%0], [%1], 16;\n" :: "r"(dst), "l"(src))
#define CPCOMMIT() asm volatile("cp.async.commit_group;\n" ::: "memory")
#define CPWAIT1()  asm volatile("cp.async.wait_group 1;\n" ::: "memory")
#define CPWAIT0()  asm volatile("cp.async.wait_group 0;\n" ::: "memory")

// ---------------------------------------------------------------------------
// prep kernels
// ---------------------------------------------------------------------------
__global__ __launch_bounds__(256) void prep_w_kernel(
    const float* __restrict__ Wq, const float* __restrict__ Wk)
{
    int idx = blockIdx.x * 256 + threadIdx.x;
    int qk = idx >= (Hh*64*384);
    int r = idx - qk * (Hh*64*384);
    int col = r / 384;
    int k2 = r % 384;
    const float* W = qk ? Wk : Wq;
    g_wh[qk][r] = pack2(W[(size_t)(2*k2) * Dd + col], W[(size_t)(2*k2+1) * Dd + col]);
}

__global__ __launch_bounds__(256) void prep_a_kernel(
    const float* __restrict__ query, const float* __restrict__ key)
{
    int idx = blockIdx.x * 256 + threadIdx.x;
    int qk = idx >= (4096*384);
    int r = idx - qk * (4096*384);
    int row = r / 384;
    int k2  = r % 384;
    const float* src = qk ? key : query;
    float2 f = *(const float2*)&src[(size_t)row * Dd + 2*k2];
    g_ah[qk][r] = pack2(f.x, f.y);
}

// V transposed: g_vth[bh*64 + d][n2] = half2(V[2n2][d], V[2n2+1][d])
__global__ __launch_bounds__(256) void prep_v_kernel(const float* __restrict__ query)
{
    __shared__ uint32_t th[64][33];
    const int tile = blockIdx.x;
    const int bh = blockIdx.y;
    const int b = bh / Hh, h = bh % Hh;
    const int n20 = tile * 32;
    const int tid = threadIdx.x;
    #pragma unroll
    for (int i = 0; i < 8; i++) {
        int lin = tid + 256 * i;
        int n2l = lin >> 6;
        int d = lin & 63;
        const float* q0 = &query[(size_t)(b * Ll + 2*(n20 + n2l)) * Dd + h * DK + d];
        th[d][n2l] = pack2(q0[0], q0[Dd]);
    }
    __syncthreads();
    #pragma unroll
    for (int i = 0; i < 8; i++) {
        int lin = tid + 256 * i;
        int d = lin >> 5;
        int n2l = lin & 31;
        g_vth[(size_t)(bh * 64 + d) * 1024 + n20 + n2l] = th[d][n2l];
    }
}

// ---------------------------------------------------------------------------
// Projection GEMM: 128 rows x 128 cols (2 heads) per block, 256 threads,
// pure fp16, k-tile 64, double-buffered cp.async. q scaled by 0.125 (exact).
// ---------------------------------------------------------------------------
#define PJ_SET 9216   // u32 per stage: Ah 4608 | Wh 4608
#define PROJ_SMEM (2 * PJ_SET * 4)

__global__ __launch_bounds__(256, 2) void proj_mma_kernel(
    const float* __restrict__ bq, const float* __restrict__ bk)
{
    extern __shared__ uint32_t psm[];
    const int qk = blockIdx.z;
    const int tid = threadIdx.x;
    const int w = tid >> 5, lane = tid & 31, g = lane >> 2, t = lane & 3;
    const int rowg = w >> 1, colg = w & 1;
    const int rb0 = rowg * 32;
    const int row0 = blockIdx.x * 128;
    const int hp = blockIdx.y;

    const uint32_t* Agh = g_ah[qk];
    const uint32_t* Wgh = &g_wh[qk][(size_t)hp * 128 * 384];
    const float* bias = qk ? bk : bq;

    const int mA = tid >> 1, kbA = (tid & 1) * 16;

    const int lm = lane >> 3, lr = lane & 7;
    const int loffA = ((lm & 1) * 8 + lr) * 36 + (lm >> 1) * 4;
    const int loffB = ((lm >> 1) * 8 + lr) * 36 + (lm & 1) * 4;

    auto stagep = [&](int kb) {
        uint32_t* S = psm + (kb & 1) * PJ_SET;
        const int koff = kb * 32 + kbA;
        const uint32_t* sa = &Agh[(size_t)(row0 + mA) * 384 + koff];
        const uint32_t* sw = &Wgh[(size_t)mA * 384 + koff];
        #pragma unroll
        for (int i = 0; i < 4; i++) {
            CP16(s2u(&S[mA*36 + kbA + i*4]),        sa + i*4);
            CP16(s2u(&S[4608 + mA*36 + kbA + i*4]), sw + i*4);
        }
        CPCOMMIT();
    };

    stagep(0);
    float acc0[8][4] = {};
    float acc1[8][4] = {};

    #pragma unroll 1
    for (int kb = 0; kb < 12; kb++) {
        if (kb < 11) { stagep(kb + 1); CPWAIT1(); } else { CPWAIT0(); }
        __syncthreads();
        uint32_t sbase = s2u(psm) + ((kb & 1) * PJ_SET) * 4;
        uint32_t a0h = sbase + (rb0*36 + loffA) * 4;
        uint32_t a1h = a0h + 16*36*4;
        uint32_t wb  = sbase + (4608 + colg*64*36 + loffB) * 4;
        #pragma unroll
        for (int j = 0; j < 4; j++) {
            uint32_t p0h0,p0h1,p0h2,p0h3, p1h0,p1h1,p1h2,p1h3;
            LDSM4(p0h0,p0h1,p0h2,p0h3, a0h + j*32);
            LDSM4(p1h0,p1h1,p1h2,p1h3, a1h + j*32);
            #pragma unroll
            for (int p = 0; p < 4; p++) {
                uint32_t wh0, wh1, wh2, wh3;
                LDSM4(wh0, wh1, wh2, wh3, wb + (p*576 + j*8)*4);
                mma16(acc0[2*p],   p0h0,p0h1,p0h2,p0h3, wh0, wh1);
                mma16(acc0[2*p+1], p0h0,p0h1,p0h2,p0h3, wh2, wh3);
                mma16(acc1[2*p],   p1h0,p1h1,p1h2,p1h3, wh0, wh1);
                mma16(acc1[2*p+1], p1h0,p1h1,p1h2,p1h3, wh2, wh3);
            }
        }
        __syncthreads();
    }

    const int hglob = hp * 2 + colg;
    const float* bp = &bias[hglob * 64];
    uint32_t* outp = qk ? g_kh : g_qh;
    const float osc = qk ? 1.0f : 0.125f;   // fold 1/sqrt(dk) into q (exact pow2)
    #pragma unroll
    for (int rb2 = 0; rb2 < 2; rb2++) {
        float (*acc)[4] = rb2 ? acc1 : acc0;
        #pragma unroll
        for (int half = 0; half < 2; half++) {
            int row = row0 + rb0 + rb2*16 + g + half*8;
            int b_ = row >> 11, l = row & (Ll - 1);
            size_t base = ((size_t)(b_ * Hh + hglob) * Ll + l) * 32;
            #pragma unroll
            for (int jn = 0; jn < 8; jn++) {
                float2 bb = *(const float2*)&bp[jn*8 + 2*t];
                outp[base + jn*4 + t] =
                    pack2((acc[jn][2*half] + bb.x) * osc,
                          (acc[jn][2*half + 1] + bb.y) * osc);
            }
        }
    }
}

// ---------------------------------------------------------------------------
// mu (= pi) kernel
// ---------------------------------------------------------------------------
__global__ __launch_bounds__(256) void mu_kernel(
    const float* __restrict__ query, const int* __restrict__ mask,
    const float* __restrict__ w_mu, const float* __restrict__ b_mu)
{
    const int h = blockIdx.x, b = blockIdx.y;
    const int tid = threadIdx.x;
    __shared__ float wmu[64];
    __shared__ float red[8];
    if (tid < 64) wmu[tid] = w_mu[tid];
    __syncthreads();
    const float bmu = b_mu[0];

    float lg[8];
    float lmax = -1e30f;
    #pragma unroll
    for (int j = 0; j < 8; j++) {
        int l = tid + j * 256;
        const float* sp = &query[((size_t)b * Ll + l) * Dd + h * DK];
        float dm = 0.0f;
        #pragma unroll
        for (int d = 0; d < 64; d += 4) {
            float4 s4 = *(const float4*)&sp[d];
            dm += s4.x * wmu[d] + s4.y * wmu[d+1] + s4.z * wmu[d+2] + s4.w * wmu[d+3];
        }
        float v = dm + bmu;
        if (mask[b * Ll + l] == 0) v = NEGV;
        lg[j] = v;
        lmax = fmaxf(lmax, v);
    }
    {
        int wi = tid >> 5, lane = tid & 31;
        #pragma unroll
        for (int o = 16; o; o >>= 1) lmax = fmaxf(lmax, __shfl_xor_sync(~0u, lmax, o));
        if (lane == 0) red[wi] = lmax;
        __syncthreads();
        if (wi == 0) {
            float r = (lane < 8) ? red[lane] : -1e30f;
            #pragma unroll
            for (int o = 16; o; o >>= 1) r = fmaxf(r, __shfl_xor_sync(~0u, r, o));
            if (lane == 0) red[0] = r;
        }
        __syncthreads();
        lmax = red[0];
        __syncthreads();
    }
    float lsum = 0.0f;
    #pragma unroll
    for (int j = 0; j < 8; j++) { lg[j] = __expf(lg[j] - lmax); lsum += lg[j]; }
    {
        int wi = tid >> 5, lane = tid & 31;
        #pragma unroll
        for (int o = 16; o; o >>= 1) lsum += __shfl_xor_sync(~0u, lsum, o);
        if (lane == 0) red[wi] = lsum;
        __syncthreads();
        if (wi == 0) {
            float r = (lane < 8) ? red[lane] : 0.0f;
            #pragma unroll
            for (int o = 16; o; o >>= 1) r += __shfl_xor_sync(~0u, r, o);
            if (lane == 0) red[0] = r;
        }
        __syncthreads();
        lsum = red[0];
    }
    float inv = 1.0f / lsum;
    #pragma unroll
    for (int j = 0; j < 8; j++)
        g_pi[((size_t)b * Hh + h) * Ll + tid + j * 256] = lg[j] * inv;
}

// ---------------------------------------------------------------------------
// Attention: 128-row tiles, 256 threads (8 warps x 16 rows), fp16.
// Fixed-base softmax with OFF=8 (fp16-P safe): no running max, no rescale;
// row-sum shuffles deferred to epilogue. Q pre-scaled by 1/8.
// ---------------------------------------------------------------------------
#define LS 68
#define STAGE_F 13376   // floats: SBuf 128*68=8704 | K 2304 | V 2304 | mask 64
#define ATTN_SMEM (2 * STAGE_F * 4)

__global__ __launch_bounds__(256, 2) void attn_mma_kernel(
    const float* __restrict__ query, const float* __restrict__ shortb,
    const int* __restrict__ mask, const float* __restrict__ bias_m,
    float* __restrict__ out)
{
    extern __shared__ float smb[];

    const int tid = threadIdx.x;
    const int w = tid >> 5, lane = tid & 31;
    const int g = lane >> 2, t = lane & 3;
    const int rw = w * 16;
    const int m0 = blockIdx.x * 128;
    const int h = blockIdx.y, b = blockIdx.z;
    const size_t bh = (size_t)b * Hh + h;
    const float* sp = shortb + (bh * Ll + m0) * Ll;

    const int lm = lane >> 3, lr = lane & 7;
    const int loffB = ((lm >> 1) * 8 + lr) * 36 + (lm & 1) * 4;

    const int rS = tid >> 2, sS = (tid & 3) * 8;

    auto stageA = [&](int n0, int bi) {
        float* SB = smb + bi * STAGE_F;
        uint32_t* K = (uint32_t*)(SB + 8704);
        uint32_t* V = K + 2304;
        int* M = (int*)(V + 2304);
        #pragma unroll
        for (int it = 0; it < 8; it++) {
            int lin = tid + it * 256, row = lin >> 4, c4 = (lin & 15) * 4;
            CP16(s2u(&SB[row * LS + c4]), &sp[(size_t)row * Ll + n0 + c4]);
        }
        const uint32_t* skh = &g_kh[(bh * Ll + n0 + rS) * 32 + sS];
        const uint32_t* svh = &g_vth[(bh * 64 + rS) * 1024 + (n0 >> 1) + sS];
        CP16(s2u(&K[rS*36 + sS]),     skh);
        CP16(s2u(&K[rS*36 + sS + 4]), skh + 4);
        CP16(s2u(&V[rS*36 + sS]),     svh);
        CP16(s2u(&V[rS*36 + sS + 4]), svh + 4);
        if (tid < 16) CP16(s2u(&M[tid * 4]), &mask[b * Ll + n0 + tid * 4]);
        CPCOMMIT();
    };

    // ---- Q fragments (pre-scaled by 1/8) ----
    uint32_t qh[16];
    {
        const uint32_t* qhp  = &g_qh[(bh * Ll + m0 + rw + g) * 32];
        const uint32_t* qhp8 = qhp + 8 * 32;
        #pragma unroll
        for (int j = 0; j < 4; j++) {
            qh[j*4 + 0] = qhp [8*j + t];
            qh[j*4 + 1] = qhp8[8*j + t];
            qh[j*4 + 2] = qhp [8*j + t + 4];
            qh[j*4 + 3] = qhp8[8*j + t + 4];
        }
    }

    stageA(0, 0);
    stageA(64, 1);
    CPWAIT1();
    __syncthreads();

    float accO[8][4] = {};
    float lrow[2] = {0.0f, 0.0f};   // thread-local partial row sums

    #pragma unroll 1
    for (int nb = 0; nb < 32; nb++) {
        const int bi = nb & 1;
        float* SB = smb + bi * STAGE_F;
        const float* SBw = SB + rw * LS;
        uint32_t kbase = s2u(SB + 8704) + loffB * 4;
        uint32_t vbase = kbase + 2304 * 4;
        const int* Mc = (const int*)(SB + 8704 + 4608);

        // ---- S = Q K^T ----
        float s[8][4] = {};
        #pragma unroll
        for (int j = 0; j < 4; j++) {
            uint32_t kf[16];
            #pragma unroll
            for (int p = 0; p < 4; p++)
                LDSM4(kf[p*4], kf[p*4+1], kf[p*4+2], kf[p*4+3],
                      kbase + (p*576 + j*8)*4);
            #pragma unroll
            for (int p = 0; p < 4; p++) {
                mma16(s[2*p],   qh[j*4], qh[j*4+1], qh[j*4+2], qh[j*4+3], kf[p*4],   kf[p*4+1]);
                mma16(s[2*p+1], qh[j*4], qh[j*4+1], qh[j*4+2], qh[j*4+3], kf[p*4+2], kf[p*4+3]);
            }
        }

        // ---- mask, +short, exp (fixed base), local row-sum ----
        #pragma unroll
        for (int jn = 0; jn < 8; jn++) {
            int c0 = jn * 8 + 2 * t;
            int2 mk = *(const int2*)&Mc[c0];
            float2 sh0 = *(const float2*)&SBw[(g)     * LS + c0];
            float2 sh1 = *(const float2*)&SBw[(g + 8) * LS + c0];
            s[jn][0] = __expf((mk.x ? s[jn][0] + sh0.x : NEGV) - SOFT_OFF);
            s[jn][1] = __expf((mk.y ? s[jn][1] + sh0.y : NEGV) - SOFT_OFF);
            s[jn][2] = __expf((mk.x ? s[jn][2] + sh1.x : NEGV) - SOFT_OFF);
            s[jn][3] = __expf((mk.y ? s[jn][3] + sh1.y : NEGV) - SOFT_OFF);
            lrow[0] += s[jn][0] + s[jn][1];
            lrow[1] += s[jn][2] + s[jn][3];
        }

        // ---- accO += P V ----
        #pragma unroll
        for (int j = 0; j < 4; j++) {
            uint32_t ph0 = pack2(s[2*j][0],   s[2*j][1]);
            uint32_t ph1 = pack2(s[2*j][2],   s[2*j][3]);
            uint32_t ph2 = pack2(s[2*j+1][0], s[2*j+1][1]);
            uint32_t ph3 = pack2(s[2*j+1][2], s[2*j+1][3]);
            #pragma unroll
            for (int p = 0; p < 4; p++) {
                uint32_t vh0, vh1, vh2, vh3;
                LDSM4(vh0, vh1, vh2, vh3, vbase + (p*576 + j*8)*4);
                mma16(accO[2*p],   ph0, ph1, ph2, ph3, vh0, vh1);
                mma16(accO[2*p+1], ph0, ph1, ph2, ph3, vh2, vh3);
            }
        }

        // ---- rotate buffers ----
        __syncthreads();
        if (nb < 31) {
            int n2 = (nb + 2 < 32 ? nb + 2 : 31) * 64;
            stageA(n2, bi);
            CPWAIT1();
            __syncthreads();
        }
    }

    // ---- finalize row sums across the quad (once, not per chunk) ----
    #pragma unroll
    for (int half = 0; half < 2; half++) {
        lrow[half] += __shfl_xor_sync(0xffffffffu, lrow[half], 1);
        lrow[half] += __shfl_xor_sync(0xffffffffu, lrow[half], 2);
    }

    // ---- fused epilogue ----
    const float bm = bias_m[0];
    #pragma unroll
    for (int half = 0; half < 2; half++) {
        const int r0 = half * 2;
        int row = m0 + rw + g + half * 8;
        float piv = g_pi[bh * Ll + row] * 0.2f;
        float inv = 0.8f / lrow[half];
        #pragma unroll
        for (int jd = 0; jd < 8; jd++) {
            int c = jd * 8 + 2 * t;
            float2 sq = *(const float2*)&query[((size_t)b * Ll + row) * Dd + h * DK + c];
            float2 o;
            o.x = accO[jd][r0]     * inv + piv * sq.x + bm;
            o.y = accO[jd][r0 + 1] * inv + piv * sq.y + bm;
            *(float2*)&out[(bh * Ll + row) * DK + c] = o;
        }
    }
}

// ---------------------------------------------------------------------------
extern "C" void kernel_launch(void* const* d_in, const int* in_sizes, int n_in,
                              void* d_out, int out_size)
{
    const float* query  = (const float*)d_in[0];
    const float* key    = (const float*)d_in[1];
    const float* shortb = (const float*)d_in[2];
    const int*   mask   = (const int*)d_in[4];
    const float* Wq     = (const float*)d_in[5];
    const float* bq     = (const float*)d_in[6];
    const float* Wk     = (const float*)d_in[7];
    const float* bk     = (const float*)d_in[8];
    const float* w_mu   = (const float*)d_in[9];
    const float* b_mu   = (const float*)d_in[10];
    const float* bias_m = (const float*)d_in[11];
    float* out = (float*)d_out;

    cudaFuncSetAttribute(proj_mma_kernel, cudaFuncAttributeMaxDynamicSharedMemorySize, PROJ_SMEM);
    cudaFuncSetAttribute(attn_mma_kernel, cudaFuncAttributeMaxDynamicSharedMemorySize, ATTN_SMEM);

    prep_w_kernel<<<2304, 256>>>(Wq, Wk);
    prep_a_kernel<<<12288, 256>>>(query, key);
    prep_v_kernel<<<dim3(32, 24), 256>>>(query);
    proj_mma_kernel<<<dim3(32, 6, 2), 256, PROJ_SMEM>>>(bq, bk);
    mu_kernel<<<dim3(12, 2), 256>>>(query, mask, w_mu, b_mu);
    attn_mma_kernel<<<dim3(16, 12, 2), 256, ATTN_SMEM>>>(query, shortb, mask, bias_m, out);
}